// round 1
// baseline (speedup 1.0000x reference)
#include <cuda_runtime.h>
#include <math.h>

#define BB 8
#define SS 1024
#define FF 8
#define DD 512
#define HH 8
#define LL 3
#define EE 4
#define TT (BB*SS)
#define HD 64

// ---------------- scratch (device globals; no allocs allowed) ----------------
__device__ float g_h[TT*DD];
__device__ float g_qkv[TT*3*DD];
__device__ float g_attn[TT*DD];
__device__ float g_tmp[TT*DD];
__device__ float g_hid[(size_t)EE*TT*2*DD];
__device__ float g_eo[(size_t)EE*TT*DD];
__device__ int   g_cnt[EE];
__device__ int   g_etok[EE*TT];
__device__ int   g_slot[2*TT];
__device__ float g_wt[2*TT];
__device__ float g_istats[BB*FF*2];

#define FMA44(ACC,a,b) \
  ACC[0][0]+=a.x*b.x; ACC[0][1]+=a.x*b.y; ACC[0][2]+=a.x*b.z; ACC[0][3]+=a.x*b.w; \
  ACC[1][0]+=a.y*b.x; ACC[1][1]+=a.y*b.y; ACC[1][2]+=a.y*b.z; ACC[1][3]+=a.y*b.w; \
  ACC[2][0]+=a.z*b.x; ACC[2][1]+=a.z*b.y; ACC[2][2]+=a.z*b.z; ACC[2][3]+=a.z*b.w; \
  ACC[3][0]+=a.w*b.x; ACC[3][1]+=a.w*b.y; ACC[3][2]+=a.w*b.z; ACC[3][3]+=a.w*b.w;

// ---------------- generic GEMM: C[M,N] = A[M,K] @ W[N,K]^T + bias ----------------
// 64x64 block tile, K-tile 16, 256 threads, 4x4 per-thread micro-tile.
// GATHER: A row indices come from gidx (per-expert token lists).
// cnts: if non-null, M = cnts[blockIdx.z] (routed MoE).
template<bool GATHER, bool RELU>
__global__ void __launch_bounds__(256) gemm_bias(
    const float* __restrict__ A, const float* __restrict__ W,
    const float* __restrict__ bias, float* __restrict__ C,
    int M, int N, int Kd, int lda, int ldc,
    long astride, long wstride, int bstride, long cstride,
    const int* __restrict__ gidx, const int* __restrict__ cnts)
{
    int e = blockIdx.z;
    A    += (long)e * astride;
    W    += (long)e * wstride;
    bias += (long)e * bstride;
    C    += (long)e * cstride;
    if (cnts) M = cnts[e];
    int m0 = blockIdx.y * 64;
    if (m0 >= M) return;
    int n0 = blockIdx.x * 64;

    __shared__ float As[16][68];
    __shared__ float Bs[16][68];

    int tid = threadIdx.x;
    int lrow = tid >> 2;      // 0..63
    int kv   = tid & 3;       // 0..3
    int rm = (tid >> 4) * 4;  // 0..60
    int rn = (tid & 15) * 4;  // 0..60

    float acc[4][4] = {};

    const float* Ap = nullptr;
    if (m0 + lrow < M) {
        int arow;
        if (GATHER) arow = (gidx + (long)e * TT)[m0 + lrow];
        else        arow = m0 + lrow;
        Ap = A + (long)arow * lda;
    }
    const float* Wrow = W + (long)(n0 + lrow) * Kd;

    for (int k0 = 0; k0 < Kd; k0 += 16) {
        float4 av = make_float4(0.f,0.f,0.f,0.f);
        if (Ap) av = *(const float4*)&Ap[k0 + kv*4];
        float4 bv = *(const float4*)&Wrow[k0 + kv*4];
        __syncthreads();
        As[kv*4+0][lrow]=av.x; As[kv*4+1][lrow]=av.y; As[kv*4+2][lrow]=av.z; As[kv*4+3][lrow]=av.w;
        Bs[kv*4+0][lrow]=bv.x; Bs[kv*4+1][lrow]=bv.y; Bs[kv*4+2][lrow]=bv.z; Bs[kv*4+3][lrow]=bv.w;
        __syncthreads();
#pragma unroll
        for (int k = 0; k < 16; k++) {
            float4 a = *(const float4*)&As[k][rm];
            float4 b = *(const float4*)&Bs[k][rn];
            FMA44(acc, a, b);
        }
    }
    float4 bb = *(const float4*)&bias[n0 + rn];
#pragma unroll
    for (int i = 0; i < 4; i++) {
        int row = m0 + rm + i;
        if (row < M) {
            float4 v;
            v.x = acc[i][0] + bb.x; v.y = acc[i][1] + bb.y;
            v.z = acc[i][2] + bb.z; v.w = acc[i][3] + bb.w;
            if (RELU) {
                v.x = fmaxf(v.x, 0.f); v.y = fmaxf(v.y, 0.f);
                v.z = fmaxf(v.z, 0.f); v.w = fmaxf(v.w, 0.f);
            }
            *(float4*)&C[(long)row * ldc + n0 + rn] = v;
        }
    }
}

// ---------------- attention: flash-style, 64-query tiles, 64-key chunks ----------------
// grid (S/64, H, B), 256 threads. smem: Qs,Ks (d-major), Vs,Ps (j-major), all [64][68].
#define ATTN_SMEM ((4*64*68 + 3*64) * 4)
__global__ void __launch_bounds__(256) attn_kernel(const float* __restrict__ qkv,
                                                   float* __restrict__ out)
{
    extern __shared__ float sm[];
    float* Qs = sm;
    float* Ks = Qs + 64*68;
    float* Vs = Ks + 64*68;
    float* Ps = Vs + 64*68;
    float* mrow = Ps + 64*68;
    float* lrow = mrow + 64;
    float* arow = lrow + 64;

    int q0 = blockIdx.x * 64;
    int hh = blockIdx.y;
    int b  = blockIdx.z;
    int tid = threadIdx.x;
    int rq = (tid >> 4) * 4;   // 4 query rows
    int rd = (tid & 15) * 4;   // 4 key cols / 4 head-dims

    const float* base = qkv + (long)b * SS * (3*DD) + hh * HD;

    // load Q, transposed to d-major
    {
        int q = tid >> 2, dv = tid & 3;
        const float* qp = base + (long)(q0 + q) * (3*DD);
#pragma unroll
        for (int it = 0; it < 4; it++) {
            int d0 = (it*4 + dv) * 4;
            float4 v = *(const float4*)&qp[d0];
            Qs[(d0+0)*68+q]=v.x; Qs[(d0+1)*68+q]=v.y; Qs[(d0+2)*68+q]=v.z; Qs[(d0+3)*68+q]=v.w;
        }
    }
    if (tid < 64) { mrow[tid] = -1e30f; lrow[tid] = 0.f; }

    float o[4][4] = {};

    for (int jc = 0; jc < SS/64; jc++) {
        __syncthreads();
        // load K (transposed) and V
        {
            int j = tid >> 2, dv = tid & 3;
            const float* kp = base + (long)(jc*64 + j) * (3*DD) + DD;
            const float* vp = kp + DD;
#pragma unroll
            for (int it = 0; it < 4; it++) {
                int d0 = (it*4 + dv) * 4;
                float4 kv = *(const float4*)&kp[d0];
                Ks[(d0+0)*68+j]=kv.x; Ks[(d0+1)*68+j]=kv.y; Ks[(d0+2)*68+j]=kv.z; Ks[(d0+3)*68+j]=kv.w;
                float4 vv = *(const float4*)&vp[d0];
                *(float4*)&Vs[j*68 + d0] = vv;
            }
        }
        __syncthreads();
        // scores S = Q K^T (over d)
        float s[4][4] = {};
#pragma unroll
        for (int d = 0; d < 64; d++) {
            float4 a = *(const float4*)&Qs[d*68 + rq];
            float4 bqk = *(const float4*)&Ks[d*68 + rd];
            FMA44(s, a, bqk);
        }
        // write scaled scores into Ps[j][q]
#pragma unroll
        for (int qq = 0; qq < 4; qq++)
#pragma unroll
            for (int jj = 0; jj < 4; jj++)
                Ps[(rd+jj)*68 + rq+qq] = s[qq][jj] * 0.125f;
        __syncthreads();
        // online softmax row pass
        if (tid < 64) {
            int q = tid;
            float mold = mrow[q];
            float mx = mold;
#pragma unroll 8
            for (int jj = 0; jj < 64; jj++) mx = fmaxf(mx, Ps[jj*68+q]);
            float al = __expf(mold - mx);
            float ls = 0.f;
#pragma unroll 8
            for (int jj = 0; jj < 64; jj++) {
                float p = __expf(Ps[jj*68+q] - mx);
                Ps[jj*68+q] = p;
                ls += p;
            }
            mrow[q] = mx;
            lrow[q] = lrow[q]*al + ls;
            arow[q] = al;
        }
        __syncthreads();
        float a0=arow[rq],a1=arow[rq+1],a2=arow[rq+2],a3=arow[rq+3];
#pragma unroll
        for (int j = 0; j < 4; j++) { o[0][j]*=a0; o[1][j]*=a1; o[2][j]*=a2; o[3][j]*=a3; }
        // O += P @ V (over j)
#pragma unroll
        for (int jj = 0; jj < 64; jj++) {
            float4 p = *(const float4*)&Ps[jj*68 + rq];
            float4 v = *(const float4*)&Vs[jj*68 + rd];
            FMA44(o, p, v);
        }
    }
    float inv0 = 1.f/lrow[rq], inv1 = 1.f/lrow[rq+1], inv2 = 1.f/lrow[rq+2], inv3 = 1.f/lrow[rq+3];
    float invs[4] = {inv0, inv1, inv2, inv3};
#pragma unroll
    for (int qq = 0; qq < 4; qq++) {
        float4 r;
        r.x = o[qq][0]*invs[qq]; r.y = o[qq][1]*invs[qq];
        r.z = o[qq][2]*invs[qq]; r.w = o[qq][3]*invs[qq];
        *(float4*)&out[(long)(b*SS + q0 + rq + qq) * DD + hh*HD + rd] = r;
    }
}

// ---------------- instance-norm stats (per b,f; over S; ddof=1; eps on std) ----------------
__global__ void istats_kernel(const float* __restrict__ x, float* __restrict__ stats)
{
    int bf = blockIdx.x;       // 64
    int b = bf >> 3, f = bf & 7;
    int tid = threadIdx.x;     // 256
    float s = 0.f, ss = 0.f;
    for (int i = tid; i < SS; i += 256) {
        float v = x[((long)b*SS + i)*FF + f];
        s += v; ss += v*v;
    }
    __shared__ float red[16];
    int lane = tid & 31, wid = tid >> 5;
#pragma unroll
    for (int o = 16; o; o >>= 1) {
        s  += __shfl_down_sync(0xffffffffu, s, o);
        ss += __shfl_down_sync(0xffffffffu, ss, o);
    }
    if (!lane) { red[wid] = s; red[8+wid] = ss; }
    __syncthreads();
    if (!tid) {
        float S = 0.f, Q = 0.f;
        for (int w = 0; w < 8; w++) { S += red[w]; Q += red[8+w]; }
        float m = S / SS;
        float var = (Q - SS*m*m) / (SS - 1);
        stats[bf*2]   = m;
        stats[bf*2+1] = 1.f / (sqrtf(var) + 1e-5f);
    }
}

// ---------------- embed: h = xn@Wp^T + bp + femb[fi] + posenc ----------------
__global__ void embed_kernel(const float* __restrict__ x, const float* __restrict__ Wp,
                             const float* __restrict__ bp, const float* __restrict__ femb,
                             const int* __restrict__ fidx, const float* __restrict__ stats,
                             float* __restrict__ h)
{
    int token = blockIdx.x;           // 8192
    int b = token >> 10, s = token & 1023;
    int tid = threadIdx.x;            // 128
    __shared__ float xn[8];
    if (tid < 8) {
        float m = stats[(b*8+tid)*2], inv = stats[(b*8+tid)*2+1];
        xn[tid] = (x[(long)token*FF + tid] - m) * inv;
    }
    __syncthreads();
    int fi = *fidx;
    int d0 = tid * 4;
    float4 acc = *(const float4*)&bp[d0];
    float* ap = &acc.x;
#pragma unroll
    for (int f = 0; f < 8; f++) {
        float xv = xn[f];
        ap[0] += xv * Wp[(d0+0)*8+f];
        ap[1] += xv * Wp[(d0+1)*8+f];
        ap[2] += xv * Wp[(d0+2)*8+f];
        ap[3] += xv * Wp[(d0+3)*8+f];
    }
    const float c = -0.0179889460f;   // -ln(10000)/512
#pragma unroll
    for (int j = 0; j < 4; j++) {
        int d = d0 + j;
        int i = d >> 1;
        float ang = (float)s * expf((float)(2*i) * c);
        float pe = (d & 1) ? cosf(ang) : sinf(ang);
        ap[j] += femb[fi*DD + d] + pe;
    }
    *(float4*)&h[(long)token*DD + d0] = acc;
}

// ---------------- add + layernorm (ddof=0, eps in sqrt) ----------------
__global__ void add_ln_kernel(const float* __restrict__ base, const float* __restrict__ add,
                              const float* __restrict__ g, const float* __restrict__ bet,
                              float* __restrict__ out)
{
    long t = blockIdx.x;
    int tid = threadIdx.x;   // 128
    float4 xb = *(const float4*)&base[t*DD + tid*4];
    float4 xa = *(const float4*)&add[t*DD + tid*4];
    float v0=xb.x+xa.x, v1=xb.y+xa.y, v2=xb.z+xa.z, v3=xb.w+xa.w;
    float s = v0+v1+v2+v3, ss = v0*v0+v1*v1+v2*v2+v3*v3;
    __shared__ float red[16];
    int lane = tid & 31, wid = tid >> 5;
#pragma unroll
    for (int o = 16; o; o >>= 1) {
        s  += __shfl_down_sync(0xffffffffu, s, o);
        ss += __shfl_down_sync(0xffffffffu, ss, o);
    }
    if (!lane) { red[wid] = s; red[8+wid] = ss; }
    __syncthreads();
    if (!tid) {
        float S = red[0]+red[1]+red[2]+red[3];
        float Q = red[8]+red[9]+red[10]+red[11];
        red[0] = S * (1.f/DD);
        red[1] = Q * (1.f/DD);
    }
    __syncthreads();
    float m = red[0];
    float r = rsqrtf(red[1] - m*m + 1e-5f);
    float4 gv = *(const float4*)&g[tid*4];
    float4 bv = *(const float4*)&bet[tid*4];
    float4 o4;
    o4.x = (v0-m)*r*gv.x + bv.x;
    o4.y = (v1-m)*r*gv.y + bv.y;
    o4.z = (v2-m)*r*gv.z + bv.z;
    o4.w = (v3-m)*r*gv.w + bv.w;
    *(float4*)&out[t*DD + tid*4] = o4;
}

// ---------------- moe combine + layernorm ----------------
__global__ void moe_combine_ln_kernel(const float* __restrict__ h, const float* __restrict__ eo,
                                      const int* __restrict__ slot, const float* __restrict__ wt,
                                      const float* __restrict__ g, const float* __restrict__ bet,
                                      float* __restrict__ out)
{
    long t = blockIdx.x;
    int tid = threadIdx.x;   // 128
    int s0 = slot[2*t], s1 = slot[2*t+1];
    float w0 = wt[2*t], w1 = wt[2*t+1];
    float4 xh = *(const float4*)&h[t*DD + tid*4];
    float4 e0 = *(const float4*)&eo[(long)s0*DD + tid*4];
    float4 e1 = *(const float4*)&eo[(long)s1*DD + tid*4];
    float v0 = xh.x + w0*e0.x + w1*e1.x;
    float v1 = xh.y + w0*e0.y + w1*e1.y;
    float v2 = xh.z + w0*e0.z + w1*e1.z;
    float v3 = xh.w + w0*e0.w + w1*e1.w;
    float s = v0+v1+v2+v3, ss = v0*v0+v1*v1+v2*v2+v3*v3;
    __shared__ float red[16];
    int lane = tid & 31, wid = tid >> 5;
#pragma unroll
    for (int o = 16; o; o >>= 1) {
        s  += __shfl_down_sync(0xffffffffu, s, o);
        ss += __shfl_down_sync(0xffffffffu, ss, o);
    }
    if (!lane) { red[wid] = s; red[8+wid] = ss; }
    __syncthreads();
    if (!tid) {
        float S = red[0]+red[1]+red[2]+red[3];
        float Q = red[8]+red[9]+red[10]+red[11];
        red[0] = S * (1.f/DD);
        red[1] = Q * (1.f/DD);
    }
    __syncthreads();
    float m = red[0];
    float r = rsqrtf(red[1] - m*m + 1e-5f);
    float4 gv = *(const float4*)&g[tid*4];
    float4 bv = *(const float4*)&bet[tid*4];
    float4 o4;
    o4.x = (v0-m)*r*gv.x + bv.x;
    o4.y = (v1-m)*r*gv.y + bv.y;
    o4.z = (v2-m)*r*gv.z + bv.z;
    o4.w = (v3-m)*r*gv.w + bv.w;
    *(float4*)&out[t*DD + tid*4] = o4;
}

// ---------------- gating: softmax over E=4, top-2, renorm, build routed lists ----------------
__global__ void zero_counts_kernel(int* c) { if (threadIdx.x < EE) c[threadIdx.x] = 0; }

__global__ void gate_kernel(const float* __restrict__ h, const float* __restrict__ gw,
                            const float* __restrict__ gb, int* __restrict__ cnt,
                            int* __restrict__ etok, int* __restrict__ slot,
                            float* __restrict__ wt)
{
    int t = blockIdx.x * 4 + (threadIdx.x >> 5);
    int lane = threadIdx.x & 31;
    const float* hp = h + (long)t * DD;
    float acc[4] = {0.f,0.f,0.f,0.f};
#pragma unroll
    for (int it = 0; it < 4; it++) {
        int d0 = (it*32 + lane) * 4;
        float4 xv = *(const float4*)&hp[d0];
#pragma unroll
        for (int e = 0; e < 4; e++) {
            float4 wv = *(const float4*)&gw[e*DD + d0];
            acc[e] += xv.x*wv.x + xv.y*wv.y + xv.z*wv.z + xv.w*wv.w;
        }
    }
#pragma unroll
    for (int e = 0; e < 4; e++)
#pragma unroll
        for (int o = 16; o; o >>= 1)
            acc[e] += __shfl_down_sync(0xffffffffu, acc[e], o);
    if (!lane) {
        float lg[4], p[4];
        float mx = -1e30f;
#pragma unroll
        for (int e = 0; e < 4; e++) { lg[e] = acc[e] + gb[e]; mx = fmaxf(mx, lg[e]); }
        float sum = 0.f;
#pragma unroll
        for (int e = 0; e < 4; e++) { p[e] = expf(lg[e]-mx); sum += p[e]; }
#pragma unroll
        for (int e = 0; e < 4; e++) p[e] /= sum;
        int i0 = 0;
#pragma unroll
        for (int e = 1; e < 4; e++) if (p[e] > p[i0]) i0 = e;
        int i1 = (i0 == 0) ? 1 : 0;
#pragma unroll
        for (int e = 0; e < 4; e++) if (e != i0 && p[e] > p[i1]) i1 = e;
        float w0 = p[i0], w1 = p[i1];
        float inv = 1.f / (w0 + w1);
        int pos0 = atomicAdd(&cnt[i0], 1);
        etok[i0*TT + pos0] = t;
        slot[2*t]   = i0*TT + pos0;
        wt[2*t]     = w0 * inv;
        int pos1 = atomicAdd(&cnt[i1], 1);
        etok[i1*TT + pos1] = t;
        slot[2*t+1] = i1*TT + pos1;
        wt[2*t+1]   = w1 * inv;
    }
}

// ---------------- head: out[b,i] = dot(h[b,-1,:], hw[i,:]) + hb[i] ----------------
__global__ void head_kernel(const float* __restrict__ h, const float* __restrict__ hw,
                            const float* __restrict__ hb, float* __restrict__ out)
{
    int w = threadIdx.x >> 5, lane = threadIdx.x & 31;  // 24 warps
    int b = w / 3, i = w % 3;
    const float* hp = h + ((long)(b*SS + SS-1)) * DD;
    float s = 0.f;
#pragma unroll
    for (int it = 0; it < 4; it++) {
        int d0 = (it*32 + lane) * 4;
        float4 a = *(const float4*)&hp[d0];
        float4 c = *(const float4*)&hw[i*DD + d0];
        s += a.x*c.x + a.y*c.y + a.z*c.z + a.w*c.w;
    }
#pragma unroll
    for (int o = 16; o; o >>= 1) s += __shfl_down_sync(0xffffffffu, s, o);
    if (!lane) out[b*3+i] = s + hb[i];
}

// ---------------- orchestration ----------------
extern "C" void kernel_launch(void* const* d_in, const int* in_sizes, int n_in,
                              void* d_out, int out_size)
{
    const float* x      = (const float*)d_in[0];
    const float* Wp     = (const float*)d_in[1];
    const float* bp     = (const float*)d_in[2];
    const float* femb   = (const float*)d_in[3];
    const float* qkv_w  = (const float*)d_in[4];
    const float* qkv_b  = (const float*)d_in[5];
    const float* ow     = (const float*)d_in[6];
    const float* ob     = (const float*)d_in[7];
    const float* g1     = (const float*)d_in[8];
    const float* beta1  = (const float*)d_in[9];
    const float* gw     = (const float*)d_in[10];
    const float* gb     = (const float*)d_in[11];
    const float* ew1    = (const float*)d_in[12];
    const float* eb1    = (const float*)d_in[13];
    const float* ew2    = (const float*)d_in[14];
    const float* eb2    = (const float*)d_in[15];
    const float* g2     = (const float*)d_in[16];
    const float* beta2  = (const float*)d_in[17];
    const float* hw     = (const float*)d_in[18];
    const float* hb     = (const float*)d_in[19];
    const int*   fidx   = (const int*)d_in[20];
    float* out = (float*)d_out;

    float *h, *qkv, *attn, *tmp, *hid, *eo, *wt, *istats;
    int *cnt, *etok, *slot;
    cudaGetSymbolAddress((void**)&h,      g_h);
    cudaGetSymbolAddress((void**)&qkv,    g_qkv);
    cudaGetSymbolAddress((void**)&attn,   g_attn);
    cudaGetSymbolAddress((void**)&tmp,    g_tmp);
    cudaGetSymbolAddress((void**)&hid,    g_hid);
    cudaGetSymbolAddress((void**)&eo,     g_eo);
    cudaGetSymbolAddress((void**)&cnt,    g_cnt);
    cudaGetSymbolAddress((void**)&etok,   g_etok);
    cudaGetSymbolAddress((void**)&slot,   g_slot);
    cudaGetSymbolAddress((void**)&wt,     g_wt);
    cudaGetSymbolAddress((void**)&istats, g_istats);

    cudaFuncSetAttribute(attn_kernel, cudaFuncAttributeMaxDynamicSharedMemorySize, ATTN_SMEM);

    istats_kernel<<<BB*FF, 256>>>(x, istats);
    embed_kernel<<<TT, 128>>>(x, Wp, bp, femb, fidx, istats, h);

    for (int l = 0; l < LL; l++) {
        // QKV projection
        gemm_bias<false,false><<<dim3(3*DD/64, TT/64, 1), 256>>>(
            h, qkv_w + (long)l*3*DD*DD, qkv_b + l*3*DD, qkv,
            TT, 3*DD, DD, DD, 3*DD, 0, 0, 0, 0, nullptr, nullptr);
        // attention
        attn_kernel<<<dim3(SS/64, HH, BB), 256, ATTN_SMEM>>>(qkv, attn);
        // output projection
        gemm_bias<false,false><<<dim3(DD/64, TT/64, 1), 256>>>(
            attn, ow + (long)l*DD*DD, ob + l*DD, tmp,
            TT, DD, DD, DD, DD, 0, 0, 0, 0, nullptr, nullptr);
        add_ln_kernel<<<TT, 128>>>(h, tmp, g1 + l*DD, beta1 + l*DD, h);
        // MoE: gate + routed expert FFNs + combine
        zero_counts_kernel<<<1, 32>>>(cnt);
        gate_kernel<<<TT/4, 128>>>(h, gw + l*EE*DD, gb + l*EE, cnt, etok, slot, wt);
        gemm_bias<true,true><<<dim3(2*DD/64, TT/64, EE), 256>>>(
            h, ew1 + (long)l*EE*2*DD*DD, eb1 + l*EE*2*DD, hid,
            TT, 2*DD, DD, DD, 2*DD,
            0, (long)2*DD*DD, 2*DD, (long)TT*2*DD, etok, cnt);
        gemm_bias<false,false><<<dim3(DD/64, TT/64, EE), 256>>>(
            hid, ew2 + (long)l*EE*DD*2*DD, eb2 + l*EE*DD, eo,
            TT, DD, 2*DD, 2*DD, DD,
            (long)TT*2*DD, (long)DD*2*DD, DD, (long)TT*DD, nullptr, cnt);
        moe_combine_ln_kernel<<<TT, 128>>>(h, eo, slot, wt, g2 + l*DD, beta2 + l*DD, h);
    }
    head_kernel<<<1, 768>>>(h, hw, hb, out);
}

// round 3
// speedup vs baseline: 1.9691x; 1.9691x over previous
#include <cuda_runtime.h>
#include <math.h>
#include <cstdint>

#define BB 8
#define SS 1024
#define FF 8
#define DD 512
#define HH 8
#define LL 3
#define EE 4
#define TT (BB*SS)
#define HD 64

// ---------------- scratch (device globals; no allocs allowed) ----------------
__device__ float g_h[TT*DD];
__device__ float g_qkv[TT*3*DD];
__device__ float g_attn[TT*DD];
__device__ float g_tmp[TT*DD];
__device__ float g_hid[(size_t)EE*TT*2*DD];
__device__ float g_eo[(size_t)EE*TT*DD];
__device__ int   g_cnt[EE];
__device__ int   g_etok[EE*TT];
__device__ int   g_slot[2*TT];
__device__ float g_wt[2*TT];
__device__ float g_istats[BB*FF*2];

__device__ __forceinline__ float to_tf32(float x) {
    float r; asm("cvt.rna.tf32.f32 %0, %1;" : "=f"(r) : "f"(x)); return r;
}
__device__ __forceinline__ void mma_tf32(float* d, const uint32_t* a, const uint32_t* b) {
    asm volatile(
      "mma.sync.aligned.m16n8k8.row.col.f32.tf32.tf32.f32 "
      "{%0,%1,%2,%3}, {%4,%5,%6,%7}, {%8,%9}, {%0,%1,%2,%3};"
      : "+f"(d[0]), "+f"(d[1]), "+f"(d[2]), "+f"(d[3])
      : "r"(a[0]), "r"(a[1]), "r"(a[2]), "r"(a[3]), "r"(b[0]), "r"(b[1]));
}

// ================= mma.sync tf32 GEMM: C[M,N] = A[M,K] @ W[N,K]^T + bias =================
// 128x128 CTA tile, 8 warps (2x4), warp tile 64x32, K-tile 32, reg-staged double buffer.
#define SMS 36   // smem row stride in floats (32 + 4 pad)
template<bool GATHER, bool RELU>
__global__ void __launch_bounds__(256) gemm_mma(
    const float* __restrict__ A, const float* __restrict__ W,
    const float* __restrict__ bias, float* __restrict__ C,
    int M, int N, int Kd, int lda, int ldc,
    long astride, long wstride, int bstride, long cstride,
    const int* __restrict__ gidx, const int* __restrict__ cnts)
{
    __shared__ float As[128*SMS];
    __shared__ float Bs[128*SMS];

    int e = blockIdx.z;
    A    += (long)e * astride;
    W    += (long)e * wstride;
    bias += (long)e * bstride;
    C    += (long)e * cstride;
    if (cnts) M = cnts[e];
    int m0 = blockIdx.y * 128;
    if (m0 >= M) return;
    int n0 = blockIdx.x * 128;

    int tid = threadIdx.x, lane = tid & 31, warp = tid >> 5;
    int wm = (warp >> 2) * 64;   // 0,64
    int wn = (warp & 3) * 32;    // 0,32,64,96

    // staging map: i = tid + p*256 ; row = i>>3 (0..127), c4 = i&7 (float4 within 32-float row)
    const float* ap[4];
    const float* bp[4];
#pragma unroll
    for (int p = 0; p < 4; p++) {
        int i = tid + p * 256;
        int row = i >> 3, c4 = i & 7;
        int mr = m0 + row;
        if (mr < M) {
            int ar = GATHER ? gidx[(long)e * TT + mr] : mr;
            ap[p] = A + (long)ar * lda + c4 * 4;
        } else ap[p] = nullptr;
        bp[p] = W + (long)(n0 + row) * Kd + c4 * 4;
    }

    float4 aReg[4], bReg[4];
#pragma unroll
    for (int p = 0; p < 4; p++) {
        aReg[p] = ap[p] ? *(const float4*)(ap[p]) : make_float4(0.f,0.f,0.f,0.f);
        bReg[p] = *(const float4*)(bp[p]);
    }

    float acc[4][4][4];
#pragma unroll
    for (int a_ = 0; a_ < 4; a_++)
#pragma unroll
        for (int b_ = 0; b_ < 4; b_++)
#pragma unroll
            for (int c_ = 0; c_ < 4; c_++) acc[a_][b_][c_] = 0.f;

    int nkt = Kd / 32;
    for (int kt = 0; kt < nkt; kt++) {
#pragma unroll
        for (int p = 0; p < 4; p++) {
            int i = tid + p * 256;
            int row = i >> 3, c4 = i & 7;
            float4 a = aReg[p], b = bReg[p];
            a.x = to_tf32(a.x); a.y = to_tf32(a.y); a.z = to_tf32(a.z); a.w = to_tf32(a.w);
            b.x = to_tf32(b.x); b.y = to_tf32(b.y); b.z = to_tf32(b.z); b.w = to_tf32(b.w);
            *(float4*)&As[row*SMS + c4*4] = a;
            *(float4*)&Bs[row*SMS + c4*4] = b;
        }
        __syncthreads();
        if (kt + 1 < nkt) {
            int koff = (kt + 1) * 32;
#pragma unroll
            for (int p = 0; p < 4; p++) {
                aReg[p] = ap[p] ? *(const float4*)(ap[p] + koff) : make_float4(0.f,0.f,0.f,0.f);
                bReg[p] = *(const float4*)(bp[p] + koff);
            }
        }
        const uint32_t* Asu = (const uint32_t*)As;
        const uint32_t* Bsu = (const uint32_t*)Bs;
#pragma unroll
        for (int ks = 0; ks < 4; ks++) {
            int k0 = ks * 8 + (lane & 3);
            uint32_t af[4][4], bf[4][2];
            int r0 = wm + (lane >> 2);
#pragma unroll
            for (int mf = 0; mf < 4; mf++) {
                int r = r0 + mf * 16;
                af[mf][0] = Asu[r*SMS + k0];
                af[mf][1] = Asu[(r+8)*SMS + k0];
                af[mf][2] = Asu[r*SMS + k0 + 4];
                af[mf][3] = Asu[(r+8)*SMS + k0 + 4];
            }
            int nb = wn + (lane >> 2);
#pragma unroll
            for (int nf = 0; nf < 4; nf++) {
                int n = nb + nf * 8;
                bf[nf][0] = Bsu[n*SMS + k0];
                bf[nf][1] = Bsu[n*SMS + k0 + 4];
            }
#pragma unroll
            for (int mf = 0; mf < 4; mf++)
#pragma unroll
                for (int nf = 0; nf < 4; nf++)
                    mma_tf32(acc[mf][nf], af[mf], bf[nf]);
        }
        __syncthreads();
    }

    // epilogue: d0,d1 -> (r, 2c),(r, 2c+1); d2,d3 -> (r+8, ...)
#pragma unroll
    for (int mf = 0; mf < 4; mf++) {
        int rA = m0 + wm + mf*16 + (lane >> 2);
        int rB = rA + 8;
#pragma unroll
        for (int nf = 0; nf < 4; nf++) {
            int col = n0 + wn + nf*8 + (lane & 3) * 2;
            float2 bb = *(const float2*)&bias[col];
            float2 v0, v1;
            v0.x = acc[mf][nf][0] + bb.x; v0.y = acc[mf][nf][1] + bb.y;
            v1.x = acc[mf][nf][2] + bb.x; v1.y = acc[mf][nf][3] + bb.y;
            if (RELU) {
                v0.x = fmaxf(v0.x, 0.f); v0.y = fmaxf(v0.y, 0.f);
                v1.x = fmaxf(v1.x, 0.f); v1.y = fmaxf(v1.y, 0.f);
            }
            if (rA < M) *(float2*)&C[(long)rA*ldc + col] = v0;
            if (rB < M) *(float2*)&C[(long)rB*ldc + col] = v1;
        }
    }
}

#define FMA44(ACC,a,b) \
  ACC[0][0]+=a.x*b.x; ACC[0][1]+=a.x*b.y; ACC[0][2]+=a.x*b.z; ACC[0][3]+=a.x*b.w; \
  ACC[1][0]+=a.y*b.x; ACC[1][1]+=a.y*b.y; ACC[1][2]+=a.y*b.z; ACC[1][3]+=a.y*b.w; \
  ACC[2][0]+=a.z*b.x; ACC[2][1]+=a.z*b.y; ACC[2][2]+=a.z*b.z; ACC[2][3]+=a.z*b.w; \
  ACC[3][0]+=a.w*b.x; ACC[3][1]+=a.w*b.y; ACC[3][2]+=a.w*b.z; ACC[3][3]+=a.w*b.w;

// ---------------- attention: flash-style, 64-query tiles, 64-key chunks ----------------
#define ATTN_SMEM ((4*64*68 + 3*64) * 4)
__global__ void __launch_bounds__(256) attn_kernel(const float* __restrict__ qkv,
                                                   float* __restrict__ out)
{
    extern __shared__ float sm[];
    float* Qs = sm;
    float* Ks = Qs + 64*68;
    float* Vs = Ks + 64*68;
    float* Ps = Vs + 64*68;
    float* mrow = Ps + 64*68;
    float* lrow = mrow + 64;
    float* arow = lrow + 64;

    int q0 = blockIdx.x * 64;
    int hh = blockIdx.y;
    int b  = blockIdx.z;
    int tid = threadIdx.x;
    int rq = (tid >> 4) * 4;
    int rd = (tid & 15) * 4;

    const float* base = qkv + (long)b * SS * (3*DD) + hh * HD;

    {
        int q = tid >> 2, dv = tid & 3;
        const float* qp = base + (long)(q0 + q) * (3*DD);
#pragma unroll
        for (int it = 0; it < 4; it++) {
            int d0 = (it*4 + dv) * 4;
            float4 v = *(const float4*)&qp[d0];
            Qs[(d0+0)*68+q]=v.x; Qs[(d0+1)*68+q]=v.y; Qs[(d0+2)*68+q]=v.z; Qs[(d0+3)*68+q]=v.w;
        }
    }
    if (tid < 64) { mrow[tid] = -1e30f; lrow[tid] = 0.f; }

    float o[4][4] = {};

    for (int jc = 0; jc < SS/64; jc++) {
        __syncthreads();
        {
            int j = tid >> 2, dv = tid & 3;
            const float* kp = base + (long)(jc*64 + j) * (3*DD) + DD;
            const float* vp = kp + DD;
#pragma unroll
            for (int it = 0; it < 4; it++) {
                int d0 = (it*4 + dv) * 4;
                float4 kv = *(const float4*)&kp[d0];
                Ks[(d0+0)*68+j]=kv.x; Ks[(d0+1)*68+j]=kv.y; Ks[(d0+2)*68+j]=kv.z; Ks[(d0+3)*68+j]=kv.w;
                float4 vv = *(const float4*)&vp[d0];
                *(float4*)&Vs[j*68 + d0] = vv;
            }
        }
        __syncthreads();
        float s[4][4] = {};
#pragma unroll
        for (int d = 0; d < 64; d++) {
            float4 a = *(const float4*)&Qs[d*68 + rq];
            float4 bqk = *(const float4*)&Ks[d*68 + rd];
            FMA44(s, a, bqk);
        }
#pragma unroll
        for (int qq = 0; qq < 4; qq++)
#pragma unroll
            for (int jj = 0; jj < 4; jj++)
                Ps[(rd+jj)*68 + rq+qq] = s[qq][jj] * 0.125f;
        __syncthreads();
        if (tid < 64) {
            int qn = tid;
            float mold = mrow[qn];
            float mx = mold;
#pragma unroll 8
            for (int jj = 0; jj < 64; jj++) mx = fmaxf(mx, Ps[jj*68+qn]);
            float al = __expf(mold - mx);
            float ls = 0.f;
#pragma unroll 8
            for (int jj = 0; jj < 64; jj++) {
                float p = __expf(Ps[jj*68+qn] - mx);
                Ps[jj*68+qn] = p;
                ls += p;
            }
            mrow[qn] = mx;
            lrow[qn] = lrow[qn]*al + ls;
            arow[qn] = al;
        }
        __syncthreads();
        float a0=arow[rq],a1=arow[rq+1],a2=arow[rq+2],a3=arow[rq+3];
#pragma unroll
        for (int j = 0; j < 4; j++) { o[0][j]*=a0; o[1][j]*=a1; o[2][j]*=a2; o[3][j]*=a3; }
#pragma unroll
        for (int jj = 0; jj < 64; jj++) {
            float4 p = *(const float4*)&Ps[jj*68 + rq];
            float4 v = *(const float4*)&Vs[jj*68 + rd];
            FMA44(o, p, v);
        }
    }
    float invs[4] = {1.f/lrow[rq], 1.f/lrow[rq+1], 1.f/lrow[rq+2], 1.f/lrow[rq+3]};
#pragma unroll
    for (int qq = 0; qq < 4; qq++) {
        float4 r;
        r.x = o[qq][0]*invs[qq]; r.y = o[qq][1]*invs[qq];
        r.z = o[qq][2]*invs[qq]; r.w = o[qq][3]*invs[qq];
        *(float4*)&out[(long)(b*SS + q0 + rq + qq) * DD + hh*HD + rd] = r;
    }
}

// ---------------- instance-norm stats ----------------
__global__ void istats_kernel(const float* __restrict__ x, float* __restrict__ stats)
{
    int bf = blockIdx.x;
    int b = bf >> 3, f = bf & 7;
    int tid = threadIdx.x;
    float s = 0.f, ss = 0.f;
    for (int i = tid; i < SS; i += 256) {
        float v = x[((long)b*SS + i)*FF + f];
        s += v; ss += v*v;
    }
    __shared__ float red[16];
    int lane = tid & 31, wid = tid >> 5;
#pragma unroll
    for (int o = 16; o; o >>= 1) {
        s  += __shfl_down_sync(0xffffffffu, s, o);
        ss += __shfl_down_sync(0xffffffffu, ss, o);
    }
    if (!lane) { red[wid] = s; red[8+wid] = ss; }
    __syncthreads();
    if (!tid) {
        float S = 0.f, Q = 0.f;
        for (int w = 0; w < 8; w++) { S += red[w]; Q += red[8+w]; }
        float m = S / SS;
        float var = (Q - SS*m*m) / (SS - 1);
        stats[bf*2]   = m;
        stats[bf*2+1] = 1.f / (sqrtf(var) + 1e-5f);
    }
}

// ---------------- embed ----------------
__global__ void embed_kernel(const float* __restrict__ x, const float* __restrict__ Wp,
                             const float* __restrict__ bp, const float* __restrict__ femb,
                             const int* __restrict__ fidx, const float* __restrict__ stats,
                             float* __restrict__ h)
{
    int token = blockIdx.x;
    int b = token >> 10, s = token & 1023;
    int tid = threadIdx.x;
    __shared__ float xn[8];
    if (tid < 8) {
        float m = stats[(b*8+tid)*2], inv = stats[(b*8+tid)*2+1];
        xn[tid] = (x[(long)token*FF + tid] - m) * inv;
    }
    __syncthreads();
    int fi = *fidx;
    int d0 = tid * 4;
    float4 acc = *(const float4*)&bp[d0];
    float* ap = &acc.x;
#pragma unroll
    for (int f = 0; f < 8; f++) {
        float xv = xn[f];
        ap[0] += xv * Wp[(d0+0)*8+f];
        ap[1] += xv * Wp[(d0+1)*8+f];
        ap[2] += xv * Wp[(d0+2)*8+f];
        ap[3] += xv * Wp[(d0+3)*8+f];
    }
    const float c = -0.0179889460f;
#pragma unroll
    for (int j = 0; j < 4; j++) {
        int d = d0 + j;
        int i = d >> 1;
        float ang = (float)s * expf((float)(2*i) * c);
        float pe = (d & 1) ? cosf(ang) : sinf(ang);
        ap[j] += femb[fi*DD + d] + pe;
    }
    *(float4*)&h[(long)token*DD + d0] = acc;
}

// ---------------- add + layernorm ----------------
__global__ void add_ln_kernel(const float* __restrict__ base, const float* __restrict__ add,
                              const float* __restrict__ g, const float* __restrict__ bet,
                              float* __restrict__ out)
{
    long t = blockIdx.x;
    int tid = threadIdx.x;
    float4 xb = *(const float4*)&base[t*DD + tid*4];
    float4 xa = *(const float4*)&add[t*DD + tid*4];
    float v0=xb.x+xa.x, v1=xb.y+xa.y, v2=xb.z+xa.z, v3=xb.w+xa.w;
    float s = v0+v1+v2+v3, ss = v0*v0+v1*v1+v2*v2+v3*v3;
    __shared__ float red[16];
    int lane = tid & 31, wid = tid >> 5;
#pragma unroll
    for (int o = 16; o; o >>= 1) {
        s  += __shfl_down_sync(0xffffffffu, s, o);
        ss += __shfl_down_sync(0xffffffffu, ss, o);
    }
    if (!lane) { red[wid] = s; red[8+wid] = ss; }
    __syncthreads();
    if (!tid) {
        float S = red[0]+red[1]+red[2]+red[3];
        float Q = red[8]+red[9]+red[10]+red[11];
        red[0] = S * (1.f/DD);
        red[1] = Q * (1.f/DD);
    }
    __syncthreads();
    float m = red[0];
    float r = rsqrtf(red[1] - m*m + 1e-5f);
    float4 gv = *(const float4*)&g[tid*4];
    float4 bv = *(const float4*)&bet[tid*4];
    float4 o4;
    o4.x = (v0-m)*r*gv.x + bv.x;
    o4.y = (v1-m)*r*gv.y + bv.y;
    o4.z = (v2-m)*r*gv.z + bv.z;
    o4.w = (v3-m)*r*gv.w + bv.w;
    *(float4*)&out[t*DD + tid*4] = o4;
}

// ---------------- moe combine + layernorm ----------------
__global__ void moe_combine_ln_kernel(const float* __restrict__ h, const float* __restrict__ eo,
                                      const int* __restrict__ slot, const float* __restrict__ wt,
                                      const float* __restrict__ g, const float* __restrict__ bet,
                                      float* __restrict__ out)
{
    long t = blockIdx.x;
    int tid = threadIdx.x;
    int s0 = slot[2*t], s1 = slot[2*t+1];
    float w0 = wt[2*t], w1 = wt[2*t+1];
    float4 xh = *(const float4*)&h[t*DD + tid*4];
    float4 e0 = *(const float4*)&eo[(long)s0*DD + tid*4];
    float4 e1 = *(const float4*)&eo[(long)s1*DD + tid*4];
    float v0 = xh.x + w0*e0.x + w1*e1.x;
    float v1 = xh.y + w0*e0.y + w1*e1.y;
    float v2 = xh.z + w0*e0.z + w1*e1.z;
    float v3 = xh.w + w0*e0.w + w1*e1.w;
    float s = v0+v1+v2+v3, ss = v0*v0+v1*v1+v2*v2+v3*v3;
    __shared__ float red[16];
    int lane = tid & 31, wid = tid >> 5;
#pragma unroll
    for (int o = 16; o; o >>= 1) {
        s  += __shfl_down_sync(0xffffffffu, s, o);
        ss += __shfl_down_sync(0xffffffffu, ss, o);
    }
    if (!lane) { red[wid] = s; red[8+wid] = ss; }
    __syncthreads();
    if (!tid) {
        float S = red[0]+red[1]+red[2]+red[3];
        float Q = red[8]+red[9]+red[10]+red[11];
        red[0] = S * (1.f/DD);
        red[1] = Q * (1.f/DD);
    }
    __syncthreads();
    float m = red[0];
    float r = rsqrtf(red[1] - m*m + 1e-5f);
    float4 gv = *(const float4*)&g[tid*4];
    float4 bv = *(const float4*)&bet[tid*4];
    float4 o4;
    o4.x = (v0-m)*r*gv.x + bv.x;
    o4.y = (v1-m)*r*gv.y + bv.y;
    o4.z = (v2-m)*r*gv.z + bv.z;
    o4.w = (v3-m)*r*gv.w + bv.w;
    *(float4*)&out[t*DD + tid*4] = o4;
}

// ---------------- gating ----------------
__global__ void zero_counts_kernel(int* c) { if (threadIdx.x < EE) c[threadIdx.x] = 0; }

__global__ void gate_kernel(const float* __restrict__ h, const float* __restrict__ gw,
                            const float* __restrict__ gb, int* __restrict__ cnt,
                            int* __restrict__ etok, int* __restrict__ slot,
                            float* __restrict__ wt)
{
    int t = blockIdx.x * 4 + (threadIdx.x >> 5);
    int lane = threadIdx.x & 31;
    const float* hp = h + (long)t * DD;
    float acc[4] = {0.f,0.f,0.f,0.f};
#pragma unroll
    for (int it = 0; it < 4; it++) {
        int d0 = (it*32 + lane) * 4;
        float4 xv = *(const float4*)&hp[d0];
#pragma unroll
        for (int e = 0; e < 4; e++) {
            float4 wv = *(const float4*)&gw[e*DD + d0];
            acc[e] += xv.x*wv.x + xv.y*wv.y + xv.z*wv.z + xv.w*wv.w;
        }
    }
#pragma unroll
    for (int e = 0; e < 4; e++)
#pragma unroll
        for (int o = 16; o; o >>= 1)
            acc[e] += __shfl_down_sync(0xffffffffu, acc[e], o);
    if (!lane) {
        float lg[4], p[4];
        float mx = -1e30f;
#pragma unroll
        for (int e = 0; e < 4; e++) { lg[e] = acc[e] + gb[e]; mx = fmaxf(mx, lg[e]); }
        float sum = 0.f;
#pragma unroll
        for (int e = 0; e < 4; e++) { p[e] = expf(lg[e]-mx); sum += p[e]; }
#pragma unroll
        for (int e = 0; e < 4; e++) p[e] /= sum;
        int i0 = 0;
#pragma unroll
        for (int e = 1; e < 4; e++) if (p[e] > p[i0]) i0 = e;
        int i1 = (i0 == 0) ? 1 : 0;
#pragma unroll
        for (int e = 0; e < 4; e++) if (e != i0 && p[e] > p[i1]) i1 = e;
        float w0 = p[i0], w1 = p[i1];
        float inv = 1.f / (w0 + w1);
        int pos0 = atomicAdd(&cnt[i0], 1);
        etok[i0*TT + pos0] = t;
        slot[2*t]   = i0*TT + pos0;
        wt[2*t]     = w0 * inv;
        int pos1 = atomicAdd(&cnt[i1], 1);
        etok[i1*TT + pos1] = t;
        slot[2*t+1] = i1*TT + pos1;
        wt[2*t+1]   = w1 * inv;
    }
}

// ---------------- head ----------------
__global__ void head_kernel(const float* __restrict__ h, const float* __restrict__ hw,
                            const float* __restrict__ hb, float* __restrict__ out)
{
    int w = threadIdx.x >> 5, lane = threadIdx.x & 31;
    int b = w / 3, i = w % 3;
    const float* hp = h + ((long)(b*SS + SS-1)) * DD;
    float s = 0.f;
#pragma unroll
    for (int it = 0; it < 4; it++) {
        int d0 = (it*32 + lane) * 4;
        float4 a = *(const float4*)&hp[d0];
        float4 c = *(const float4*)&hw[i*DD + d0];
        s += a.x*c.x + a.y*c.y + a.z*c.z + a.w*c.w;
    }
#pragma unroll
    for (int o = 16; o; o >>= 1) s += __shfl_down_sync(0xffffffffu, s, o);
    if (!lane) out[b*3+i] = s + hb[i];
}

// ---------------- orchestration ----------------
extern "C" void kernel_launch(void* const* d_in, const int* in_sizes, int n_in,
                              void* d_out, int out_size)
{
    const float* x      = (const float*)d_in[0];
    const float* Wp     = (const float*)d_in[1];
    const float* bp     = (const float*)d_in[2];
    const float* femb   = (const float*)d_in[3];
    const float* qkv_w  = (const float*)d_in[4];
    const float* qkv_b  = (const float*)d_in[5];
    const float* ow     = (const float*)d_in[6];
    const float* ob     = (const float*)d_in[7];
    const float* g1     = (const float*)d_in[8];
    const float* beta1  = (const float*)d_in[9];
    const float* gw     = (const float*)d_in[10];
    const float* gb     = (const float*)d_in[11];
    const float* ew1    = (const float*)d_in[12];
    const float* eb1    = (const float*)d_in[13];
    const float* ew2    = (const float*)d_in[14];
    const float* eb2    = (const float*)d_in[15];
    const float* g2     = (const float*)d_in[16];
    const float* beta2  = (const float*)d_in[17];
    const float* hw     = (const float*)d_in[18];
    const float* hb     = (const float*)d_in[19];
    const int*   fidx   = (const int*)d_in[20];
    float* out = (float*)d_out;

    float *h, *qkv, *attn, *tmp, *hid, *eo, *wt, *istats;
    int *cnt, *etok, *slot;
    cudaGetSymbolAddress((void**)&h,      g_h);
    cudaGetSymbolAddress((void**)&qkv,    g_qkv);
    cudaGetSymbolAddress((void**)&attn,   g_attn);
    cudaGetSymbolAddress((void**)&tmp,    g_tmp);
    cudaGetSymbolAddress((void**)&hid,    g_hid);
    cudaGetSymbolAddress((void**)&eo,     g_eo);
    cudaGetSymbolAddress((void**)&cnt,    g_cnt);
    cudaGetSymbolAddress((void**)&etok,   g_etok);
    cudaGetSymbolAddress((void**)&slot,   g_slot);
    cudaGetSymbolAddress((void**)&wt,     g_wt);
    cudaGetSymbolAddress((void**)&istats, g_istats);

    cudaFuncSetAttribute(attn_kernel, cudaFuncAttributeMaxDynamicSharedMemorySize, ATTN_SMEM);

    istats_kernel<<<BB*FF, 256>>>(x, istats);
    embed_kernel<<<TT, 128>>>(x, Wp, bp, femb, fidx, istats, h);

    for (int l = 0; l < LL; l++) {
        // QKV projection [8192,512] x [1536,512]^T
        gemm_mma<false,false><<<dim3(3*DD/128, TT/128, 1), 256>>>(
            h, qkv_w + (long)l*3*DD*DD, qkv_b + l*3*DD, qkv,
            TT, 3*DD, DD, DD, 3*DD, 0, 0, 0, 0, nullptr, nullptr);
        // attention
        attn_kernel<<<dim3(SS/64, HH, BB), 256, ATTN_SMEM>>>(qkv, attn);
        // output projection
        gemm_mma<false,false><<<dim3(DD/128, TT/128, 1), 256>>>(
            attn, ow + (long)l*DD*DD, ob + l*DD, tmp,
            TT, DD, DD, DD, DD, 0, 0, 0, 0, nullptr, nullptr);
        add_ln_kernel<<<TT, 128>>>(h, tmp, g1 + l*DD, beta1 + l*DD, h);
        // MoE
        zero_counts_kernel<<<1, 32>>>(cnt);
        gate_kernel<<<TT/4, 128>>>(h, gw + l*EE*DD, gb + l*EE, cnt, etok, slot, wt);
        gemm_mma<true,true><<<dim3(2*DD/128, TT/128, EE), 256>>>(
            h, ew1 + (long)l*EE*2*DD*DD, eb1 + l*EE*2*DD, hid,
            TT, 2*DD, DD, DD, 2*DD,
            0, (long)2*DD*DD, 2*DD, (long)TT*2*DD, etok, cnt);
        gemm_mma<false,false><<<dim3(DD/128, TT/128, EE), 256>>>(
            hid, ew2 + (long)l*EE*DD*2*DD, eb2 + l*EE*DD, eo,
            TT, DD, 2*DD, 2*DD, DD,
            (long)TT*2*DD, (long)DD*2*DD, DD, (long)TT*DD, nullptr, cnt);
        moe_combine_ln_kernel<<<TT, 128>>>(h, eo, slot, wt, g2 + l*DD, beta2 + l*DD, h);
    }
    head_kernel<<<1, 768>>>(h, hw, hb, out);
}

// round 4
// speedup vs baseline: 2.7605x; 1.4019x over previous
#include <cuda_runtime.h>
#include <math.h>
#include <cstdint>

#define BB 8
#define SS 1024
#define FF 8
#define DD 512
#define HH 8
#define LL 3
#define EE 4
#define TT (BB*SS)
#define HD 64

// ---------------- scratch (device globals; no allocs allowed) ----------------
__device__ float g_h[TT*DD];
__device__ float g_qkv[TT*3*DD];
__device__ float g_attn[TT*DD];
__device__ float g_tmp[TT*DD];
__device__ float g_hid[(size_t)EE*TT*2*DD];
__device__ float g_eo[(size_t)EE*TT*DD];
__device__ int   g_cnt[EE];
__device__ int   g_etok[EE*TT];
__device__ int   g_slot[2*TT];
__device__ float g_wt[2*TT];
__device__ float g_istats[BB*FF*2];

__device__ __forceinline__ float to_tf32(float x) {
    float r; asm("cvt.rna.tf32.f32 %0, %1;" : "=f"(r) : "f"(x)); return r;
}
__device__ __forceinline__ void mma_tf32(float* d, const uint32_t* a, const uint32_t* b) {
    asm volatile(
      "mma.sync.aligned.m16n8k8.row.col.f32.tf32.tf32.f32 "
      "{%0,%1,%2,%3}, {%4,%5,%6,%7}, {%8,%9}, {%0,%1,%2,%3};"
      : "+f"(d[0]), "+f"(d[1]), "+f"(d[2]), "+f"(d[3])
      : "r"(a[0]), "r"(a[1]), "r"(a[2]), "r"(a[3]), "r"(b[0]), "r"(b[1]));
}

// ================= mma.sync tf32 GEMM: C[M,N] = A[M,K] @ W[N,K]^T + bias =================
#define SMS 36   // smem row stride in floats (32 + 4 pad)
template<bool GATHER, bool RELU>
__global__ void __launch_bounds__(256) gemm_mma(
    const float* __restrict__ A, const float* __restrict__ W,
    const float* __restrict__ bias, float* __restrict__ C,
    int M, int N, int Kd, int lda, int ldc,
    long astride, long wstride, int bstride, long cstride,
    const int* __restrict__ gidx, const int* __restrict__ cnts)
{
    __shared__ float As[128*SMS];
    __shared__ float Bs[128*SMS];

    int e = blockIdx.z;
    A    += (long)e * astride;
    W    += (long)e * wstride;
    bias += (long)e * bstride;
    C    += (long)e * cstride;
    if (cnts) M = cnts[e];
    int m0 = blockIdx.y * 128;
    if (m0 >= M) return;
    int n0 = blockIdx.x * 128;

    int tid = threadIdx.x, lane = tid & 31, warp = tid >> 5;
    int wm = (warp >> 2) * 64;
    int wn = (warp & 3) * 32;

    const float* ap[4];
    const float* bp[4];
#pragma unroll
    for (int p = 0; p < 4; p++) {
        int i = tid + p * 256;
        int row = i >> 3, c4 = i & 7;
        int mr = m0 + row;
        if (mr < M) {
            int ar = GATHER ? gidx[(long)e * TT + mr] : mr;
            ap[p] = A + (long)ar * lda + c4 * 4;
        } else ap[p] = nullptr;
        bp[p] = W + (long)(n0 + row) * Kd + c4 * 4;
    }

    float4 aReg[4], bReg[4];
#pragma unroll
    for (int p = 0; p < 4; p++) {
        aReg[p] = ap[p] ? *(const float4*)(ap[p]) : make_float4(0.f,0.f,0.f,0.f);
        bReg[p] = *(const float4*)(bp[p]);
    }

    float acc[4][4][4];
#pragma unroll
    for (int a_ = 0; a_ < 4; a_++)
#pragma unroll
        for (int b_ = 0; b_ < 4; b_++)
#pragma unroll
            for (int c_ = 0; c_ < 4; c_++) acc[a_][b_][c_] = 0.f;

    int nkt = Kd / 32;
    for (int kt = 0; kt < nkt; kt++) {
#pragma unroll
        for (int p = 0; p < 4; p++) {
            int i = tid + p * 256;
            int row = i >> 3, c4 = i & 7;
            float4 a = aReg[p], b = bReg[p];
            a.x = to_tf32(a.x); a.y = to_tf32(a.y); a.z = to_tf32(a.z); a.w = to_tf32(a.w);
            b.x = to_tf32(b.x); b.y = to_tf32(b.y); b.z = to_tf32(b.z); b.w = to_tf32(b.w);
            *(float4*)&As[row*SMS + c4*4] = a;
            *(float4*)&Bs[row*SMS + c4*4] = b;
        }
        __syncthreads();
        if (kt + 1 < nkt) {
            int koff = (kt + 1) * 32;
#pragma unroll
            for (int p = 0; p < 4; p++) {
                aReg[p] = ap[p] ? *(const float4*)(ap[p] + koff) : make_float4(0.f,0.f,0.f,0.f);
                bReg[p] = *(const float4*)(bp[p] + koff);
            }
        }
        const uint32_t* Asu = (const uint32_t*)As;
        const uint32_t* Bsu = (const uint32_t*)Bs;
#pragma unroll
        for (int ks = 0; ks < 4; ks++) {
            int k0 = ks * 8 + (lane & 3);
            uint32_t af[4][4], bf[4][2];
            int r0 = wm + (lane >> 2);
#pragma unroll
            for (int mf = 0; mf < 4; mf++) {
                int r = r0 + mf * 16;
                af[mf][0] = Asu[r*SMS + k0];
                af[mf][1] = Asu[(r+8)*SMS + k0];
                af[mf][2] = Asu[r*SMS + k0 + 4];
                af[mf][3] = Asu[(r+8)*SMS + k0 + 4];
            }
            int nb = wn + (lane >> 2);
#pragma unroll
            for (int nf = 0; nf < 4; nf++) {
                int n = nb + nf * 8;
                bf[nf][0] = Bsu[n*SMS + k0];
                bf[nf][1] = Bsu[n*SMS + k0 + 4];
            }
#pragma unroll
            for (int mf = 0; mf < 4; mf++)
#pragma unroll
                for (int nf = 0; nf < 4; nf++)
                    mma_tf32(acc[mf][nf], af[mf], bf[nf]);
        }
        __syncthreads();
    }

#pragma unroll
    for (int mf = 0; mf < 4; mf++) {
        int rA = m0 + wm + mf*16 + (lane >> 2);
        int rB = rA + 8;
#pragma unroll
        for (int nf = 0; nf < 4; nf++) {
            int col = n0 + wn + nf*8 + (lane & 3) * 2;
            float2 bb = *(const float2*)&bias[col];
            float2 v0, v1;
            v0.x = acc[mf][nf][0] + bb.x; v0.y = acc[mf][nf][1] + bb.y;
            v1.x = acc[mf][nf][2] + bb.x; v1.y = acc[mf][nf][3] + bb.y;
            if (RELU) {
                v0.x = fmaxf(v0.x, 0.f); v0.y = fmaxf(v0.y, 0.f);
                v1.x = fmaxf(v1.x, 0.f); v1.y = fmaxf(v1.y, 0.f);
            }
            if (rA < M) *(float2*)&C[(long)rA*ldc + col] = v0;
            if (rB < M) *(float2*)&C[(long)rB*ldc + col] = v1;
        }
    }
}

// ================= attention: flash-style with tf32 mma.sync =================
// CTA: 128 queries of one (b,h); 16 chunks of 64 keys; 8 warps = 16 rows each.
#define QT 128
#define KC 64
#define SQ 76      // stride for Qs/Ks/Ps: (r*76+k) covers all 32 banks per fragment load
#define SV 72      // stride for Vs: (k*72+n) covers all 32 banks
#define ATT_SMEM ((QT*SQ + KC*SQ + KC*SV + QT*SQ) * 4)
__global__ void __launch_bounds__(256) attn_mma_kernel(const float* __restrict__ qkv,
                                                       float* __restrict__ out)
{
    extern __shared__ float sm[];
    float* Qs = sm;                 // QT x SQ
    float* Ks = Qs + QT*SQ;         // KC x SQ
    float* Vs = Ks + KC*SQ;         // KC x SV
    float* Ps = Vs + KC*SV;         // QT x SQ

    int q0 = blockIdx.x * QT;
    int hh = blockIdx.y;
    int b  = blockIdx.z;
    int tid = threadIdx.x, lane = tid & 31, warp = tid >> 5;
    const float* base = qkv + (long)b * SS * (3*DD) + hh * HD;

    // stage Q (pre-scaled by 1/8, tf32-rounded)
    {
        int row = tid >> 1, dbase = (tid & 1) * 32;
        const float* qp = base + (long)(q0 + row) * (3*DD) + dbase;
        float* dst = &Qs[row*SQ + dbase];
#pragma unroll
        for (int v = 0; v < 8; v++) {
            float4 x = *(const float4*)(qp + v*4);
            dst[v*4+0] = to_tf32(x.x * 0.125f);
            dst[v*4+1] = to_tf32(x.y * 0.125f);
            dst[v*4+2] = to_tf32(x.z * 0.125f);
            dst[v*4+3] = to_tf32(x.w * 0.125f);
        }
    }

    int r0 = warp*16 + (lane >> 2);
    float mm0 = -1e30f, mm1 = -1e30f, ll0 = 0.f, ll1 = 0.f;
    float o[8][4];
#pragma unroll
    for (int nf = 0; nf < 8; nf++)
#pragma unroll
        for (int c = 0; c < 4; c++) o[nf][c] = 0.f;

    const uint32_t* Qsu = (const uint32_t*)Qs;
    const uint32_t* Ksu = (const uint32_t*)Ks;
    const uint32_t* Vsu = (const uint32_t*)Vs;
    const uint32_t* Psu = (const uint32_t*)Ps;

    for (int jc = 0; jc < SS/KC; jc++) {
        __syncthreads();
        // stage K, V chunk (tf32)
        {
            int j = tid >> 2, dbase = (tid & 3) * 16;
            const float* kp = base + (long)(jc*KC + j) * (3*DD) + DD + dbase;
            const float* vp = kp + DD;
            float* kd = &Ks[j*SQ + dbase];
            float* vd = &Vs[j*SV + dbase];
#pragma unroll
            for (int v = 0; v < 4; v++) {
                float4 kx = *(const float4*)(kp + v*4);
                float4 vx = *(const float4*)(vp + v*4);
                kd[v*4+0]=to_tf32(kx.x); kd[v*4+1]=to_tf32(kx.y);
                kd[v*4+2]=to_tf32(kx.z); kd[v*4+3]=to_tf32(kx.w);
                vd[v*4+0]=to_tf32(vx.x); vd[v*4+1]=to_tf32(vx.y);
                vd[v*4+2]=to_tf32(vx.z); vd[v*4+3]=to_tf32(vx.w);
            }
        }
        __syncthreads();

        // S = Q K^T  (scores already scaled via Q)
        float s[8][4];
#pragma unroll
        for (int nf = 0; nf < 8; nf++)
#pragma unroll
            for (int c = 0; c < 4; c++) s[nf][c] = 0.f;
#pragma unroll
        for (int ks = 0; ks < 8; ks++) {
            int k0 = ks*8 + (lane & 3);
            uint32_t a[4];
            a[0] = Qsu[r0*SQ + k0];
            a[1] = Qsu[(r0+8)*SQ + k0];
            a[2] = Qsu[r0*SQ + k0 + 4];
            a[3] = Qsu[(r0+8)*SQ + k0 + 4];
#pragma unroll
            for (int nf = 0; nf < 8; nf++) {
                int n = nf*8 + (lane >> 2);
                uint32_t bfr[2];
                bfr[0] = Ksu[n*SQ + k0];
                bfr[1] = Ksu[n*SQ + k0 + 4];
                mma_tf32(s[nf], a, bfr);
            }
        }

        // online softmax (rows r0 and r0+8; quad-local reductions)
        float mx0 = mm0, mx1 = mm1;
#pragma unroll
        for (int nf = 0; nf < 8; nf++) {
            mx0 = fmaxf(mx0, fmaxf(s[nf][0], s[nf][1]));
            mx1 = fmaxf(mx1, fmaxf(s[nf][2], s[nf][3]));
        }
        mx0 = fmaxf(mx0, __shfl_xor_sync(0xffffffffu, mx0, 1));
        mx0 = fmaxf(mx0, __shfl_xor_sync(0xffffffffu, mx0, 2));
        mx1 = fmaxf(mx1, __shfl_xor_sync(0xffffffffu, mx1, 1));
        mx1 = fmaxf(mx1, __shfl_xor_sync(0xffffffffu, mx1, 2));
        float al0 = __expf(mm0 - mx0), al1 = __expf(mm1 - mx1);
        float sum0 = 0.f, sum1 = 0.f;
#pragma unroll
        for (int nf = 0; nf < 8; nf++) {
            s[nf][0] = __expf(s[nf][0] - mx0);
            s[nf][1] = __expf(s[nf][1] - mx0);
            s[nf][2] = __expf(s[nf][2] - mx1);
            s[nf][3] = __expf(s[nf][3] - mx1);
            sum0 += s[nf][0] + s[nf][1];
            sum1 += s[nf][2] + s[nf][3];
        }
        sum0 += __shfl_xor_sync(0xffffffffu, sum0, 1);
        sum0 += __shfl_xor_sync(0xffffffffu, sum0, 2);
        sum1 += __shfl_xor_sync(0xffffffffu, sum1, 1);
        sum1 += __shfl_xor_sync(0xffffffffu, sum1, 2);
        ll0 = ll0*al0 + sum0; ll1 = ll1*al1 + sum1;
        mm0 = mx0; mm1 = mx1;
#pragma unroll
        for (int nf = 0; nf < 8; nf++) {
            o[nf][0] *= al0; o[nf][1] *= al0;
            o[nf][2] *= al1; o[nf][3] *= al1;
        }
        // write P (tf32) — warp-local rows
#pragma unroll
        for (int nf = 0; nf < 8; nf++) {
            float2 p01 = make_float2(to_tf32(s[nf][0]), to_tf32(s[nf][1]));
            float2 p23 = make_float2(to_tf32(s[nf][2]), to_tf32(s[nf][3]));
            *(float2*)&Ps[r0*SQ + nf*8 + 2*(lane & 3)]     = p01;
            *(float2*)&Ps[(r0+8)*SQ + nf*8 + 2*(lane & 3)] = p23;
        }
        __syncwarp();

        // O += P V
#pragma unroll
        for (int ks = 0; ks < 8; ks++) {
            int k0 = ks*8 + (lane & 3);
            uint32_t a[4];
            a[0] = Psu[r0*SQ + k0];
            a[1] = Psu[(r0+8)*SQ + k0];
            a[2] = Psu[r0*SQ + k0 + 4];
            a[3] = Psu[(r0+8)*SQ + k0 + 4];
#pragma unroll
            for (int nf = 0; nf < 8; nf++) {
                int n = nf*8 + (lane >> 2);
                uint32_t bfr[2];
                bfr[0] = Vsu[k0*SV + n];
                bfr[1] = Vsu[(k0+4)*SV + n];
                mma_tf32(o[nf], a, bfr);
            }
        }
        __syncwarp();
    }

    // epilogue
    float inv0 = 1.f / ll0, inv1 = 1.f / ll1;
    long tok0 = (long)(b*SS + q0 + r0) * DD + hh*HD;
    long tok1 = tok0 + 8L*DD;
#pragma unroll
    for (int nf = 0; nf < 8; nf++) {
        int col = nf*8 + 2*(lane & 3);
        *(float2*)&out[tok0 + col] = make_float2(o[nf][0]*inv0, o[nf][1]*inv0);
        *(float2*)&out[tok1 + col] = make_float2(o[nf][2]*inv1, o[nf][3]*inv1);
    }
}

// ---------------- instance-norm stats ----------------
__global__ void istats_kernel(const float* __restrict__ x, float* __restrict__ stats)
{
    int bf = blockIdx.x;
    int b = bf >> 3, f = bf & 7;
    int tid = threadIdx.x;
    float s = 0.f, ss = 0.f;
    for (int i = tid; i < SS; i += 256) {
        float v = x[((long)b*SS + i)*FF + f];
        s += v; ss += v*v;
    }
    __shared__ float red[16];
    int lane = tid & 31, wid = tid >> 5;
#pragma unroll
    for (int o = 16; o; o >>= 1) {
        s  += __shfl_down_sync(0xffffffffu, s, o);
        ss += __shfl_down_sync(0xffffffffu, ss, o);
    }
    if (!lane) { red[wid] = s; red[8+wid] = ss; }
    __syncthreads();
    if (!tid) {
        float S = 0.f, Q = 0.f;
        for (int w = 0; w < 8; w++) { S += red[w]; Q += red[8+w]; }
        float m = S / SS;
        float var = (Q - SS*m*m) / (SS - 1);
        stats[bf*2]   = m;
        stats[bf*2+1] = 1.f / (sqrtf(var) + 1e-5f);
    }
}

// ---------------- embed ----------------
__global__ void embed_kernel(const float* __restrict__ x, const float* __restrict__ Wp,
                             const float* __restrict__ bp, const float* __restrict__ femb,
                             const int* __restrict__ fidx, const float* __restrict__ stats,
                             float* __restrict__ h)
{
    int token = blockIdx.x;
    int b = token >> 10, s = token & 1023;
    int tid = threadIdx.x;
    __shared__ float xn[8];
    if (tid < 8) {
        float m = stats[(b*8+tid)*2], inv = stats[(b*8+tid)*2+1];
        xn[tid] = (x[(long)token*FF + tid] - m) * inv;
    }
    __syncthreads();
    int fi = *fidx;
    int d0 = tid * 4;
    float4 acc = *(const float4*)&bp[d0];
    float* ap = &acc.x;
#pragma unroll
    for (int f = 0; f < 8; f++) {
        float xv = xn[f];
        ap[0] += xv * Wp[(d0+0)*8+f];
        ap[1] += xv * Wp[(d0+1)*8+f];
        ap[2] += xv * Wp[(d0+2)*8+f];
        ap[3] += xv * Wp[(d0+3)*8+f];
    }
    const float c = -0.0179889460f;
#pragma unroll
    for (int j = 0; j < 4; j++) {
        int d = d0 + j;
        int i = d >> 1;
        float ang = (float)s * expf((float)(2*i) * c);
        float pe = (d & 1) ? cosf(ang) : sinf(ang);
        ap[j] += femb[fi*DD + d] + pe;
    }
    *(float4*)&h[(long)token*DD + d0] = acc;
}

// ---------------- add + layernorm ----------------
__global__ void add_ln_kernel(const float* __restrict__ base, const float* __restrict__ add,
                              const float* __restrict__ g, const float* __restrict__ bet,
                              float* __restrict__ out)
{
    long t = blockIdx.x;
    int tid = threadIdx.x;
    float4 xb = *(const float4*)&base[t*DD + tid*4];
    float4 xa = *(const float4*)&add[t*DD + tid*4];
    float v0=xb.x+xa.x, v1=xb.y+xa.y, v2=xb.z+xa.z, v3=xb.w+xa.w;
    float s = v0+v1+v2+v3, ss = v0*v0+v1*v1+v2*v2+v3*v3;
    __shared__ float red[16];
    int lane = tid & 31, wid = tid >> 5;
#pragma unroll
    for (int o = 16; o; o >>= 1) {
        s  += __shfl_down_sync(0xffffffffu, s, o);
        ss += __shfl_down_sync(0xffffffffu, ss, o);
    }
    if (!lane) { red[wid] = s; red[8+wid] = ss; }
    __syncthreads();
    if (!tid) {
        float S = red[0]+red[1]+red[2]+red[3];
        float Q = red[8]+red[9]+red[10]+red[11];
        red[0] = S * (1.f/DD);
        red[1] = Q * (1.f/DD);
    }
    __syncthreads();
    float m = red[0];
    float r = rsqrtf(red[1] - m*m + 1e-5f);
    float4 gv = *(const float4*)&g[tid*4];
    float4 bv = *(const float4*)&bet[tid*4];
    float4 o4;
    o4.x = (v0-m)*r*gv.x + bv.x;
    o4.y = (v1-m)*r*gv.y + bv.y;
    o4.z = (v2-m)*r*gv.z + bv.z;
    o4.w = (v3-m)*r*gv.w + bv.w;
    *(float4*)&out[t*DD + tid*4] = o4;
}

// ---------------- moe combine + layernorm ----------------
__global__ void moe_combine_ln_kernel(const float* __restrict__ h, const float* __restrict__ eo,
                                      const int* __restrict__ slot, const float* __restrict__ wt,
                                      const float* __restrict__ g, const float* __restrict__ bet,
                                      float* __restrict__ out)
{
    long t = blockIdx.x;
    int tid = threadIdx.x;
    int s0 = slot[2*t], s1 = slot[2*t+1];
    float w0 = wt[2*t], w1 = wt[2*t+1];
    float4 xh = *(const float4*)&h[t*DD + tid*4];
    float4 e0 = *(const float4*)&eo[(long)s0*DD + tid*4];
    float4 e1 = *(const float4*)&eo[(long)s1*DD + tid*4];
    float v0 = xh.x + w0*e0.x + w1*e1.x;
    float v1 = xh.y + w0*e0.y + w1*e1.y;
    float v2 = xh.z + w0*e0.z + w1*e1.z;
    float v3 = xh.w + w0*e0.w + w1*e1.w;
    float s = v0+v1+v2+v3, ss = v0*v0+v1*v1+v2*v2+v3*v3;
    __shared__ float red[16];
    int lane = tid & 31, wid = tid >> 5;
#pragma unroll
    for (int o = 16; o; o >>= 1) {
        s  += __shfl_down_sync(0xffffffffu, s, o);
        ss += __shfl_down_sync(0xffffffffu, ss, o);
    }
    if (!lane) { red[wid] = s; red[8+wid] = ss; }
    __syncthreads();
    if (!tid) {
        float S = red[0]+red[1]+red[2]+red[3];
        float Q = red[8]+red[9]+red[10]+red[11];
        red[0] = S * (1.f/DD);
        red[1] = Q * (1.f/DD);
    }
    __syncthreads();
    float m = red[0];
    float r = rsqrtf(red[1] - m*m + 1e-5f);
    float4 gv = *(const float4*)&g[tid*4];
    float4 bv = *(const float4*)&bet[tid*4];
    float4 o4;
    o4.x = (v0-m)*r*gv.x + bv.x;
    o4.y = (v1-m)*r*gv.y + bv.y;
    o4.z = (v2-m)*r*gv.z + bv.z;
    o4.w = (v3-m)*r*gv.w + bv.w;
    *(float4*)&out[t*DD + tid*4] = o4;
}

// ---------------- gating ----------------
__global__ void zero_counts_kernel(int* c) { if (threadIdx.x < EE) c[threadIdx.x] = 0; }

__global__ void gate_kernel(const float* __restrict__ h, const float* __restrict__ gw,
                            const float* __restrict__ gb, int* __restrict__ cnt,
                            int* __restrict__ etok, int* __restrict__ slot,
                            float* __restrict__ wt)
{
    int t = blockIdx.x * 4 + (threadIdx.x >> 5);
    int lane = threadIdx.x & 31;
    const float* hp = h + (long)t * DD;
    float acc[4] = {0.f,0.f,0.f,0.f};
#pragma unroll
    for (int it = 0; it < 4; it++) {
        int d0 = (it*32 + lane) * 4;
        float4 xv = *(const float4*)&hp[d0];
#pragma unroll
        for (int e = 0; e < 4; e++) {
            float4 wv = *(const float4*)&gw[e*DD + d0];
            acc[e] += xv.x*wv.x + xv.y*wv.y + xv.z*wv.z + xv.w*wv.w;
        }
    }
#pragma unroll
    for (int e = 0; e < 4; e++)
#pragma unroll
        for (int o = 16; o; o >>= 1)
            acc[e] += __shfl_down_sync(0xffffffffu, acc[e], o);
    if (!lane) {
        float lg[4], p[4];
        float mx = -1e30f;
#pragma unroll
        for (int e = 0; e < 4; e++) { lg[e] = acc[e] + gb[e]; mx = fmaxf(mx, lg[e]); }
        float sum = 0.f;
#pragma unroll
        for (int e = 0; e < 4; e++) { p[e] = expf(lg[e]-mx); sum += p[e]; }
#pragma unroll
        for (int e = 0; e < 4; e++) p[e] /= sum;
        int i0 = 0;
#pragma unroll
        for (int e = 1; e < 4; e++) if (p[e] > p[i0]) i0 = e;
        int i1 = (i0 == 0) ? 1 : 0;
#pragma unroll
        for (int e = 0; e < 4; e++) if (e != i0 && p[e] > p[i1]) i1 = e;
        float w0 = p[i0], w1 = p[i1];
        float inv = 1.f / (w0 + w1);
        int pos0 = atomicAdd(&cnt[i0], 1);
        etok[i0*TT + pos0] = t;
        slot[2*t]   = i0*TT + pos0;
        wt[2*t]     = w0 * inv;
        int pos1 = atomicAdd(&cnt[i1], 1);
        etok[i1*TT + pos1] = t;
        slot[2*t+1] = i1*TT + pos1;
        wt[2*t+1]   = w1 * inv;
    }
}

// ---------------- head ----------------
__global__ void head_kernel(const float* __restrict__ h, const float* __restrict__ hw,
                            const float* __restrict__ hb, float* __restrict__ out)
{
    int w = threadIdx.x >> 5, lane = threadIdx.x & 31;
    int b = w / 3, i = w % 3;
    const float* hp = h + ((long)(b*SS + SS-1)) * DD;
    float s = 0.f;
#pragma unroll
    for (int it = 0; it < 4; it++) {
        int d0 = (it*32 + lane) * 4;
        float4 a = *(const float4*)&hp[d0];
        float4 c = *(const float4*)&hw[i*DD + d0];
        s += a.x*c.x + a.y*c.y + a.z*c.z + a.w*c.w;
    }
#pragma unroll
    for (int o = 16; o; o >>= 1) s += __shfl_down_sync(0xffffffffu, s, o);
    if (!lane) out[b*3+i] = s + hb[i];
}

// ---------------- orchestration ----------------
extern "C" void kernel_launch(void* const* d_in, const int* in_sizes, int n_in,
                              void* d_out, int out_size)
{
    const float* x      = (const float*)d_in[0];
    const float* Wp     = (const float*)d_in[1];
    const float* bp     = (const float*)d_in[2];
    const float* femb   = (const float*)d_in[3];
    const float* qkv_w  = (const float*)d_in[4];
    const float* qkv_b  = (const float*)d_in[5];
    const float* ow     = (const float*)d_in[6];
    const float* ob     = (const float*)d_in[7];
    const float* g1     = (const float*)d_in[8];
    const float* beta1  = (const float*)d_in[9];
    const float* gw     = (const float*)d_in[10];
    const float* gb     = (const float*)d_in[11];
    const float* ew1    = (const float*)d_in[12];
    const float* eb1    = (const float*)d_in[13];
    const float* ew2    = (const float*)d_in[14];
    const float* eb2    = (const float*)d_in[15];
    const float* g2     = (const float*)d_in[16];
    const float* beta2  = (const float*)d_in[17];
    const float* hw     = (const float*)d_in[18];
    const float* hb     = (const float*)d_in[19];
    const int*   fidx   = (const int*)d_in[20];
    float* out = (float*)d_out;

    float *h, *qkv, *attn, *tmp, *hid, *eo, *wt, *istats;
    int *cnt, *etok, *slot;
    cudaGetSymbolAddress((void**)&h,      g_h);
    cudaGetSymbolAddress((void**)&qkv,    g_qkv);
    cudaGetSymbolAddress((void**)&attn,   g_attn);
    cudaGetSymbolAddress((void**)&tmp,    g_tmp);
    cudaGetSymbolAddress((void**)&hid,    g_hid);
    cudaGetSymbolAddress((void**)&eo,     g_eo);
    cudaGetSymbolAddress((void**)&cnt,    g_cnt);
    cudaGetSymbolAddress((void**)&etok,   g_etok);
    cudaGetSymbolAddress((void**)&slot,   g_slot);
    cudaGetSymbolAddress((void**)&wt,     g_wt);
    cudaGetSymbolAddress((void**)&istats, g_istats);

    cudaFuncSetAttribute(attn_mma_kernel, cudaFuncAttributeMaxDynamicSharedMemorySize, ATT_SMEM);

    istats_kernel<<<BB*FF, 256>>>(x, istats);
    embed_kernel<<<TT, 128>>>(x, Wp, bp, femb, fidx, istats, h);

    for (int l = 0; l < LL; l++) {
        // QKV projection [8192,512] x [1536,512]^T
        gemm_mma<false,false><<<dim3(3*DD/128, TT/128, 1), 256>>>(
            h, qkv_w + (long)l*3*DD*DD, qkv_b + l*3*DD, qkv,
            TT, 3*DD, DD, DD, 3*DD, 0, 0, 0, 0, nullptr, nullptr);
        // attention (tensor-core flash)
        attn_mma_kernel<<<dim3(SS/QT, HH, BB), 256, ATT_SMEM>>>(qkv, attn);
        // output projection
        gemm_mma<false,false><<<dim3(DD/128, TT/128, 1), 256>>>(
            attn, ow + (long)l*DD*DD, ob + l*DD, tmp,
            TT, DD, DD, DD, DD, 0, 0, 0, 0, nullptr, nullptr);
        add_ln_kernel<<<TT, 128>>>(h, tmp, g1 + l*DD, beta1 + l*DD, h);
        // MoE
        zero_counts_kernel<<<1, 32>>>(cnt);
        gate_kernel<<<TT/4, 128>>>(h, gw + l*EE*DD, gb + l*EE, cnt, etok, slot, wt);
        gemm_mma<true,true><<<dim3(2*DD/128, TT/128, EE), 256>>>(
            h, ew1 + (long)l*EE*2*DD*DD, eb1 + l*EE*2*DD, hid,
            TT, 2*DD, DD, DD, 2*DD,
            0, (long)2*DD*DD, 2*DD, (long)TT*2*DD, etok, cnt);
        gemm_mma<false,false><<<dim3(DD/128, TT/128, EE), 256>>>(
            hid, ew2 + (long)l*EE*DD*2*DD, eb2 + l*EE*DD, eo,
            TT, DD, 2*DD, 2*DD, DD,
            (long)TT*2*DD, (long)DD*2*DD, DD, (long)TT*DD, nullptr, cnt);
        moe_combine_ln_kernel<<<TT, 128>>>(h, eo, slot, wt, g2 + l*DD, beta2 + l*DD, h);
    }
    head_kernel<<<1, 768>>>(h, hw, hb, out);
}

// round 5
// speedup vs baseline: 5.0310x; 1.8225x over previous
#include <cuda_runtime.h>
#include <cuda_fp16.h>
#include <math.h>
#include <cstdint>

#define BB 8
#define SS 1024
#define FF 8
#define DD 512
#define HH 8
#define LL 3
#define EE 4
#define TT (BB*SS)
#define HD 64

// ---------------- scratch (device globals; no allocs allowed) ----------------
__device__ float g_h[TT*DD];
__device__ float g_tmp[TT*DD];
__device__ float g_eo[(size_t)EE*TT*DD];
__device__ int   g_cnt[EE];
__device__ int   g_etok[EE*TT];
__device__ int   g_slot[2*TT];
__device__ float g_wt[2*TT];
__device__ float g_istats[BB*FF*2];

__device__ __align__(16) __half g_h16[TT*DD];
__device__ __align__(16) __half g_qkv16[TT*3*DD];
__device__ __align__(16) __half g_attn16[TT*DD];
__device__ __align__(16) __half g_hid16[(size_t)EE*TT*2*DD];
__device__ __align__(16) __half g_qkvw16[LL*3*DD*DD];
__device__ __align__(16) __half g_ow16[LL*DD*DD];
__device__ __align__(16) __half g_ew116[(size_t)LL*EE*2*DD*DD];
__device__ __align__(16) __half g_ew216[(size_t)LL*EE*2*DD*DD];

__device__ __forceinline__ uint32_t smem_u32(const void* p) {
    uint32_t a;
    asm("{ .reg .u64 t; cvta.to.shared.u64 t, %1; cvt.u32.u64 %0, t; }" : "=r"(a) : "l"(p));
    return a;
}
__device__ __forceinline__ void mma_f16(float* d, const uint32_t* a, const uint32_t* b) {
    asm volatile(
      "mma.sync.aligned.m16n8k16.row.col.f32.f16.f16.f32 "
      "{%0,%1,%2,%3}, {%4,%5,%6,%7}, {%8,%9}, {%0,%1,%2,%3};"
      : "+f"(d[0]), "+f"(d[1]), "+f"(d[2]), "+f"(d[3])
      : "r"(a[0]), "r"(a[1]), "r"(a[2]), "r"(a[3]), "r"(b[0]), "r"(b[1]));
}
#define CP_ASYNC16(dst, src, sz) \
  asm volatile("cp.async.cg.shared.global [%0], [%1], 16, %2;" :: "r"(dst), "l"(src), "r"(sz) : "memory")
#define CP_COMMIT() asm volatile("cp.async.commit_group;" ::: "memory")
#define CP_WAIT0()  asm volatile("cp.async.wait_group 0;" ::: "memory")
#define CP_WAIT1()  asm volatile("cp.async.wait_group 1;" ::: "memory")

__device__ __forceinline__ uint32_t h2u(__half2 h) { return *(uint32_t*)&h; }

// ---------------- fp32 -> fp16 convert ----------------
__global__ void f2h_kernel(const float* __restrict__ in, __half* __restrict__ out, int n4)
{
    int i = blockIdx.x * 256 + threadIdx.x;
    if (i < n4) {
        float4 v = ((const float4*)in)[i];
        __half2* op = (__half2*)(out + 4L*i);
        op[0] = __floats2half2_rn(v.x, v.y);
        op[1] = __floats2half2_rn(v.z, v.w);
    }
}

// ================= fp16 mma GEMM: C[M,N] = A[M,K] @ W[N,K]^T + bias =================
// 128x128 CTA tile, BK=64, 8 warps (2x4), warp tile 64x32, cp.async 2-stage.
// smem rows: 64 halves = 32 words + 4 pad = 36 words (144 B)
#define GW 36
#define GBUF (128*GW*4)            // 18432 B per tile buffer
#define GEMM_SMEM (4*GBUF)         // A0,A1,B0,B1 = 73728
template<bool GATHER, bool RELU, int WMODE>   // WMODE bit0: fp32 C, bit1: half C16
__global__ void __launch_bounds__(256) gemm_h(
    const __half* __restrict__ A, const __half* __restrict__ W,
    const float* __restrict__ bias, float* __restrict__ C, __half* __restrict__ C16,
    int M, int N, int Kd, int lda, int ldc,
    long astride, long wstride, int bstride, long cstride,
    const int* __restrict__ gidx, const int* __restrict__ cnts)
{
    extern __shared__ char smem[];
    int e = blockIdx.z;
    A    += (long)e * astride;
    W    += (long)e * wstride;
    bias += (long)e * bstride;
    if (WMODE & 1) C   += (long)e * cstride;
    if (WMODE & 2) C16 += (long)e * cstride;
    if (cnts) M = cnts[e];
    int m0 = blockIdx.y * 128;
    if (m0 >= M) return;
    int n0 = blockIdx.x * 128;

    int tid = threadIdx.x, lane = tid & 31, warp = tid >> 5;
    int g = lane >> 2, t = lane & 3;
    int wm = (warp >> 2) * 64, wn = (warp & 3) * 32;

    uint32_t sb = smem_u32(smem);
    int rbase = tid >> 3, c8 = tid & 7;

    const __half* asrc[4]; uint32_t asz[4];
    const __half* bsrc[4];
    uint32_t adst[4], bdst[4];
#pragma unroll
    for (int p = 0; p < 4; p++) {
        int row = rbase + p * 32;
        int mr = m0 + row;
        bool ok = mr < M;
        int ar = 0;
        if (ok) ar = GATHER ? gidx[(long)e * TT + mr] : mr;
        asrc[p] = A + (long)ar * lda + c8 * 8;
        asz[p] = ok ? 16u : 0u;
        bsrc[p] = W + (long)(n0 + row) * Kd + c8 * 8;
        adst[p] = sb + row * 144 + c8 * 16;
        bdst[p] = sb + 2*GBUF + row * 144 + c8 * 16;
    }

    float acc[4][4][4];
#pragma unroll
    for (int a_ = 0; a_ < 4; a_++)
#pragma unroll
        for (int b_ = 0; b_ < 4; b_++)
#pragma unroll
            for (int c_ = 0; c_ < 4; c_++) acc[a_][b_][c_] = 0.f;

    int nkt = Kd / 64;
    // prologue: stage kt=0 into buf 0
#pragma unroll
    for (int p = 0; p < 4; p++) {
        CP_ASYNC16(adst[p], asrc[p], asz[p]);
        CP_ASYNC16(bdst[p], bsrc[p], 16u);
    }
    CP_COMMIT();

    for (int kt = 0; kt < nkt; kt++) {
        int buf = kt & 1;
        if (kt + 1 < nkt) {
            int koff = (kt + 1) * 64;
            uint32_t boff = ((kt + 1) & 1) * GBUF;
#pragma unroll
            for (int p = 0; p < 4; p++) {
                CP_ASYNC16(adst[p] + boff, asrc[p] + koff, asz[p]);
                CP_ASYNC16(bdst[p] + boff, bsrc[p] + koff, 16u);
            }
            CP_COMMIT();
            CP_WAIT1();
        } else {
            CP_WAIT0();
        }
        __syncthreads();

        const uint32_t* Aw = (const uint32_t*)(smem + buf * GBUF);
        const uint32_t* Bw = (const uint32_t*)(smem + 2*GBUF + buf * GBUF);
#pragma unroll
        for (int ks = 0; ks < 4; ks++) {
            int kb = ks * 8 + t;
            uint32_t af[4][4], bf[4][2];
            int r0 = wm + g;
#pragma unroll
            for (int mf = 0; mf < 4; mf++) {
                int r = r0 + mf * 16;
                af[mf][0] = Aw[r*GW + kb];
                af[mf][1] = Aw[(r+8)*GW + kb];
                af[mf][2] = Aw[r*GW + kb + 4];
                af[mf][3] = Aw[(r+8)*GW + kb + 4];
            }
#pragma unroll
            for (int nf = 0; nf < 4; nf++) {
                int n = wn + nf * 8 + g;
                bf[nf][0] = Bw[n*GW + kb];
                bf[nf][1] = Bw[n*GW + kb + 4];
            }
#pragma unroll
            for (int mf = 0; mf < 4; mf++)
#pragma unroll
                for (int nf = 0; nf < 4; nf++)
                    mma_f16(acc[mf][nf], af[mf], bf[nf]);
        }
        __syncthreads();
    }

#pragma unroll
    for (int mf = 0; mf < 4; mf++) {
        int rA = m0 + wm + mf*16 + g;
        int rB = rA + 8;
#pragma unroll
        for (int nf = 0; nf < 4; nf++) {
            int col = n0 + wn + nf*8 + t*2;
            float2 bb = *(const float2*)&bias[col];
            float2 v0, v1;
            v0.x = acc[mf][nf][0] + bb.x; v0.y = acc[mf][nf][1] + bb.y;
            v1.x = acc[mf][nf][2] + bb.x; v1.y = acc[mf][nf][3] + bb.y;
            if (RELU) {
                v0.x = fmaxf(v0.x, 0.f); v0.y = fmaxf(v0.y, 0.f);
                v1.x = fmaxf(v1.x, 0.f); v1.y = fmaxf(v1.y, 0.f);
            }
            if (rA < M) {
                if (WMODE & 1) *(float2*)&C[(long)rA*ldc + col] = v0;
                if (WMODE & 2) *(__half2*)&C16[(long)rA*ldc + col] = __floats2half2_rn(v0.x, v0.y);
            }
            if (rB < M) {
                if (WMODE & 1) *(float2*)&C[(long)rB*ldc + col] = v1;
                if (WMODE & 2) *(__half2*)&C16[(long)rB*ldc + col] = __floats2half2_rn(v1.x, v1.y);
            }
        }
    }
}

// ================= attention: flash-style with fp16 mma.sync =================
// CTA: 128 queries of one (b,h); 16 chunks of 64 keys; 8 warps x 16 rows.
// Q/K/P row stride 36 words; V interleaved k-pairs, stride 72 words.
#define AQW 36
#define AVW 72
#define ATT_SMEM ((128*AQW + 64*AQW + 32*AVW + 128*AQW) * 4)
__global__ void __launch_bounds__(256) attn_h_kernel(const __half* __restrict__ qkv,
                                                     __half* __restrict__ out)
{
    extern __shared__ char smc[];
    uint32_t* Qw = (uint32_t*)smc;
    uint32_t* Kw = Qw + 128*AQW;
    uint32_t* Vw = Kw + 64*AQW;
    uint32_t* Pw = Vw + 32*AVW;

    int q0 = blockIdx.x * 128;
    int hh = blockIdx.y;
    int b  = blockIdx.z;
    int tid = threadIdx.x, lane = tid & 31, warp = tid >> 5;
    int g = lane >> 2, t = lane & 3;
    const __half* base = qkv + (long)b * SS * (3*DD) + hh * HD;

    // stage Q (4 x 16B per thread)
#pragma unroll
    for (int p = 0; p < 4; p++) {
        int idx = tid + p*256;
        int row = idx >> 3, c8 = idx & 7;
        uint4 v = *(const uint4*)(base + (long)(q0 + row) * (3*DD) + c8*8);
        *(uint4*)&Qw[row*AQW + c8*4] = v;
    }

    int r0 = warp*16 + g;
    float mm0 = -1e30f, mm1 = -1e30f, ll0 = 0.f, ll1 = 0.f;
    float o[8][4];
#pragma unroll
    for (int nf = 0; nf < 8; nf++)
#pragma unroll
        for (int c = 0; c < 4; c++) o[nf][c] = 0.f;

    for (int jc = 0; jc < SS/64; jc++) {
        __syncthreads();
        // stage K (2 x 16B per thread)
#pragma unroll
        for (int p = 0; p < 2; p++) {
            int idx = tid + p*256;
            int j = idx >> 3, c8 = idx & 7;
            uint4 v = *(const uint4*)(base + (long)(jc*64 + j) * (3*DD) + DD + c8*8);
            *(uint4*)&Kw[j*AQW + c8*4] = v;
        }
        // stage V interleaved: thread -> (k-pair jp, n-octet)
        {
            int jp = tid >> 3, oct = tid & 7;
            const __half* vp = base + (long)(jc*64 + 2*jp) * (3*DD) + 2*DD + oct*8;
            uint4 va = *(const uint4*)vp;
            uint4 vb = *(const uint4*)(vp + 3*DD);
            __half2* ha = (__half2*)&va;
            __half2* hb = (__half2*)&vb;
            uint32_t* dst = &Vw[jp*AVW + oct*8];
#pragma unroll
            for (int i = 0; i < 4; i++) {
                dst[2*i]   = h2u(__lows2half2 (ha[i], hb[i]));
                dst[2*i+1] = h2u(__highs2half2(ha[i], hb[i]));
            }
        }
        __syncthreads();

        // S = Q K^T
        float s[8][4];
#pragma unroll
        for (int nf = 0; nf < 8; nf++)
#pragma unroll
            for (int c = 0; c < 4; c++) s[nf][c] = 0.f;
#pragma unroll
        for (int ks = 0; ks < 4; ks++) {
            int kb = ks*8 + t;
            uint32_t a[4];
            a[0] = Qw[r0*AQW + kb];
            a[1] = Qw[(r0+8)*AQW + kb];
            a[2] = Qw[r0*AQW + kb + 4];
            a[3] = Qw[(r0+8)*AQW + kb + 4];
#pragma unroll
            for (int nf = 0; nf < 8; nf++) {
                int n = nf*8 + g;
                uint32_t bfr[2];
                bfr[0] = Kw[n*AQW + kb];
                bfr[1] = Kw[n*AQW + kb + 4];
                mma_f16(s[nf], a, bfr);
            }
        }
        // scale + online softmax (quad-local)
        float mx0 = mm0, mx1 = mm1;
#pragma unroll
        for (int nf = 0; nf < 8; nf++) {
            s[nf][0] *= 0.125f; s[nf][1] *= 0.125f;
            s[nf][2] *= 0.125f; s[nf][3] *= 0.125f;
            mx0 = fmaxf(mx0, fmaxf(s[nf][0], s[nf][1]));
            mx1 = fmaxf(mx1, fmaxf(s[nf][2], s[nf][3]));
        }
        mx0 = fmaxf(mx0, __shfl_xor_sync(0xffffffffu, mx0, 1));
        mx0 = fmaxf(mx0, __shfl_xor_sync(0xffffffffu, mx0, 2));
        mx1 = fmaxf(mx1, __shfl_xor_sync(0xffffffffu, mx1, 1));
        mx1 = fmaxf(mx1, __shfl_xor_sync(0xffffffffu, mx1, 2));
        float al0 = __expf(mm0 - mx0), al1 = __expf(mm1 - mx1);
        float sum0 = 0.f, sum1 = 0.f;
#pragma unroll
        for (int nf = 0; nf < 8; nf++) {
            s[nf][0] = __expf(s[nf][0] - mx0);
            s[nf][1] = __expf(s[nf][1] - mx0);
            s[nf][2] = __expf(s[nf][2] - mx1);
            s[nf][3] = __expf(s[nf][3] - mx1);
            sum0 += s[nf][0] + s[nf][1];
            sum1 += s[nf][2] + s[nf][3];
        }
        sum0 += __shfl_xor_sync(0xffffffffu, sum0, 1);
        sum0 += __shfl_xor_sync(0xffffffffu, sum0, 2);
        sum1 += __shfl_xor_sync(0xffffffffu, sum1, 1);
        sum1 += __shfl_xor_sync(0xffffffffu, sum1, 2);
        ll0 = ll0*al0 + sum0; ll1 = ll1*al1 + sum1;
        mm0 = mx0; mm1 = mx1;
#pragma unroll
        for (int nf = 0; nf < 8; nf++) {
            o[nf][0] *= al0; o[nf][1] *= al0;
            o[nf][2] *= al1; o[nf][3] *= al1;
        }
        // write P as half (warp-local rows)
#pragma unroll
        for (int nf = 0; nf < 8; nf++) {
            Pw[r0*AQW + nf*4 + t]     = h2u(__floats2half2_rn(s[nf][0], s[nf][1]));
            Pw[(r0+8)*AQW + nf*4 + t] = h2u(__floats2half2_rn(s[nf][2], s[nf][3]));
        }
        __syncwarp();
        // O += P V
#pragma unroll
        for (int ks = 0; ks < 4; ks++) {
            int kb = ks*8 + t;
            uint32_t a[4];
            a[0] = Pw[r0*AQW + kb];
            a[1] = Pw[(r0+8)*AQW + kb];
            a[2] = Pw[r0*AQW + kb + 4];
            a[3] = Pw[(r0+8)*AQW + kb + 4];
#pragma unroll
            for (int nf = 0; nf < 8; nf++) {
                int n = nf*8 + g;
                uint32_t bfr[2];
                bfr[0] = Vw[(ks*8 + t)*AVW + n];
                bfr[1] = Vw[(ks*8 + t + 4)*AVW + n];
                mma_f16(o[nf], a, bfr);
            }
        }
    }

    float inv0 = 1.f / ll0, inv1 = 1.f / ll1;
    long tok0 = (long)(b*SS + q0 + r0) * DD + hh*HD;
    long tok1 = tok0 + 8L*DD;
#pragma unroll
    for (int nf = 0; nf < 8; nf++) {
        int col = nf*8 + 2*t;
        *(__half2*)&out[tok0 + col] = __floats2half2_rn(o[nf][0]*inv0, o[nf][1]*inv0);
        *(__half2*)&out[tok1 + col] = __floats2half2_rn(o[nf][2]*inv1, o[nf][3]*inv1);
    }
}

// ---------------- instance-norm stats ----------------
__global__ void istats_kernel(const float* __restrict__ x, float* __restrict__ stats)
{
    int bf = blockIdx.x;
    int b = bf >> 3, f = bf & 7;
    int tid = threadIdx.x;
    float s = 0.f, ss = 0.f;
    for (int i = tid; i < SS; i += 256) {
        float v = x[((long)b*SS + i)*FF + f];
        s += v; ss += v*v;
    }
    __shared__ float red[16];
    int lane = tid & 31, wid = tid >> 5;
#pragma unroll
    for (int o = 16; o; o >>= 1) {
        s  += __shfl_down_sync(0xffffffffu, s, o);
        ss += __shfl_down_sync(0xffffffffu, ss, o);
    }
    if (!lane) { red[wid] = s; red[8+wid] = ss; }
    __syncthreads();
    if (!tid) {
        float S = 0.f, Q = 0.f;
        for (int w = 0; w < 8; w++) { S += red[w]; Q += red[8+w]; }
        float m = S / SS;
        float var = (Q - SS*m*m) / (SS - 1);
        stats[bf*2]   = m;
        stats[bf*2+1] = 1.f / (sqrtf(var) + 1e-5f);
    }
}

// ---------------- embed (writes fp32 + fp16) ----------------
__global__ void embed_kernel(const float* __restrict__ x, const float* __restrict__ Wp,
                             const float* __restrict__ bp, const float* __restrict__ femb,
                             const int* __restrict__ fidx, const float* __restrict__ stats,
                             float* __restrict__ h, __half* __restrict__ h16)
{
    int token = blockIdx.x;
    int b = token >> 10, s = token & 1023;
    int tid = threadIdx.x;
    __shared__ float xn[8];
    if (tid < 8) {
        float m = stats[(b*8+tid)*2], inv = stats[(b*8+tid)*2+1];
        xn[tid] = (x[(long)token*FF + tid] - m) * inv;
    }
    __syncthreads();
    int fi = *fidx;
    int d0 = tid * 4;
    float4 acc = *(const float4*)&bp[d0];
    float* ap = &acc.x;
#pragma unroll
    for (int f = 0; f < 8; f++) {
        float xv = xn[f];
        ap[0] += xv * Wp[(d0+0)*8+f];
        ap[1] += xv * Wp[(d0+1)*8+f];
        ap[2] += xv * Wp[(d0+2)*8+f];
        ap[3] += xv * Wp[(d0+3)*8+f];
    }
    const float c = -0.0179889460f;
#pragma unroll
    for (int j = 0; j < 4; j++) {
        int d = d0 + j;
        int i = d >> 1;
        float ang = (float)s * expf((float)(2*i) * c);
        float pe = (d & 1) ? cosf(ang) : sinf(ang);
        ap[j] += femb[fi*DD + d] + pe;
    }
    *(float4*)&h[(long)token*DD + d0] = acc;
    __half2* hp = (__half2*)&h16[(long)token*DD + d0];
    hp[0] = __floats2half2_rn(acc.x, acc.y);
    hp[1] = __floats2half2_rn(acc.z, acc.w);
}

// ---------------- add + layernorm (writes fp32 + fp16) ----------------
__global__ void add_ln_kernel(const float* __restrict__ base, const float* __restrict__ add,
                              const float* __restrict__ g, const float* __restrict__ bet,
                              float* __restrict__ out, __half* __restrict__ out16)
{
    long t = blockIdx.x;
    int tid = threadIdx.x;
    float4 xb = *(const float4*)&base[t*DD + tid*4];
    float4 xa = *(const float4*)&add[t*DD + tid*4];
    float v0=xb.x+xa.x, v1=xb.y+xa.y, v2=xb.z+xa.z, v3=xb.w+xa.w;
    float s = v0+v1+v2+v3, ss = v0*v0+v1*v1+v2*v2+v3*v3;
    __shared__ float red[16];
    int lane = tid & 31, wid = tid >> 5;
#pragma unroll
    for (int o = 16; o; o >>= 1) {
        s  += __shfl_down_sync(0xffffffffu, s, o);
        ss += __shfl_down_sync(0xffffffffu, ss, o);
    }
    if (!lane) { red[wid] = s; red[8+wid] = ss; }
    __syncthreads();
    if (!tid) {
        float S = red[0]+red[1]+red[2]+red[3];
        float Q = red[8]+red[9]+red[10]+red[11];
        red[0] = S * (1.f/DD);
        red[1] = Q * (1.f/DD);
    }
    __syncthreads();
    float m = red[0];
    float r = rsqrtf(red[1] - m*m + 1e-5f);
    float4 gv = *(const float4*)&g[tid*4];
    float4 bv = *(const float4*)&bet[tid*4];
    float4 o4;
    o4.x = (v0-m)*r*gv.x + bv.x;
    o4.y = (v1-m)*r*gv.y + bv.y;
    o4.z = (v2-m)*r*gv.z + bv.z;
    o4.w = (v3-m)*r*gv.w + bv.w;
    *(float4*)&out[t*DD + tid*4] = o4;
    __half2* hp = (__half2*)&out16[t*DD + tid*4];
    hp[0] = __floats2half2_rn(o4.x, o4.y);
    hp[1] = __floats2half2_rn(o4.z, o4.w);
}

// ---------------- moe combine + layernorm (writes fp32 + fp16) ----------------
__global__ void moe_combine_ln_kernel(const float* __restrict__ h, const float* __restrict__ eo,
                                      const int* __restrict__ slot, const float* __restrict__ wt,
                                      const float* __restrict__ g, const float* __restrict__ bet,
                                      float* __restrict__ out, __half* __restrict__ out16)
{
    long t = blockIdx.x;
    int tid = threadIdx.x;
    int s0 = slot[2*t], s1 = slot[2*t+1];
    float w0 = wt[2*t], w1 = wt[2*t+1];
    float4 xh = *(const float4*)&h[t*DD + tid*4];
    float4 e0 = *(const float4*)&eo[(long)s0*DD + tid*4];
    float4 e1 = *(const float4*)&eo[(long)s1*DD + tid*4];
    float v0 = xh.x + w0*e0.x + w1*e1.x;
    float v1 = xh.y + w0*e0.y + w1*e1.y;
    float v2 = xh.z + w0*e0.z + w1*e1.z;
    float v3 = xh.w + w0*e0.w + w1*e1.w;
    float s = v0+v1+v2+v3, ss = v0*v0+v1*v1+v2*v2+v3*v3;
    __shared__ float red[16];
    int lane = tid & 31, wid = tid >> 5;
#pragma unroll
    for (int o = 16; o; o >>= 1) {
        s  += __shfl_down_sync(0xffffffffu, s, o);
        ss += __shfl_down_sync(0xffffffffu, ss, o);
    }
    if (!lane) { red[wid] = s; red[8+wid] = ss; }
    __syncthreads();
    if (!tid) {
        float S = red[0]+red[1]+red[2]+red[3];
        float Q = red[8]+red[9]+red[10]+red[11];
        red[0] = S * (1.f/DD);
        red[1] = Q * (1.f/DD);
    }
    __syncthreads();
    float m = red[0];
    float r = rsqrtf(red[1] - m*m + 1e-5f);
    float4 gv = *(const float4*)&g[tid*4];
    float4 bv = *(const float4*)&bet[tid*4];
    float4 o4;
    o4.x = (v0-m)*r*gv.x + bv.x;
    o4.y = (v1-m)*r*gv.y + bv.y;
    o4.z = (v2-m)*r*gv.z + bv.z;
    o4.w = (v3-m)*r*gv.w + bv.w;
    *(float4*)&out[t*DD + tid*4] = o4;
    __half2* hp = (__half2*)&out16[t*DD + tid*4];
    hp[0] = __floats2half2_rn(o4.x, o4.y);
    hp[1] = __floats2half2_rn(o4.z, o4.w);
}

// ---------------- gating ----------------
__global__ void zero_counts_kernel(int* c) { if (threadIdx.x < EE) c[threadIdx.x] = 0; }

__global__ void gate_kernel(const float* __restrict__ h, const float* __restrict__ gw,
                            const float* __restrict__ gb, int* __restrict__ cnt,
                            int* __restrict__ etok, int* __restrict__ slot,
                            float* __restrict__ wt)
{
    int t = blockIdx.x * 4 + (threadIdx.x >> 5);
    int lane = threadIdx.x & 31;
    const float* hp = h + (long)t * DD;
    float acc[4] = {0.f,0.f,0.f,0.f};
#pragma unroll
    for (int it = 0; it < 4; it++) {
        int d0 = (it*32 + lane) * 4;
        float4 xv = *(const float4*)&hp[d0];
#pragma unroll
        for (int e = 0; e < 4; e++) {
            float4 wv = *(const float4*)&gw[e*DD + d0];
            acc[e] += xv.x*wv.x + xv.y*wv.y + xv.z*wv.z + xv.w*wv.w;
        }
    }
#pragma unroll
    for (int e = 0; e < 4; e++)
#pragma unroll
        for (int o = 16; o; o >>= 1)
            acc[e] += __shfl_down_sync(0xffffffffu, acc[e], o);
    if (!lane) {
        float lg[4], p[4];
        float mx = -1e30f;
#pragma unroll
        for (int e = 0; e < 4; e++) { lg[e] = acc[e] + gb[e]; mx = fmaxf(mx, lg[e]); }
        float sum = 0.f;
#pragma unroll
        for (int e = 0; e < 4; e++) { p[e] = expf(lg[e]-mx); sum += p[e]; }
#pragma unroll
        for (int e = 0; e < 4; e++) p[e] /= sum;
        int i0 = 0;
#pragma unroll
        for (int e = 1; e < 4; e++) if (p[e] > p[i0]) i0 = e;
        int i1 = (i0 == 0) ? 1 : 0;
#pragma unroll
        for (int e = 0; e < 4; e++) if (e != i0 && p[e] > p[i1]) i1 = e;
        float w0 = p[i0], w1 = p[i1];
        float inv = 1.f / (w0 + w1);
        int pos0 = atomicAdd(&cnt[i0], 1);
        etok[i0*TT + pos0] = t;
        slot[2*t]   = i0*TT + pos0;
        wt[2*t]     = w0 * inv;
        int pos1 = atomicAdd(&cnt[i1], 1);
        etok[i1*TT + pos1] = t;
        slot[2*t+1] = i1*TT + pos1;
        wt[2*t+1]   = w1 * inv;
    }
}

// ---------------- head ----------------
__global__ void head_kernel(const float* __restrict__ h, const float* __restrict__ hw,
                            const float* __restrict__ hb, float* __restrict__ out)
{
    int w = threadIdx.x >> 5, lane = threadIdx.x & 31;
    int b = w / 3, i = w % 3;
    const float* hp = h + ((long)(b*SS + SS-1)) * DD;
    float s = 0.f;
#pragma unroll
    for (int it = 0; it < 4; it++) {
        int d0 = (it*32 + lane) * 4;
        float4 a = *(const float4*)&hp[d0];
        float4 c = *(const float4*)&hw[i*DD + d0];
        s += a.x*c.x + a.y*c.y + a.z*c.z + a.w*c.w;
    }
#pragma unroll
    for (int o = 16; o; o >>= 1) s += __shfl_down_sync(0xffffffffu, s, o);
    if (!lane) out[b*3+i] = s + hb[i];
}

// ---------------- orchestration ----------------
extern "C" void kernel_launch(void* const* d_in, const int* in_sizes, int n_in,
                              void* d_out, int out_size)
{
    const float* x      = (const float*)d_in[0];
    const float* Wp     = (const float*)d_in[1];
    const float* bp     = (const float*)d_in[2];
    const float* femb   = (const float*)d_in[3];
    const float* qkv_w  = (const float*)d_in[4];
    const float* qkv_b  = (const float*)d_in[5];
    const float* ow     = (const float*)d_in[6];
    const float* ob     = (const float*)d_in[7];
    const float* g1     = (const float*)d_in[8];
    const float* beta1  = (const float*)d_in[9];
    const float* gw     = (const float*)d_in[10];
    const float* gb     = (const float*)d_in[11];
    const float* ew1    = (const float*)d_in[12];
    const float* eb1    = (const float*)d_in[13];
    const float* ew2    = (const float*)d_in[14];
    const float* eb2    = (const float*)d_in[15];
    const float* g2     = (const float*)d_in[16];
    const float* beta2  = (const float*)d_in[17];
    const float* hw     = (const float*)d_in[18];
    const float* hb     = (const float*)d_in[19];
    const int*   fidx   = (const int*)d_in[20];
    float* out = (float*)d_out;

    float *h, *tmp, *eo, *wt, *istats;
    int *cnt, *etok, *slot;
    __half *h16, *qkv16, *attn16, *hid16, *qkvw16, *ow16, *ew116, *ew216;
    cudaGetSymbolAddress((void**)&h,      g_h);
    cudaGetSymbolAddress((void**)&tmp,    g_tmp);
    cudaGetSymbolAddress((void**)&eo,     g_eo);
    cudaGetSymbolAddress((void**)&cnt,    g_cnt);
    cudaGetSymbolAddress((void**)&etok,   g_etok);
    cudaGetSymbolAddress((void**)&slot,   g_slot);
    cudaGetSymbolAddress((void**)&wt,     g_wt);
    cudaGetSymbolAddress((void**)&istats, g_istats);
    cudaGetSymbolAddress((void**)&h16,    g_h16);
    cudaGetSymbolAddress((void**)&qkv16,  g_qkv16);
    cudaGetSymbolAddress((void**)&attn16, g_attn16);
    cudaGetSymbolAddress((void**)&hid16,  g_hid16);
    cudaGetSymbolAddress((void**)&qkvw16, g_qkvw16);
    cudaGetSymbolAddress((void**)&ow16,   g_ow16);
    cudaGetSymbolAddress((void**)&ew116,  g_ew116);
    cudaGetSymbolAddress((void**)&ew216,  g_ew216);

    cudaFuncSetAttribute(attn_h_kernel, cudaFuncAttributeMaxDynamicSharedMemorySize, ATT_SMEM);
    cudaFuncSetAttribute(gemm_h<false,false,1>, cudaFuncAttributeMaxDynamicSharedMemorySize, GEMM_SMEM);
    cudaFuncSetAttribute(gemm_h<false,false,2>, cudaFuncAttributeMaxDynamicSharedMemorySize, GEMM_SMEM);
    cudaFuncSetAttribute(gemm_h<true,true,2>,   cudaFuncAttributeMaxDynamicSharedMemorySize, GEMM_SMEM);

    // weight conversion (fp32 -> fp16), once per launch
    f2h_kernel<<<(LL*3*DD*DD/4 + 255)/256, 256>>>(qkv_w, qkvw16, LL*3*DD*DD/4);
    f2h_kernel<<<(LL*DD*DD/4 + 255)/256, 256>>>(ow, ow16, LL*DD*DD/4);
    f2h_kernel<<<(LL*EE*2*DD*DD/4 + 255)/256, 256>>>(ew1, ew116, LL*EE*2*DD*DD/4);
    f2h_kernel<<<(LL*EE*2*DD*DD/4 + 255)/256, 256>>>(ew2, ew216, LL*EE*2*DD*DD/4);

    istats_kernel<<<BB*FF, 256>>>(x, istats);
    embed_kernel<<<TT, 128>>>(x, Wp, bp, femb, fidx, istats, h, h16);

    for (int l = 0; l < LL; l++) {
        // QKV projection -> half only
        gemm_h<false,false,2><<<dim3(3*DD/128, TT/128, 1), 256, GEMM_SMEM>>>(
            h16, qkvw16 + (long)l*3*DD*DD, qkv_b + l*3*DD, nullptr, qkv16,
            TT, 3*DD, DD, DD, 3*DD, 0, 0, 0, 0, nullptr, nullptr);
        // attention (fp16 tensor-core flash) -> half
        attn_h_kernel<<<dim3(SS/128, HH, BB), 256, ATT_SMEM>>>(qkv16, attn16);
        // output projection -> fp32
        gemm_h<false,false,1><<<dim3(DD/128, TT/128, 1), 256, GEMM_SMEM>>>(
            attn16, ow16 + (long)l*DD*DD, ob + l*DD, tmp, nullptr,
            TT, DD, DD, DD, DD, 0, 0, 0, 0, nullptr, nullptr);
        add_ln_kernel<<<TT, 128>>>(h, tmp, g1 + l*DD, beta1 + l*DD, h, h16);
        // MoE
        zero_counts_kernel<<<1, 32>>>(cnt);
        gate_kernel<<<TT/4, 128>>>(h, gw + l*EE*DD, gb + l*EE, cnt, etok, slot, wt);
        gemm_h<true,true,2><<<dim3(2*DD/128, TT/128, EE), 256, GEMM_SMEM>>>(
            h16, ew116 + (long)l*EE*2*DD*DD, eb1 + l*EE*2*DD, nullptr, hid16,
            TT, 2*DD, DD, DD, 2*DD,
            0, (long)2*DD*DD, 2*DD, (long)TT*2*DD, etok, cnt);
        gemm_h<false,false,1><<<dim3(DD/128, TT/128, EE), 256, GEMM_SMEM>>>(
            hid16, ew216 + (long)l*EE*2*DD*DD, eb2 + l*EE*DD, eo, nullptr,
            TT, DD, 2*DD, 2*DD, DD,
            (long)TT*2*DD, (long)2*DD*DD, DD, (long)TT*DD, nullptr, cnt);
        moe_combine_ln_kernel<<<TT, 128>>>(h, eo, slot, wt, g2 + l*DD, beta2 + l*DD, h, h16);
    }
    head_kernel<<<1, 768>>>(h, hw, hb, out);
}

// round 6
// speedup vs baseline: 5.7389x; 1.1407x over previous
#include <cuda_runtime.h>
#include <cuda_fp16.h>
#include <math.h>
#include <cstdint>

#define BB 8
#define SS 1024
#define FF 8
#define DD 512
#define HH 8
#define LL 3
#define EE 4
#define TT (BB*SS)
#define HD 64

// ---------------- scratch (device globals; no allocs allowed) ----------------
__device__ float g_h[TT*DD];
__device__ float g_tmp[TT*DD];
__device__ float g_eo[(size_t)EE*TT*DD];
__device__ int   g_cnt[EE];
__device__ int   g_etok[EE*TT];
__device__ int   g_slot[2*TT];
__device__ float g_wt[2*TT];
__device__ float g_istats[BB*FF*2];

__device__ __align__(16) __half g_h16[TT*DD];
__device__ __align__(16) __half g_qkv16[TT*3*DD];
__device__ __align__(16) __half g_attn16[TT*DD];
__device__ __align__(16) __half g_hid16[(size_t)EE*TT*2*DD];
__device__ __align__(16) __half g_qkvw16[LL*3*DD*DD];
__device__ __align__(16) __half g_ow16[LL*DD*DD];
__device__ __align__(16) __half g_ew116[(size_t)LL*EE*2*DD*DD];
__device__ __align__(16) __half g_ew216[(size_t)LL*EE*2*DD*DD];

__device__ __forceinline__ uint32_t smem_u32(const void* p) {
    uint32_t a;
    asm("{ .reg .u64 t; cvta.to.shared.u64 t, %1; cvt.u32.u64 %0, t; }" : "=r"(a) : "l"(p));
    return a;
}
__device__ __forceinline__ void mma_f16(float* d, const uint32_t* a, const uint32_t* b) {
    asm volatile(
      "mma.sync.aligned.m16n8k16.row.col.f32.f16.f16.f32 "
      "{%0,%1,%2,%3}, {%4,%5,%6,%7}, {%8,%9}, {%0,%1,%2,%3};"
      : "+f"(d[0]), "+f"(d[1]), "+f"(d[2]), "+f"(d[3])
      : "r"(a[0]), "r"(a[1]), "r"(a[2]), "r"(a[3]), "r"(b[0]), "r"(b[1]));
}
__device__ __forceinline__ void ldm_x4(uint32_t* r, uint32_t addr) {
    asm volatile("ldmatrix.sync.aligned.m8n8.x4.shared.b16 {%0,%1,%2,%3}, [%4];"
        : "=r"(r[0]), "=r"(r[1]), "=r"(r[2]), "=r"(r[3]) : "r"(addr));
}
__device__ __forceinline__ void ldm_x4_t(uint32_t* r, uint32_t addr) {
    asm volatile("ldmatrix.sync.aligned.m8n8.x4.trans.shared.b16 {%0,%1,%2,%3}, [%4];"
        : "=r"(r[0]), "=r"(r[1]), "=r"(r[2]), "=r"(r[3]) : "r"(addr));
}
#define CP_ASYNC16(dst, src, sz) \
  asm volatile("cp.async.cg.shared.global [%0], [%1], 16, %2;" :: "r"(dst), "l"(src), "r"(sz) : "memory")
#define CP_COMMIT() asm volatile("cp.async.commit_group;" ::: "memory")
#define CP_WAIT0()  asm volatile("cp.async.wait_group 0;" ::: "memory")
#define CP_WAIT1()  asm volatile("cp.async.wait_group 1;" ::: "memory")

__device__ __forceinline__ uint32_t h2u(__half2 h) { return *(uint32_t*)&h; }

// ---------------- fp32 -> fp16 convert ----------------
__global__ void f2h_kernel(const float* __restrict__ in, __half* __restrict__ out, int n4)
{
    int i = blockIdx.x * 256 + threadIdx.x;
    if (i < n4) {
        float4 v = ((const float4*)in)[i];
        __half2* op = (__half2*)(out + 4L*i);
        op[0] = __floats2half2_rn(v.x, v.y);
        op[1] = __floats2half2_rn(v.z, v.w);
    }
}

// ================= fp16 mma GEMM (ldmatrix fragments): C = A @ W^T + bias =================
// 128x128 CTA tile, BK=64, 8 warps (2x4), warp tile 64x32, cp.async 2-stage.
#define GBUF (128*144)             // 18432 B per tile buffer (rows of 64 halves + 16B pad)
#define GEMM_SMEM (4*GBUF)
template<bool GATHER, bool RELU, int WMODE>   // WMODE bit0: fp32 C, bit1: half C16
__global__ void __launch_bounds__(256) gemm_h(
    const __half* __restrict__ A, const __half* __restrict__ W,
    const float* __restrict__ bias, float* __restrict__ C, __half* __restrict__ C16,
    int M, int N, int Kd, int lda, int ldc,
    long astride, long wstride, int bstride, long cstride,
    const int* __restrict__ gidx, const int* __restrict__ cnts)
{
    extern __shared__ char smem[];
    int e = blockIdx.z;
    A    += (long)e * astride;
    W    += (long)e * wstride;
    bias += (long)e * bstride;
    if (WMODE & 1) C   += (long)e * cstride;
    if (WMODE & 2) C16 += (long)e * cstride;
    if (cnts) M = cnts[e];
    int m0 = blockIdx.y * 128;
    if (m0 >= M) return;
    int n0 = blockIdx.x * 128;

    int tid = threadIdx.x, lane = tid & 31, warp = tid >> 5;
    int g = lane >> 2, t = lane & 3;
    int wm = (warp >> 2) * 64, wn = (warp & 3) * 32;

    uint32_t sb = smem_u32(smem);
    int rbase = tid >> 3, c8 = tid & 7;

    const __half* asrc[4]; uint32_t asz[4];
    const __half* bsrc[4];
    uint32_t adst[4], bdst[4];
#pragma unroll
    for (int p = 0; p < 4; p++) {
        int row = rbase + p * 32;
        int mr = m0 + row;
        bool ok = mr < M;
        int ar = 0;
        if (ok) ar = GATHER ? gidx[(long)e * TT + mr] : mr;
        asrc[p] = A + (long)ar * lda + c8 * 8;
        asz[p] = ok ? 16u : 0u;
        bsrc[p] = W + (long)(n0 + row) * Kd + c8 * 8;
        adst[p] = sb + row * 144 + c8 * 16;
        bdst[p] = sb + 2*GBUF + row * 144 + c8 * 16;
    }

    // ldmatrix per-lane offsets
    uint32_t qrow  = (lane & 7) + ((lane >> 3) & 1) * 8;
    uint32_t khalf = (lane >> 4) * 16;
    uint32_t offA[4], offB[2];
#pragma unroll
    for (int mf = 0; mf < 4; mf++) offA[mf] = (wm + mf*16 + qrow) * 144 + khalf;
#pragma unroll
    for (int j = 0; j < 2; j++)
        offB[j] = (uint32_t)(wn + j*16 + ((lane >> 4) & 1)*8 + (lane & 7)) * 144
                + ((lane >> 3) & 1) * 16;

    float acc[4][4][4];
#pragma unroll
    for (int a_ = 0; a_ < 4; a_++)
#pragma unroll
        for (int b_ = 0; b_ < 4; b_++)
#pragma unroll
            for (int c_ = 0; c_ < 4; c_++) acc[a_][b_][c_] = 0.f;

    int nkt = Kd / 64;
#pragma unroll
    for (int p = 0; p < 4; p++) {
        CP_ASYNC16(adst[p], asrc[p], asz[p]);
        CP_ASYNC16(bdst[p], bsrc[p], 16u);
    }
    CP_COMMIT();

    for (int kt = 0; kt < nkt; kt++) {
        int buf = kt & 1;
        if (kt + 1 < nkt) {
            int koff = (kt + 1) * 64;
            uint32_t boff = ((kt + 1) & 1) * GBUF;
#pragma unroll
            for (int p = 0; p < 4; p++) {
                CP_ASYNC16(adst[p] + boff, asrc[p] + koff, asz[p]);
                CP_ASYNC16(bdst[p] + boff, bsrc[p] + koff, 16u);
            }
            CP_COMMIT();
            CP_WAIT1();
        } else {
            CP_WAIT0();
        }
        __syncthreads();

        uint32_t ab = sb + buf * GBUF;
        uint32_t bb = sb + 2*GBUF + buf * GBUF;
#pragma unroll
        for (int ks = 0; ks < 4; ks++) {
            uint32_t af[4][4], bf[2][4];
#pragma unroll
            for (int mf = 0; mf < 4; mf++) ldm_x4(af[mf], ab + offA[mf] + ks*32);
#pragma unroll
            for (int j = 0; j < 2; j++) ldm_x4(bf[j], bb + offB[j] + ks*32);
#pragma unroll
            for (int mf = 0; mf < 4; mf++)
#pragma unroll
                for (int nf = 0; nf < 4; nf++)
                    mma_f16(acc[mf][nf], af[mf], &bf[nf >> 1][(nf & 1) * 2]);
        }
        __syncthreads();
    }

#pragma unroll
    for (int mf = 0; mf < 4; mf++) {
        int rA = m0 + wm + mf*16 + g;
        int rB = rA + 8;
#pragma unroll
        for (int nf = 0; nf < 4; nf++) {
            int col = n0 + wn + nf*8 + t*2;
            float2 bb2 = *(const float2*)&bias[col];
            float2 v0, v1;
            v0.x = acc[mf][nf][0] + bb2.x; v0.y = acc[mf][nf][1] + bb2.y;
            v1.x = acc[mf][nf][2] + bb2.x; v1.y = acc[mf][nf][3] + bb2.y;
            if (RELU) {
                v0.x = fmaxf(v0.x, 0.f); v0.y = fmaxf(v0.y, 0.f);
                v1.x = fmaxf(v1.x, 0.f); v1.y = fmaxf(v1.y, 0.f);
            }
            if (rA < M) {
                if (WMODE & 1) *(float2*)&C[(long)rA*ldc + col] = v0;
                if (WMODE & 2) *(__half2*)&C16[(long)rA*ldc + col] = __floats2half2_rn(v0.x, v0.y);
            }
            if (rB < M) {
                if (WMODE & 1) *(float2*)&C[(long)rB*ldc + col] = v1;
                if (WMODE & 2) *(__half2*)&C16[(long)rB*ldc + col] = __floats2half2_rn(v1.x, v1.y);
            }
        }
    }
}

// ================= attention: flash fp16 mma + ldmatrix + cp.async prefetch =================
// CTA: 128 queries of one (b,h); 16 chunks of 64 keys; 8 warps x 16 rows.
// smem bytes: Q[0,18432) K0[18432) K1[27648) V0[36864) V1[46080) P[55296,73728)
#define AQB 0
#define AKB 18432
#define AVB 36864
#define APB 55296
#define AKVB 9216
#define ATT_SMEM 73728
__global__ void __launch_bounds__(256) attn_h_kernel(const __half* __restrict__ qkv,
                                                     __half* __restrict__ out)
{
    extern __shared__ char smc[];
    uint32_t sb = smem_u32(smc);
    uint32_t* Pw = (uint32_t*)(smc + APB);

    int q0 = blockIdx.x * 128;
    int hh = blockIdx.y;
    int b  = blockIdx.z;
    int tid = threadIdx.x, lane = tid & 31, warp = tid >> 5;
    int g = lane >> 2, t = lane & 3;
    const __half* base  = qkv + (long)b * SS * (3*DD) + hh * HD;
    const __half* kbase = base + DD;
    const __half* vbase = base + 2*DD;

    // staging map: each thread stages 2 K-rows and 2 V-rows (16B each)
    int srow0 = tid >> 3, sc8 = tid & 7;
    int srow1 = srow0 + 32;
    uint32_t kd0 = sb + AKB + srow0*144 + sc8*16;
    uint32_t kd1 = sb + AKB + srow1*144 + sc8*16;
    uint32_t vd0 = sb + AVB + srow0*144 + sc8*16;
    uint32_t vd1 = sb + AVB + srow1*144 + sc8*16;

    // prefetch chunk 0 into buf 0
    {
        const __half* k0 = kbase + (long)srow0*(3*DD) + sc8*8;
        const __half* k1 = kbase + (long)srow1*(3*DD) + sc8*8;
        const __half* v0 = vbase + (long)srow0*(3*DD) + sc8*8;
        const __half* v1 = vbase + (long)srow1*(3*DD) + sc8*8;
        CP_ASYNC16(kd0, k0, 16u); CP_ASYNC16(kd1, k1, 16u);
        CP_ASYNC16(vd0, v0, 16u); CP_ASYNC16(vd1, v1, 16u);
    }
    CP_COMMIT();

    // stage Q direct
#pragma unroll
    for (int p = 0; p < 4; p++) {
        int idx = tid + p*256;
        int row = idx >> 3, c8 = idx & 7;
        *(uint4*)(smc + AQB + row*144 + c8*16) =
            *(const uint4*)(base + (long)(q0 + row) * (3*DD) + c8*8);
    }

    // ldmatrix per-lane offsets
    uint32_t qrow  = (lane & 7) + ((lane >> 3) & 1) * 8;
    uint32_t khalf = (lane >> 4) * 16;
    uint32_t offQ = sb + AQB + (warp*16 + qrow)*144 + khalf;
    uint32_t offP = sb + APB + (warp*16 + qrow)*144 + khalf;
    uint32_t offK[4], offV[4];
#pragma unroll
    for (int j = 0; j < 4; j++)
        offK[j] = (uint32_t)(j*16 + ((lane >> 4) & 1)*8 + (lane & 7)) * 144
                + ((lane >> 3) & 1) * 16;
    {
        uint32_t kr = ((lane >> 3) & 1)*8 + (lane & 7);
#pragma unroll
        for (int j = 0; j < 4; j++)
            offV[j] = kr*144 + j*32 + ((lane >> 4) & 1)*16;
    }

    int r0 = warp*16 + g;
    float mm0 = -1e30f, mm1 = -1e30f, ll0 = 0.f, ll1 = 0.f;
    float o[8][4];
#pragma unroll
    for (int nf = 0; nf < 8; nf++)
#pragma unroll
        for (int c = 0; c < 4; c++) o[nf][c] = 0.f;

    for (int jc = 0; jc < SS/64; jc++) {
        int buf = jc & 1;
        CP_WAIT0();
        __syncthreads();
        if (jc + 1 < SS/64) {
            uint32_t nb = (uint32_t)(buf ^ 1) * AKVB;
            long goff = (long)(jc + 1) * 64 * (3*DD);
            const __half* k0 = kbase + goff + (long)srow0*(3*DD) + sc8*8;
            const __half* k1 = kbase + goff + (long)srow1*(3*DD) + sc8*8;
            const __half* v0 = vbase + goff + (long)srow0*(3*DD) + sc8*8;
            const __half* v1 = vbase + goff + (long)srow1*(3*DD) + sc8*8;
            CP_ASYNC16(kd0 + nb, k0, 16u); CP_ASYNC16(kd1 + nb, k1, 16u);
            CP_ASYNC16(vd0 + nb, v0, 16u); CP_ASYNC16(vd1 + nb, v1, 16u);
            CP_COMMIT();
        }
        uint32_t kb = sb + AKB + buf * AKVB;
        uint32_t vb = sb + AVB + buf * AKVB;

        // S = Q K^T
        float s[8][4];
#pragma unroll
        for (int nf = 0; nf < 8; nf++)
#pragma unroll
            for (int c = 0; c < 4; c++) s[nf][c] = 0.f;
#pragma unroll
        for (int ks = 0; ks < 4; ks++) {
            uint32_t a[4];
            ldm_x4(a, offQ + ks*32);
#pragma unroll
            for (int j = 0; j < 4; j++) {
                uint32_t bf[4];
                ldm_x4(bf, kb + offK[j] + ks*32);
                mma_f16(s[2*j],   a, &bf[0]);
                mma_f16(s[2*j+1], a, &bf[2]);
            }
        }
        // scale + online softmax (quad-local)
        float mx0 = mm0, mx1 = mm1;
#pragma unroll
        for (int nf = 0; nf < 8; nf++) {
            s[nf][0] *= 0.125f; s[nf][1] *= 0.125f;
            s[nf][2] *= 0.125f; s[nf][3] *= 0.125f;
            mx0 = fmaxf(mx0, fmaxf(s[nf][0], s[nf][1]));
            mx1 = fmaxf(mx1, fmaxf(s[nf][2], s[nf][3]));
        }
        mx0 = fmaxf(mx0, __shfl_xor_sync(0xffffffffu, mx0, 1));
        mx0 = fmaxf(mx0, __shfl_xor_sync(0xffffffffu, mx0, 2));
        mx1 = fmaxf(mx1, __shfl_xor_sync(0xffffffffu, mx1, 1));
        mx1 = fmaxf(mx1, __shfl_xor_sync(0xffffffffu, mx1, 2));
        float al0 = __expf(mm0 - mx0), al1 = __expf(mm1 - mx1);
        float sum0 = 0.f, sum1 = 0.f;
#pragma unroll
        for (int nf = 0; nf < 8; nf++) {
            s[nf][0] = __expf(s[nf][0] - mx0);
            s[nf][1] = __expf(s[nf][1] - mx0);
            s[nf][2] = __expf(s[nf][2] - mx1);
            s[nf][3] = __expf(s[nf][3] - mx1);
            sum0 += s[nf][0] + s[nf][1];
            sum1 += s[nf][2] + s[nf][3];
        }
        sum0 += __shfl_xor_sync(0xffffffffu, sum0, 1);
        sum0 += __shfl_xor_sync(0xffffffffu, sum0, 2);
        sum1 += __shfl_xor_sync(0xffffffffu, sum1, 1);
        sum1 += __shfl_xor_sync(0xffffffffu, sum1, 2);
        ll0 = ll0*al0 + sum0; ll1 = ll1*al1 + sum1;
        mm0 = mx0; mm1 = mx1;
#pragma unroll
        for (int nf = 0; nf < 8; nf++) {
            o[nf][0] *= al0; o[nf][1] *= al0;
            o[nf][2] *= al1; o[nf][3] *= al1;
        }
        // write P as half (warp-local rows)
#pragma unroll
        for (int nf = 0; nf < 8; nf++) {
            Pw[(warp*16 + g)*36 + nf*4 + t]     = h2u(__floats2half2_rn(s[nf][0], s[nf][1]));
            Pw[(warp*16 + g + 8)*36 + nf*4 + t] = h2u(__floats2half2_rn(s[nf][2], s[nf][3]));
        }
        __syncwarp();
        // O += P V
#pragma unroll
        for (int ks = 0; ks < 4; ks++) {
            uint32_t a[4];
            ldm_x4(a, offP + ks*32);
#pragma unroll
            for (int j = 0; j < 4; j++) {
                uint32_t bf[4];
                ldm_x4_t(bf, vb + offV[j] + ks*2304);
                mma_f16(o[2*j],   a, &bf[0]);
                mma_f16(o[2*j+1], a, &bf[2]);
            }
        }
    }

    float inv0 = 1.f / ll0, inv1 = 1.f / ll1;
    long tok0 = (long)(b*SS + q0 + r0) * DD + hh*HD;
    long tok1 = tok0 + 8L*DD;
#pragma unroll
    for (int nf = 0; nf < 8; nf++) {
        int col = nf*8 + 2*t;
        *(__half2*)&out[tok0 + col] = __floats2half2_rn(o[nf][0]*inv0, o[nf][1]*inv0);
        *(__half2*)&out[tok1 + col] = __floats2half2_rn(o[nf][2]*inv1, o[nf][3]*inv1);
    }
}

// ---------------- instance-norm stats ----------------
__global__ void istats_kernel(const float* __restrict__ x, float* __restrict__ stats)
{
    int bf = blockIdx.x;
    int b = bf >> 3, f = bf & 7;
    int tid = threadIdx.x;
    float s = 0.f, ss = 0.f;
    for (int i = tid; i < SS; i += 256) {
        float v = x[((long)b*SS + i)*FF + f];
        s += v; ss += v*v;
    }
    __shared__ float red[16];
    int lane = tid & 31, wid = tid >> 5;
#pragma unroll
    for (int o = 16; o; o >>= 1) {
        s  += __shfl_down_sync(0xffffffffu, s, o);
        ss += __shfl_down_sync(0xffffffffu, ss, o);
    }
    if (!lane) { red[wid] = s; red[8+wid] = ss; }
    __syncthreads();
    if (!tid) {
        float S = 0.f, Q = 0.f;
        for (int w = 0; w < 8; w++) { S += red[w]; Q += red[8+w]; }
        float m = S / SS;
        float var = (Q - SS*m*m) / (SS - 1);
        stats[bf*2]   = m;
        stats[bf*2+1] = 1.f / (sqrtf(var) + 1e-5f);
    }
}

// ---------------- embed (writes fp32 + fp16) ----------------
__global__ void embed_kernel(const float* __restrict__ x, const float* __restrict__ Wp,
                             const float* __restrict__ bp, const float* __restrict__ femb,
                             const int* __restrict__ fidx, const float* __restrict__ stats,
                             float* __restrict__ h, __half* __restrict__ h16)
{
    int token = blockIdx.x;
    int b = token >> 10, s = token & 1023;
    int tid = threadIdx.x;
    __shared__ float xn[8];
    if (tid < 8) {
        float m = stats[(b*8+tid)*2], inv = stats[(b*8+tid)*2+1];
        xn[tid] = (x[(long)token*FF + tid] - m) * inv;
    }
    __syncthreads();
    int fi = *fidx;
    int d0 = tid * 4;
    float4 acc = *(const float4*)&bp[d0];
    float* ap = &acc.x;
#pragma unroll
    for (int f = 0; f < 8; f++) {
        float xv = xn[f];
        ap[0] += xv * Wp[(d0+0)*8+f];
        ap[1] += xv * Wp[(d0+1)*8+f];
        ap[2] += xv * Wp[(d0+2)*8+f];
        ap[3] += xv * Wp[(d0+3)*8+f];
    }
    const float c = -0.0179889460f;
#pragma unroll
    for (int j = 0; j < 4; j++) {
        int d = d0 + j;
        int i = d >> 1;
        float ang = (float)s * expf((float)(2*i) * c);
        float pe = (d & 1) ? cosf(ang) : sinf(ang);
        ap[j] += femb[fi*DD + d] + pe;
    }
    *(float4*)&h[(long)token*DD + d0] = acc;
    __half2* hp = (__half2*)&h16[(long)token*DD + d0];
    hp[0] = __floats2half2_rn(acc.x, acc.y);
    hp[1] = __floats2half2_rn(acc.z, acc.w);
}

// ---------------- add + layernorm (writes fp32 + fp16) ----------------
__global__ void add_ln_kernel(const float* __restrict__ base, const float* __restrict__ add,
                              const float* __restrict__ g, const float* __restrict__ bet,
                              float* __restrict__ out, __half* __restrict__ out16)
{
    long t = blockIdx.x;
    int tid = threadIdx.x;
    float4 xb = *(const float4*)&base[t*DD + tid*4];
    float4 xa = *(const float4*)&add[t*DD + tid*4];
    float v0=xb.x+xa.x, v1=xb.y+xa.y, v2=xb.z+xa.z, v3=xb.w+xa.w;
    float s = v0+v1+v2+v3, ss = v0*v0+v1*v1+v2*v2+v3*v3;
    __shared__ float red[16];
    int lane = tid & 31, wid = tid >> 5;
#pragma unroll
    for (int o = 16; o; o >>= 1) {
        s  += __shfl_down_sync(0xffffffffu, s, o);
        ss += __shfl_down_sync(0xffffffffu, ss, o);
    }
    if (!lane) { red[wid] = s; red[8+wid] = ss; }
    __syncthreads();
    if (!tid) {
        float S = red[0]+red[1]+red[2]+red[3];
        float Q = red[8]+red[9]+red[10]+red[11];
        red[0] = S * (1.f/DD);
        red[1] = Q * (1.f/DD);
    }
    __syncthreads();
    float m = red[0];
    float r = rsqrtf(red[1] - m*m + 1e-5f);
    float4 gv = *(const float4*)&g[tid*4];
    float4 bv = *(const float4*)&bet[tid*4];
    float4 o4;
    o4.x = (v0-m)*r*gv.x + bv.x;
    o4.y = (v1-m)*r*gv.y + bv.y;
    o4.z = (v2-m)*r*gv.z + bv.z;
    o4.w = (v3-m)*r*gv.w + bv.w;
    *(float4*)&out[t*DD + tid*4] = o4;
    __half2* hp = (__half2*)&out16[t*DD + tid*4];
    hp[0] = __floats2half2_rn(o4.x, o4.y);
    hp[1] = __floats2half2_rn(o4.z, o4.w);
}

// ---------------- moe combine + layernorm (writes fp32 + fp16) ----------------
__global__ void moe_combine_ln_kernel(const float* __restrict__ h, const float* __restrict__ eo,
                                      const int* __restrict__ slot, const float* __restrict__ wt,
                                      const float* __restrict__ g, const float* __restrict__ bet,
                                      float* __restrict__ out, __half* __restrict__ out16)
{
    long t = blockIdx.x;
    int tid = threadIdx.x;
    int s0 = slot[2*t], s1 = slot[2*t+1];
    float w0 = wt[2*t], w1 = wt[2*t+1];
    float4 xh = *(const float4*)&h[t*DD + tid*4];
    float4 e0 = *(const float4*)&eo[(long)s0*DD + tid*4];
    float4 e1 = *(const float4*)&eo[(long)s1*DD + tid*4];
    float v0 = xh.x + w0*e0.x + w1*e1.x;
    float v1 = xh.y + w0*e0.y + w1*e1.y;
    float v2 = xh.z + w0*e0.z + w1*e1.z;
    float v3 = xh.w + w0*e0.w + w1*e1.w;
    float s = v0+v1+v2+v3, ss = v0*v0+v1*v1+v2*v2+v3*v3;
    __shared__ float red[16];
    int lane = tid & 31, wid = tid >> 5;
#pragma unroll
    for (int o = 16; o; o >>= 1) {
        s  += __shfl_down_sync(0xffffffffu, s, o);
        ss += __shfl_down_sync(0xffffffffu, ss, o);
    }
    if (!lane) { red[wid] = s; red[8+wid] = ss; }
    __syncthreads();
    if (!tid) {
        float S = red[0]+red[1]+red[2]+red[3];
        float Q = red[8]+red[9]+red[10]+red[11];
        red[0] = S * (1.f/DD);
        red[1] = Q * (1.f/DD);
    }
    __syncthreads();
    float m = red[0];
    float r = rsqrtf(red[1] - m*m + 1e-5f);
    float4 gv = *(const float4*)&g[tid*4];
    float4 bv = *(const float4*)&bet[tid*4];
    float4 o4;
    o4.x = (v0-m)*r*gv.x + bv.x;
    o4.y = (v1-m)*r*gv.y + bv.y;
    o4.z = (v2-m)*r*gv.z + bv.z;
    o4.w = (v3-m)*r*gv.w + bv.w;
    *(float4*)&out[t*DD + tid*4] = o4;
    __half2* hp = (__half2*)&out16[t*DD + tid*4];
    hp[0] = __floats2half2_rn(o4.x, o4.y);
    hp[1] = __floats2half2_rn(o4.z, o4.w);
}

// ---------------- gating ----------------
__global__ void zero_counts_kernel(int* c) { if (threadIdx.x < EE) c[threadIdx.x] = 0; }

__global__ void gate_kernel(const float* __restrict__ h, const float* __restrict__ gw,
                            const float* __restrict__ gb, int* __restrict__ cnt,
                            int* __restrict__ etok, int* __restrict__ slot,
                            float* __restrict__ wt)
{
    int t = blockIdx.x * 4 + (threadIdx.x >> 5);
    int lane = threadIdx.x & 31;
    const float* hp = h + (long)t * DD;
    float acc[4] = {0.f,0.f,0.f,0.f};
#pragma unroll
    for (int it = 0; it < 4; it++) {
        int d0 = (it*32 + lane) * 4;
        float4 xv = *(const float4*)&hp[d0];
#pragma unroll
        for (int e = 0; e < 4; e++) {
            float4 wv = *(const float4*)&gw[e*DD + d0];
            acc[e] += xv.x*wv.x + xv.y*wv.y + xv.z*wv.z + xv.w*wv.w;
        }
    }
#pragma unroll
    for (int e = 0; e < 4; e++)
#pragma unroll
        for (int o = 16; o; o >>= 1)
            acc[e] += __shfl_down_sync(0xffffffffu, acc[e], o);
    if (!lane) {
        float lg[4], p[4];
        float mx = -1e30f;
#pragma unroll
        for (int e = 0; e < 4; e++) { lg[e] = acc[e] + gb[e]; mx = fmaxf(mx, lg[e]); }
        float sum = 0.f;
#pragma unroll
        for (int e = 0; e < 4; e++) { p[e] = expf(lg[e]-mx); sum += p[e]; }
#pragma unroll
        for (int e = 0; e < 4; e++) p[e] /= sum;
        int i0 = 0;
#pragma unroll
        for (int e = 1; e < 4; e++) if (p[e] > p[i0]) i0 = e;
        int i1 = (i0 == 0) ? 1 : 0;
#pragma unroll
        for (int e = 0; e < 4; e++) if (e != i0 && p[e] > p[i1]) i1 = e;
        float w0 = p[i0], w1 = p[i1];
        float inv = 1.f / (w0 + w1);
        int pos0 = atomicAdd(&cnt[i0], 1);
        etok[i0*TT + pos0] = t;
        slot[2*t]   = i0*TT + pos0;
        wt[2*t]     = w0 * inv;
        int pos1 = atomicAdd(&cnt[i1], 1);
        etok[i1*TT + pos1] = t;
        slot[2*t+1] = i1*TT + pos1;
        wt[2*t+1]   = w1 * inv;
    }
}

// ---------------- head ----------------
__global__ void head_kernel(const float* __restrict__ h, const float* __restrict__ hw,
                            const float* __restrict__ hb, float* __restrict__ out)
{
    int w = threadIdx.x >> 5, lane = threadIdx.x & 31;
    int b = w / 3, i = w % 3;
    const float* hp = h + ((long)(b*SS + SS-1)) * DD;
    float s = 0.f;
#pragma unroll
    for (int it = 0; it < 4; it++) {
        int d0 = (it*32 + lane) * 4;
        float4 a = *(const float4*)&hp[d0];
        float4 c = *(const float4*)&hw[i*DD + d0];
        s += a.x*c.x + a.y*c.y + a.z*c.z + a.w*c.w;
    }
#pragma unroll
    for (int o = 16; o; o >>= 1) s += __shfl_down_sync(0xffffffffu, s, o);
    if (!lane) out[b*3+i] = s + hb[i];
}

// ---------------- orchestration ----------------
extern "C" void kernel_launch(void* const* d_in, const int* in_sizes, int n_in,
                              void* d_out, int out_size)
{
    const float* x      = (const float*)d_in[0];
    const float* Wp     = (const float*)d_in[1];
    const float* bp     = (const float*)d_in[2];
    const float* femb   = (const float*)d_in[3];
    const float* qkv_w  = (const float*)d_in[4];
    const float* qkv_b  = (const float*)d_in[5];
    const float* ow     = (const float*)d_in[6];
    const float* ob     = (const float*)d_in[7];
    const float* g1     = (const float*)d_in[8];
    const float* beta1  = (const float*)d_in[9];
    const float* gw     = (const float*)d_in[10];
    const float* gb     = (const float*)d_in[11];
    const float* ew1    = (const float*)d_in[12];
    const float* eb1    = (const float*)d_in[13];
    const float* ew2    = (const float*)d_in[14];
    const float* eb2    = (const float*)d_in[15];
    const float* g2     = (const float*)d_in[16];
    const float* beta2  = (const float*)d_in[17];
    const float* hw     = (const float*)d_in[18];
    const float* hb     = (const float*)d_in[19];
    const int*   fidx   = (const int*)d_in[20];
    float* out = (float*)d_out;

    float *h, *tmp, *eo, *wt, *istats;
    int *cnt, *etok, *slot;
    __half *h16, *qkv16, *attn16, *hid16, *qkvw16, *ow16, *ew116, *ew216;
    cudaGetSymbolAddress((void**)&h,      g_h);
    cudaGetSymbolAddress((void**)&tmp,    g_tmp);
    cudaGetSymbolAddress((void**)&eo,     g_eo);
    cudaGetSymbolAddress((void**)&cnt,    g_cnt);
    cudaGetSymbolAddress((void**)&etok,   g_etok);
    cudaGetSymbolAddress((void**)&slot,   g_slot);
    cudaGetSymbolAddress((void**)&wt,     g_wt);
    cudaGetSymbolAddress((void**)&istats, g_istats);
    cudaGetSymbolAddress((void**)&h16,    g_h16);
    cudaGetSymbolAddress((void**)&qkv16,  g_qkv16);
    cudaGetSymbolAddress((void**)&attn16, g_attn16);
    cudaGetSymbolAddress((void**)&hid16,  g_hid16);
    cudaGetSymbolAddress((void**)&qkvw16, g_qkvw16);
    cudaGetSymbolAddress((void**)&ow16,   g_ow16);
    cudaGetSymbolAddress((void**)&ew116,  g_ew116);
    cudaGetSymbolAddress((void**)&ew216,  g_ew216);

    cudaFuncSetAttribute(attn_h_kernel, cudaFuncAttributeMaxDynamicSharedMemorySize, ATT_SMEM);
    cudaFuncSetAttribute(gemm_h<false,false,1>, cudaFuncAttributeMaxDynamicSharedMemorySize, GEMM_SMEM);
    cudaFuncSetAttribute(gemm_h<false,false,2>, cudaFuncAttributeMaxDynamicSharedMemorySize, GEMM_SMEM);
    cudaFuncSetAttribute(gemm_h<true,true,2>,   cudaFuncAttributeMaxDynamicSharedMemorySize, GEMM_SMEM);

    // weight conversion (fp32 -> fp16), once per launch
    f2h_kernel<<<(LL*3*DD*DD/4 + 255)/256, 256>>>(qkv_w, qkvw16, LL*3*DD*DD/4);
    f2h_kernel<<<(LL*DD*DD/4 + 255)/256, 256>>>(ow, ow16, LL*DD*DD/4);
    f2h_kernel<<<(LL*EE*2*DD*DD/4 + 255)/256, 256>>>(ew1, ew116, LL*EE*2*DD*DD/4);
    f2h_kernel<<<(LL*EE*2*DD*DD/4 + 255)/256, 256>>>(ew2, ew216, LL*EE*2*DD*DD/4);

    istats_kernel<<<BB*FF, 256>>>(x, istats);
    embed_kernel<<<TT, 128>>>(x, Wp, bp, femb, fidx, istats, h, h16);

    for (int l = 0; l < LL; l++) {
        // QKV projection -> half only
        gemm_h<false,false,2><<<dim3(3*DD/128, TT/128, 1), 256, GEMM_SMEM>>>(
            h16, qkvw16 + (long)l*3*DD*DD, qkv_b + l*3*DD, nullptr, qkv16,
            TT, 3*DD, DD, DD, 3*DD, 0, 0, 0, 0, nullptr, nullptr);
        // attention (fp16 flash, ldmatrix + prefetch) -> half
        attn_h_kernel<<<dim3(SS/128, HH, BB), 256, ATT_SMEM>>>(qkv16, attn16);
        // output projection -> fp32
        gemm_h<false,false,1><<<dim3(DD/128, TT/128, 1), 256, GEMM_SMEM>>>(
            attn16, ow16 + (long)l*DD*DD, ob + l*DD, tmp, nullptr,
            TT, DD, DD, DD, DD, 0, 0, 0, 0, nullptr, nullptr);
        add_ln_kernel<<<TT, 128>>>(h, tmp, g1 + l*DD, beta1 + l*DD, h, h16);
        // MoE
        zero_counts_kernel<<<1, 32>>>(cnt);
        gate_kernel<<<TT/4, 128>>>(h, gw + l*EE*DD, gb + l*EE, cnt, etok, slot, wt);
        gemm_h<true,true,2><<<dim3(2*DD/128, TT/128, EE), 256, GEMM_SMEM>>>(
            h16, ew116 + (long)l*EE*2*DD*DD, eb1 + l*EE*2*DD, nullptr, hid16,
            TT, 2*DD, DD, DD, 2*DD,
            0, (long)2*DD*DD, 2*DD, (long)TT*2*DD, etok, cnt);
        gemm_h<false,false,1><<<dim3(DD/128, TT/128, EE), 256, GEMM_SMEM>>>(
            hid16, ew216 + (long)l*EE*2*DD*DD, eb2 + l*EE*DD, eo, nullptr,
            TT, DD, 2*DD, 2*DD, DD,
            (long)TT*2*DD, (long)2*DD*DD, DD, (long)TT*DD, nullptr, cnt);
        moe_combine_ln_kernel<<<TT, 128>>>(h, eo, slot, wt, g2 + l*DD, beta2 + l*DD, h, h16);
    }
    head_kernel<<<1, 768>>>(h, hw, hb, out);
}

// round 7
// speedup vs baseline: 5.9127x; 1.0303x over previous
#include <cuda_runtime.h>
#include <cuda_fp16.h>
#include <math.h>
#include <cstdint>

#define BB 8
#define SS 1024
#define FF 8
#define DD 512
#define HH 8
#define LL 3
#define EE 4
#define TT (BB*SS)
#define HD 64

// ---------------- scratch (device globals; no allocs allowed) ----------------
__device__ float g_h[TT*DD];
__device__ float g_tmp[TT*DD];
__device__ int   g_cnt[LL*EE];
__device__ int   g_etok[EE*TT];
__device__ int   g_slot[2*TT];
__device__ float g_wt[2*TT];
__device__ float g_istats[BB*FF*2];

__device__ __align__(16) __half g_h16[TT*DD];
__device__ __align__(16) __half g_qkv16[TT*3*DD];
__device__ __align__(16) __half g_attn16[TT*DD];
__device__ __align__(16) __half g_hid16[(size_t)EE*TT*2*DD];
__device__ __align__(16) __half g_eo16[(size_t)EE*TT*DD];
__device__ __align__(16) __half g_qkvw16[LL*3*DD*DD];
__device__ __align__(16) __half g_ow16[LL*DD*DD];
__device__ __align__(16) __half g_ew116[(size_t)LL*EE*2*DD*DD];
__device__ __align__(16) __half g_ew216[(size_t)LL*EE*2*DD*DD];

__device__ __forceinline__ uint32_t smem_u32(const void* p) {
    uint32_t a;
    asm("{ .reg .u64 t; cvta.to.shared.u64 t, %1; cvt.u32.u64 %0, t; }" : "=r"(a) : "l"(p));
    return a;
}
__device__ __forceinline__ void mma_f16(float* d, const uint32_t* a, const uint32_t* b) {
    asm volatile(
      "mma.sync.aligned.m16n8k16.row.col.f32.f16.f16.f32 "
      "{%0,%1,%2,%3}, {%4,%5,%6,%7}, {%8,%9}, {%0,%1,%2,%3};"
      : "+f"(d[0]), "+f"(d[1]), "+f"(d[2]), "+f"(d[3])
      : "r"(a[0]), "r"(a[1]), "r"(a[2]), "r"(a[3]), "r"(b[0]), "r"(b[1]));
}
__device__ __forceinline__ void ldm_x4(uint32_t* r, uint32_t addr) {
    asm volatile("ldmatrix.sync.aligned.m8n8.x4.shared.b16 {%0,%1,%2,%3}, [%4];"
        : "=r"(r[0]), "=r"(r[1]), "=r"(r[2]), "=r"(r[3]) : "r"(addr));
}
__device__ __forceinline__ void ldm_x4_t(uint32_t* r, uint32_t addr) {
    asm volatile("ldmatrix.sync.aligned.m8n8.x4.trans.shared.b16 {%0,%1,%2,%3}, [%4];"
        : "=r"(r[0]), "=r"(r[1]), "=r"(r[2]), "=r"(r[3]) : "r"(addr));
}
#define CP_ASYNC16(dst, src, sz) \
  asm volatile("cp.async.cg.shared.global [%0], [%1], 16, %2;" :: "r"(dst), "l"(src), "r"(sz) : "memory")
#define CP_COMMIT() asm volatile("cp.async.commit_group;" ::: "memory")
#define CP_WAIT0()  asm volatile("cp.async.wait_group 0;" ::: "memory")
#define CP_WAIT1()  asm volatile("cp.async.wait_group 1;" ::: "memory")

__device__ __forceinline__ uint32_t h2u(__half2 h) { return *(uint32_t*)&h; }

// ---------------- merged fp32 -> fp16 weight convert (single launch) ----------------
#define N1F4 (LL*3*DD*DD/4)
#define N2F4 (LL*DD*DD/4)
#define N3F4 (LL*EE*2*DD*DD/4)
#define NTOTF4 (N1F4 + N2F4 + 2*N3F4)
__global__ void f2h_all_kernel(const float* __restrict__ s1, __half* __restrict__ d1,
                               const float* __restrict__ s2, __half* __restrict__ d2,
                               const float* __restrict__ s3, __half* __restrict__ d3,
                               const float* __restrict__ s4, __half* __restrict__ d4)
{
    long i = (long)blockIdx.x * 256 + threadIdx.x;
    if (i >= NTOTF4) return;
    const float* src; __half* dst; long j;
    if (i < N1F4)                    { src = s1; dst = d1; j = i; }
    else if (i < N1F4 + N2F4)        { src = s2; dst = d2; j = i - N1F4; }
    else if (i < N1F4 + N2F4 + N3F4) { src = s3; dst = d3; j = i - N1F4 - N2F4; }
    else                             { src = s4; dst = d4; j = i - N1F4 - N2F4 - N3F4; }
    float4 v = ((const float4*)src)[j];
    __half2* op = (__half2*)(dst + 4*j);
    op[0] = __floats2half2_rn(v.x, v.y);
    op[1] = __floats2half2_rn(v.z, v.w);
}

// ================= fp16 mma GEMM (ldmatrix fragments): C = A @ W^T + bias =================
#define GBUF (128*144)
#define GEMM_SMEM (4*GBUF)
template<bool GATHER, bool RELU, int WMODE>   // WMODE bit0: fp32 C, bit1: half C16
__global__ void __launch_bounds__(256) gemm_h(
    const __half* __restrict__ A, const __half* __restrict__ W,
    const float* __restrict__ bias, float* __restrict__ C, __half* __restrict__ C16,
    int M, int N, int Kd, int lda, int ldc,
    long astride, long wstride, int bstride, long cstride,
    const int* __restrict__ gidx, const int* __restrict__ cnts)
{
    extern __shared__ char smem[];
    int e = blockIdx.z;
    A    += (long)e * astride;
    W    += (long)e * wstride;
    bias += (long)e * bstride;
    if (WMODE & 1) C   += (long)e * cstride;
    if (WMODE & 2) C16 += (long)e * cstride;
    if (cnts) M = cnts[e];
    int m0 = blockIdx.y * 128;
    if (m0 >= M) return;
    int n0 = blockIdx.x * 128;

    int tid = threadIdx.x, lane = tid & 31, warp = tid >> 5;
    int g = lane >> 2, t = lane & 3;
    int wm = (warp >> 2) * 64, wn = (warp & 3) * 32;

    uint32_t sb = smem_u32(smem);
    int rbase = tid >> 3, c8 = tid & 7;

    const __half* asrc[4]; uint32_t asz[4];
    const __half* bsrc[4];
    uint32_t adst[4], bdst[4];
#pragma unroll
    for (int p = 0; p < 4; p++) {
        int row = rbase + p * 32;
        int mr = m0 + row;
        bool ok = mr < M;
        int ar = 0;
        if (ok) ar = GATHER ? gidx[(long)e * TT + mr] : mr;
        asrc[p] = A + (long)ar * lda + c8 * 8;
        asz[p] = ok ? 16u : 0u;
        bsrc[p] = W + (long)(n0 + row) * Kd + c8 * 8;
        adst[p] = sb + row * 144 + c8 * 16;
        bdst[p] = sb + 2*GBUF + row * 144 + c8 * 16;
    }

    uint32_t qrow  = (lane & 7) + ((lane >> 3) & 1) * 8;
    uint32_t khalf = (lane >> 4) * 16;
    uint32_t offA[4], offB[2];
#pragma unroll
    for (int mf = 0; mf < 4; mf++) offA[mf] = (wm + mf*16 + qrow) * 144 + khalf;
#pragma unroll
    for (int j = 0; j < 2; j++)
        offB[j] = (uint32_t)(wn + j*16 + ((lane >> 4) & 1)*8 + (lane & 7)) * 144
                + ((lane >> 3) & 1) * 16;

    float acc[4][4][4];
#pragma unroll
    for (int a_ = 0; a_ < 4; a_++)
#pragma unroll
        for (int b_ = 0; b_ < 4; b_++)
#pragma unroll
            for (int c_ = 0; c_ < 4; c_++) acc[a_][b_][c_] = 0.f;

    int nkt = Kd / 64;
#pragma unroll
    for (int p = 0; p < 4; p++) {
        CP_ASYNC16(adst[p], asrc[p], asz[p]);
        CP_ASYNC16(bdst[p], bsrc[p], 16u);
    }
    CP_COMMIT();

    for (int kt = 0; kt < nkt; kt++) {
        int buf = kt & 1;
        if (kt + 1 < nkt) {
            int koff = (kt + 1) * 64;
            uint32_t boff = ((kt + 1) & 1) * GBUF;
#pragma unroll
            for (int p = 0; p < 4; p++) {
                CP_ASYNC16(adst[p] + boff, asrc[p] + koff, asz[p]);
                CP_ASYNC16(bdst[p] + boff, bsrc[p] + koff, 16u);
            }
            CP_COMMIT();
            CP_WAIT1();
        } else {
            CP_WAIT0();
        }
        __syncthreads();

        uint32_t ab = sb + buf * GBUF;
        uint32_t bb = sb + 2*GBUF + buf * GBUF;
#pragma unroll
        for (int ks = 0; ks < 4; ks++) {
            uint32_t af[4][4], bf[2][4];
#pragma unroll
            for (int mf = 0; mf < 4; mf++) ldm_x4(af[mf], ab + offA[mf] + ks*32);
#pragma unroll
            for (int j = 0; j < 2; j++) ldm_x4(bf[j], bb + offB[j] + ks*32);
#pragma unroll
            for (int mf = 0; mf < 4; mf++)
#pragma unroll
                for (int nf = 0; nf < 4; nf++)
                    mma_f16(acc[mf][nf], af[mf], &bf[nf >> 1][(nf & 1) * 2]);
        }
        __syncthreads();
    }

#pragma unroll
    for (int mf = 0; mf < 4; mf++) {
        int rA = m0 + wm + mf*16 + g;
        int rB = rA + 8;
#pragma unroll
        for (int nf = 0; nf < 4; nf++) {
            int col = n0 + wn + nf*8 + t*2;
            float2 bb2 = *(const float2*)&bias[col];
            float2 v0, v1;
            v0.x = acc[mf][nf][0] + bb2.x; v0.y = acc[mf][nf][1] + bb2.y;
            v1.x = acc[mf][nf][2] + bb2.x; v1.y = acc[mf][nf][3] + bb2.y;
            if (RELU) {
                v0.x = fmaxf(v0.x, 0.f); v0.y = fmaxf(v0.y, 0.f);
                v1.x = fmaxf(v1.x, 0.f); v1.y = fmaxf(v1.y, 0.f);
            }
            if (rA < M) {
                if (WMODE & 1) *(float2*)&C[(long)rA*ldc + col] = v0;
                if (WMODE & 2) *(__half2*)&C16[(long)rA*ldc + col] = __floats2half2_rn(v0.x, v0.y);
            }
            if (rB < M) {
                if (WMODE & 1) *(float2*)&C[(long)rB*ldc + col] = v1;
                if (WMODE & 2) *(__half2*)&C16[(long)rB*ldc + col] = __floats2half2_rn(v1.x, v1.y);
            }
        }
    }
}

// ================= attention: flash fp16 mma + ldmatrix + cp.async prefetch =================
#define AQB 0
#define AKB 18432
#define AVB 36864
#define APB 55296
#define AKVB 9216
#define ATT_SMEM 73728
__global__ void __launch_bounds__(256) attn_h_kernel(const __half* __restrict__ qkv,
                                                     __half* __restrict__ out)
{
    extern __shared__ char smc[];
    uint32_t sb = smem_u32(smc);
    uint32_t* Pw = (uint32_t*)(smc + APB);

    int q0 = blockIdx.x * 128;
    int hh = blockIdx.y;
    int b  = blockIdx.z;
    int tid = threadIdx.x, lane = tid & 31, warp = tid >> 5;
    int g = lane >> 2, t = lane & 3;
    const __half* base  = qkv + (long)b * SS * (3*DD) + hh * HD;
    const __half* kbase = base + DD;
    const __half* vbase = base + 2*DD;

    int srow0 = tid >> 3, sc8 = tid & 7;
    int srow1 = srow0 + 32;
    uint32_t kd0 = sb + AKB + srow0*144 + sc8*16;
    uint32_t kd1 = sb + AKB + srow1*144 + sc8*16;
    uint32_t vd0 = sb + AVB + srow0*144 + sc8*16;
    uint32_t vd1 = sb + AVB + srow1*144 + sc8*16;

    {
        const __half* k0 = kbase + (long)srow0*(3*DD) + sc8*8;
        const __half* k1 = kbase + (long)srow1*(3*DD) + sc8*8;
        const __half* v0 = vbase + (long)srow0*(3*DD) + sc8*8;
        const __half* v1 = vbase + (long)srow1*(3*DD) + sc8*8;
        CP_ASYNC16(kd0, k0, 16u); CP_ASYNC16(kd1, k1, 16u);
        CP_ASYNC16(vd0, v0, 16u); CP_ASYNC16(vd1, v1, 16u);
    }
    CP_COMMIT();

#pragma unroll
    for (int p = 0; p < 4; p++) {
        int idx = tid + p*256;
        int row = idx >> 3, c8 = idx & 7;
        *(uint4*)(smc + AQB + row*144 + c8*16) =
            *(const uint4*)(base + (long)(q0 + row) * (3*DD) + c8*8);
    }

    uint32_t qrow  = (lane & 7) + ((lane >> 3) & 1) * 8;
    uint32_t khalf = (lane >> 4) * 16;
    uint32_t offQ = sb + AQB + (warp*16 + qrow)*144 + khalf;
    uint32_t offP = sb + APB + (warp*16 + qrow)*144 + khalf;
    uint32_t offK[4], offV[4];
#pragma unroll
    for (int j = 0; j < 4; j++)
        offK[j] = (uint32_t)(j*16 + ((lane >> 4) & 1)*8 + (lane & 7)) * 144
                + ((lane >> 3) & 1) * 16;
    {
        uint32_t kr = ((lane >> 3) & 1)*8 + (lane & 7);
#pragma unroll
        for (int j = 0; j < 4; j++)
            offV[j] = kr*144 + j*32 + ((lane >> 4) & 1)*16;
    }

    int r0 = warp*16 + g;
    float mm0 = -1e30f, mm1 = -1e30f, ll0 = 0.f, ll1 = 0.f;
    float o[8][4];
#pragma unroll
    for (int nf = 0; nf < 8; nf++)
#pragma unroll
        for (int c = 0; c < 4; c++) o[nf][c] = 0.f;

    for (int jc = 0; jc < SS/64; jc++) {
        int buf = jc & 1;
        CP_WAIT0();
        __syncthreads();
        if (jc + 1 < SS/64) {
            uint32_t nb = (uint32_t)(buf ^ 1) * AKVB;
            long goff = (long)(jc + 1) * 64 * (3*DD);
            const __half* k0 = kbase + goff + (long)srow0*(3*DD) + sc8*8;
            const __half* k1 = kbase + goff + (long)srow1*(3*DD) + sc8*8;
            const __half* v0 = vbase + goff + (long)srow0*(3*DD) + sc8*8;
            const __half* v1 = vbase + goff + (long)srow1*(3*DD) + sc8*8;
            CP_ASYNC16(kd0 + nb, k0, 16u); CP_ASYNC16(kd1 + nb, k1, 16u);
            CP_ASYNC16(vd0 + nb, v0, 16u); CP_ASYNC16(vd1 + nb, v1, 16u);
            CP_COMMIT();
        }
        uint32_t kb = sb + AKB + buf * AKVB;
        uint32_t vb = sb + AVB + buf * AKVB;

        float s[8][4];
#pragma unroll
        for (int nf = 0; nf < 8; nf++)
#pragma unroll
            for (int c = 0; c < 4; c++) s[nf][c] = 0.f;
#pragma unroll
        for (int ks = 0; ks < 4; ks++) {
            uint32_t a[4];
            ldm_x4(a, offQ + ks*32);
#pragma unroll
            for (int j = 0; j < 4; j++) {
                uint32_t bf[4];
                ldm_x4(bf, kb + offK[j] + ks*32);
                mma_f16(s[2*j],   a, &bf[0]);
                mma_f16(s[2*j+1], a, &bf[2]);
            }
        }
        float mx0 = mm0, mx1 = mm1;
#pragma unroll
        for (int nf = 0; nf < 8; nf++) {
            s[nf][0] *= 0.125f; s[nf][1] *= 0.125f;
            s[nf][2] *= 0.125f; s[nf][3] *= 0.125f;
            mx0 = fmaxf(mx0, fmaxf(s[nf][0], s[nf][1]));
            mx1 = fmaxf(mx1, fmaxf(s[nf][2], s[nf][3]));
        }
        mx0 = fmaxf(mx0, __shfl_xor_sync(0xffffffffu, mx0, 1));
        mx0 = fmaxf(mx0, __shfl_xor_sync(0xffffffffu, mx0, 2));
        mx1 = fmaxf(mx1, __shfl_xor_sync(0xffffffffu, mx1, 1));
        mx1 = fmaxf(mx1, __shfl_xor_sync(0xffffffffu, mx1, 2));
        float al0 = __expf(mm0 - mx0), al1 = __expf(mm1 - mx1);
        float sum0 = 0.f, sum1 = 0.f;
#pragma unroll
        for (int nf = 0; nf < 8; nf++) {
            s[nf][0] = __expf(s[nf][0] - mx0);
            s[nf][1] = __expf(s[nf][1] - mx0);
            s[nf][2] = __expf(s[nf][2] - mx1);
            s[nf][3] = __expf(s[nf][3] - mx1);
            sum0 += s[nf][0] + s[nf][1];
            sum1 += s[nf][2] + s[nf][3];
        }
        sum0 += __shfl_xor_sync(0xffffffffu, sum0, 1);
        sum0 += __shfl_xor_sync(0xffffffffu, sum0, 2);
        sum1 += __shfl_xor_sync(0xffffffffu, sum1, 1);
        sum1 += __shfl_xor_sync(0xffffffffu, sum1, 2);
        ll0 = ll0*al0 + sum0; ll1 = ll1*al1 + sum1;
        mm0 = mx0; mm1 = mx1;
#pragma unroll
        for (int nf = 0; nf < 8; nf++) {
            o[nf][0] *= al0; o[nf][1] *= al0;
            o[nf][2] *= al1; o[nf][3] *= al1;
        }
#pragma unroll
        for (int nf = 0; nf < 8; nf++) {
            Pw[(warp*16 + g)*36 + nf*4 + t]     = h2u(__floats2half2_rn(s[nf][0], s[nf][1]));
            Pw[(warp*16 + g + 8)*36 + nf*4 + t] = h2u(__floats2half2_rn(s[nf][2], s[nf][3]));
        }
        __syncwarp();
#pragma unroll
        for (int ks = 0; ks < 4; ks++) {
            uint32_t a[4];
            ldm_x4(a, offP + ks*32);
#pragma unroll
            for (int j = 0; j < 4; j++) {
                uint32_t bf[4];
                ldm_x4_t(bf, vb + offV[j] + ks*2304);
                mma_f16(o[2*j],   a, &bf[0]);
                mma_f16(o[2*j+1], a, &bf[2]);
            }
        }
    }

    float inv0 = 1.f / ll0, inv1 = 1.f / ll1;
    long tok0 = (long)(b*SS + q0 + r0) * DD + hh*HD;
    long tok1 = tok0 + 8L*DD;
#pragma unroll
    for (int nf = 0; nf < 8; nf++) {
        int col = nf*8 + 2*t;
        *(__half2*)&out[tok0 + col] = __floats2half2_rn(o[nf][0]*inv0, o[nf][1]*inv0);
        *(__half2*)&out[tok1 + col] = __floats2half2_rn(o[nf][2]*inv1, o[nf][3]*inv1);
    }
}

// ---------------- instance-norm stats (+ zero all per-layer MoE counters) ----------------
__global__ void istats_kernel(const float* __restrict__ x, float* __restrict__ stats,
                              int* __restrict__ cntAll)
{
    int bf = blockIdx.x;
    int b = bf >> 3, f = bf & 7;
    int tid = threadIdx.x;
    if (bf == 0 && tid < LL*EE) cntAll[tid] = 0;
    float s = 0.f, ss = 0.f;
    for (int i = tid; i < SS; i += 256) {
        float v = x[((long)b*SS + i)*FF + f];
        s += v; ss += v*v;
    }
    __shared__ float red[16];
    int lane = tid & 31, wid = tid >> 5;
#pragma unroll
    for (int o = 16; o; o >>= 1) {
        s  += __shfl_down_sync(0xffffffffu, s, o);
        ss += __shfl_down_sync(0xffffffffu, ss, o);
    }
    if (!lane) { red[wid] = s; red[8+wid] = ss; }
    __syncthreads();
    if (!tid) {
        float S = 0.f, Q = 0.f;
        for (int w = 0; w < 8; w++) { S += red[w]; Q += red[8+w]; }
        float m = S / SS;
        float var = (Q - SS*m*m) / (SS - 1);
        stats[bf*2]   = m;
        stats[bf*2+1] = 1.f / (sqrtf(var) + 1e-5f);
    }
}

// ---------------- embed (writes fp32 + fp16) ----------------
__global__ void embed_kernel(const float* __restrict__ x, const float* __restrict__ Wp,
                             const float* __restrict__ bp, const float* __restrict__ femb,
                             const int* __restrict__ fidx, const float* __restrict__ stats,
                             float* __restrict__ h, __half* __restrict__ h16)
{
    int token = blockIdx.x;
    int b = token >> 10, s = token & 1023;
    int tid = threadIdx.x;
    __shared__ float xn[8];
    if (tid < 8) {
        float m = stats[(b*8+tid)*2], inv = stats[(b*8+tid)*2+1];
        xn[tid] = (x[(long)token*FF + tid] - m) * inv;
    }
    __syncthreads();
    int fi = *fidx;
    int d0 = tid * 4;
    float4 acc = *(const float4*)&bp[d0];
    float* ap = &acc.x;
#pragma unroll
    for (int f = 0; f < 8; f++) {
        float xv = xn[f];
        ap[0] += xv * Wp[(d0+0)*8+f];
        ap[1] += xv * Wp[(d0+1)*8+f];
        ap[2] += xv * Wp[(d0+2)*8+f];
        ap[3] += xv * Wp[(d0+3)*8+f];
    }
    const float c = -0.0179889460f;
#pragma unroll
    for (int j = 0; j < 4; j++) {
        int d = d0 + j;
        int i = d >> 1;
        float ang = (float)s * expf((float)(2*i) * c);
        float pe = (d & 1) ? cosf(ang) : sinf(ang);
        ap[j] += femb[fi*DD + d] + pe;
    }
    *(float4*)&h[(long)token*DD + d0] = acc;
    __half2* hp = (__half2*)&h16[(long)token*DD + d0];
    hp[0] = __floats2half2_rn(acc.x, acc.y);
    hp[1] = __floats2half2_rn(acc.z, acc.w);
}

// ---------------- add + layernorm + fused MoE gating ----------------
__global__ void add_ln_gate_kernel(const float* __restrict__ base, const float* __restrict__ add,
                                   const float* __restrict__ g, const float* __restrict__ bet,
                                   const float* __restrict__ gw, const float* __restrict__ gb,
                                   float* __restrict__ out, __half* __restrict__ out16,
                                   int* __restrict__ cnt, int* __restrict__ etok,
                                   int* __restrict__ slot, float* __restrict__ wt)
{
    long tk = blockIdx.x;
    int tid = threadIdx.x;
    float4 xb = *(const float4*)&base[tk*DD + tid*4];
    float4 xa = *(const float4*)&add[tk*DD + tid*4];
    float v0=xb.x+xa.x, v1=xb.y+xa.y, v2=xb.z+xa.z, v3=xb.w+xa.w;
    float s = v0+v1+v2+v3, ss = v0*v0+v1*v1+v2*v2+v3*v3;
    __shared__ float red[16];
    __shared__ float gred[4][4];
    int lane = tid & 31, wid = tid >> 5;
#pragma unroll
    for (int o = 16; o; o >>= 1) {
        s  += __shfl_down_sync(0xffffffffu, s, o);
        ss += __shfl_down_sync(0xffffffffu, ss, o);
    }
    if (!lane) { red[wid] = s; red[8+wid] = ss; }
    __syncthreads();
    if (!tid) {
        float S = red[0]+red[1]+red[2]+red[3];
        float Q = red[8]+red[9]+red[10]+red[11];
        red[0] = S * (1.f/DD);
        red[1] = Q * (1.f/DD);
    }
    __syncthreads();
    float m = red[0];
    float r = rsqrtf(red[1] - m*m + 1e-5f);
    float4 gv = *(const float4*)&g[tid*4];
    float4 bv = *(const float4*)&bet[tid*4];
    float4 o4;
    o4.x = (v0-m)*r*gv.x + bv.x;
    o4.y = (v1-m)*r*gv.y + bv.y;
    o4.z = (v2-m)*r*gv.z + bv.z;
    o4.w = (v3-m)*r*gv.w + bv.w;
    *(float4*)&out[tk*DD + tid*4] = o4;
    __half2* hp = (__half2*)&out16[tk*DD + tid*4];
    hp[0] = __floats2half2_rn(o4.x, o4.y);
    hp[1] = __floats2half2_rn(o4.z, o4.w);

    // ---- fused gating: logits[e] = dot(ln_row, gw[e]) + gb[e] ----
    float p[4];
#pragma unroll
    for (int e = 0; e < 4; e++) {
        float4 wv = *(const float4*)&gw[e*DD + tid*4];
        p[e] = o4.x*wv.x + o4.y*wv.y + o4.z*wv.z + o4.w*wv.w;
    }
#pragma unroll
    for (int e = 0; e < 4; e++)
#pragma unroll
        for (int o = 16; o; o >>= 1)
            p[e] += __shfl_down_sync(0xffffffffu, p[e], o);
    if (!lane) {
        gred[wid][0] = p[0]; gred[wid][1] = p[1];
        gred[wid][2] = p[2]; gred[wid][3] = p[3];
    }
    __syncthreads();
    if (!tid) {
        float lg[4], pr[4];
        float mx = -1e30f;
#pragma unroll
        for (int e = 0; e < 4; e++) {
            lg[e] = gred[0][e]+gred[1][e]+gred[2][e]+gred[3][e] + gb[e];
            mx = fmaxf(mx, lg[e]);
        }
        float sum = 0.f;
#pragma unroll
        for (int e = 0; e < 4; e++) { pr[e] = expf(lg[e]-mx); sum += pr[e]; }
#pragma unroll
        for (int e = 0; e < 4; e++) pr[e] /= sum;
        int i0 = 0;
#pragma unroll
        for (int e = 1; e < 4; e++) if (pr[e] > pr[i0]) i0 = e;
        int i1 = (i0 == 0) ? 1 : 0;
#pragma unroll
        for (int e = 0; e < 4; e++) if (e != i0 && pr[e] > pr[i1]) i1 = e;
        float w0 = pr[i0], w1 = pr[i1];
        float inv = 1.f / (w0 + w1);
        int pos0 = atomicAdd(&cnt[i0], 1);
        etok[i0*TT + pos0] = (int)tk;
        slot[2*tk]   = i0*TT + pos0;
        wt[2*tk]     = w0 * inv;
        int pos1 = atomicAdd(&cnt[i1], 1);
        etok[i1*TT + pos1] = (int)tk;
        slot[2*tk+1] = i1*TT + pos1;
        wt[2*tk+1]   = w1 * inv;
    }
}

// ---------------- moe combine + layernorm (eo in fp16) ----------------
__global__ void moe_combine_ln_kernel(const float* __restrict__ h, const __half* __restrict__ eo,
                                      const int* __restrict__ slot, const float* __restrict__ wt,
                                      const float* __restrict__ g, const float* __restrict__ bet,
                                      float* __restrict__ out, __half* __restrict__ out16)
{
    long t = blockIdx.x;
    int tid = threadIdx.x;
    int s0 = slot[2*t], s1 = slot[2*t+1];
    float w0 = wt[2*t], w1 = wt[2*t+1];
    float4 xh = *(const float4*)&h[t*DD + tid*4];
    uint2 e0u = *(const uint2*)&eo[(long)s0*DD + tid*4];
    uint2 e1u = *(const uint2*)&eo[(long)s1*DD + tid*4];
    float2 e0a = __half22float2(*(__half2*)&e0u.x);
    float2 e0b = __half22float2(*(__half2*)&e0u.y);
    float2 e1a = __half22float2(*(__half2*)&e1u.x);
    float2 e1b = __half22float2(*(__half2*)&e1u.y);
    float v0 = xh.x + w0*e0a.x + w1*e1a.x;
    float v1 = xh.y + w0*e0a.y + w1*e1a.y;
    float v2 = xh.z + w0*e0b.x + w1*e1b.x;
    float v3 = xh.w + w0*e0b.y + w1*e1b.y;
    float s = v0+v1+v2+v3, ss = v0*v0+v1*v1+v2*v2+v3*v3;
    __shared__ float red[16];
    int lane = tid & 31, wid = tid >> 5;
#pragma unroll
    for (int o = 16; o; o >>= 1) {
        s  += __shfl_down_sync(0xffffffffu, s, o);
        ss += __shfl_down_sync(0xffffffffu, ss, o);
    }
    if (!lane) { red[wid] = s; red[8+wid] = ss; }
    __syncthreads();
    if (!tid) {
        float S = red[0]+red[1]+red[2]+red[3];
        float Q = red[8]+red[9]+red[10]+red[11];
        red[0] = S * (1.f/DD);
        red[1] = Q * (1.f/DD);
    }
    __syncthreads();
    float m = red[0];
    float r = rsqrtf(red[1] - m*m + 1e-5f);
    float4 gv = *(const float4*)&g[tid*4];
    float4 bv = *(const float4*)&bet[tid*4];
    float4 o4;
    o4.x = (v0-m)*r*gv.x + bv.x;
    o4.y = (v1-m)*r*gv.y + bv.y;
    o4.z = (v2-m)*r*gv.z + bv.z;
    o4.w = (v3-m)*r*gv.w + bv.w;
    *(float4*)&out[t*DD + tid*4] = o4;
    __half2* hp = (__half2*)&out16[t*DD + tid*4];
    hp[0] = __floats2half2_rn(o4.x, o4.y);
    hp[1] = __floats2half2_rn(o4.z, o4.w);
}

// ---------------- head ----------------
__global__ void head_kernel(const float* __restrict__ h, const float* __restrict__ hw,
                            const float* __restrict__ hb, float* __restrict__ out)
{
    int w = threadIdx.x >> 5, lane = threadIdx.x & 31;
    int b = w / 3, i = w % 3;
    const float* hp = h + ((long)(b*SS + SS-1)) * DD;
    float s = 0.f;
#pragma unroll
    for (int it = 0; it < 4; it++) {
        int d0 = (it*32 + lane) * 4;
        float4 a = *(const float4*)&hp[d0];
        float4 c = *(const float4*)&hw[i*DD + d0];
        s += a.x*c.x + a.y*c.y + a.z*c.z + a.w*c.w;
    }
#pragma unroll
    for (int o = 16; o; o >>= 1) s += __shfl_down_sync(0xffffffffu, s, o);
    if (!lane) out[b*3+i] = s + hb[i];
}

// ---------------- orchestration ----------------
extern "C" void kernel_launch(void* const* d_in, const int* in_sizes, int n_in,
                              void* d_out, int out_size)
{
    const float* x      = (const float*)d_in[0];
    const float* Wp     = (const float*)d_in[1];
    const float* bp     = (const float*)d_in[2];
    const float* femb   = (const float*)d_in[3];
    const float* qkv_w  = (const float*)d_in[4];
    const float* qkv_b  = (const float*)d_in[5];
    const float* ow     = (const float*)d_in[6];
    const float* ob     = (const float*)d_in[7];
    const float* g1     = (const float*)d_in[8];
    const float* beta1  = (const float*)d_in[9];
    const float* gw     = (const float*)d_in[10];
    const float* gb     = (const float*)d_in[11];
    const float* ew1    = (const float*)d_in[12];
    const float* eb1    = (const float*)d_in[13];
    const float* ew2    = (const float*)d_in[14];
    const float* eb2    = (const float*)d_in[15];
    const float* g2     = (const float*)d_in[16];
    const float* beta2  = (const float*)d_in[17];
    const float* hw     = (const float*)d_in[18];
    const float* hb     = (const float*)d_in[19];
    const int*   fidx   = (const int*)d_in[20];
    float* out = (float*)d_out;

    float *h, *tmp, *wt, *istats;
    int *cnt, *etok, *slot;
    __half *h16, *qkv16, *attn16, *hid16, *eo16, *qkvw16, *ow16, *ew116, *ew216;
    cudaGetSymbolAddress((void**)&h,      g_h);
    cudaGetSymbolAddress((void**)&tmp,    g_tmp);
    cudaGetSymbolAddress((void**)&cnt,    g_cnt);
    cudaGetSymbolAddress((void**)&etok,   g_etok);
    cudaGetSymbolAddress((void**)&slot,   g_slot);
    cudaGetSymbolAddress((void**)&wt,     g_wt);
    cudaGetSymbolAddress((void**)&istats, g_istats);
    cudaGetSymbolAddress((void**)&h16,    g_h16);
    cudaGetSymbolAddress((void**)&qkv16,  g_qkv16);
    cudaGetSymbolAddress((void**)&attn16, g_attn16);
    cudaGetSymbolAddress((void**)&hid16,  g_hid16);
    cudaGetSymbolAddress((void**)&eo16,   g_eo16);
    cudaGetSymbolAddress((void**)&qkvw16, g_qkvw16);
    cudaGetSymbolAddress((void**)&ow16,   g_ow16);
    cudaGetSymbolAddress((void**)&ew116,  g_ew116);
    cudaGetSymbolAddress((void**)&ew216,  g_ew216);

    cudaFuncSetAttribute(attn_h_kernel, cudaFuncAttributeMaxDynamicSharedMemorySize, ATT_SMEM);
    cudaFuncSetAttribute(gemm_h<false,false,1>, cudaFuncAttributeMaxDynamicSharedMemorySize, GEMM_SMEM);
    cudaFuncSetAttribute(gemm_h<false,false,2>, cudaFuncAttributeMaxDynamicSharedMemorySize, GEMM_SMEM);
    cudaFuncSetAttribute(gemm_h<true,true,2>,   cudaFuncAttributeMaxDynamicSharedMemorySize, GEMM_SMEM);

    // weight conversion (fp32 -> fp16), single launch
    f2h_all_kernel<<<(NTOTF4 + 255)/256, 256>>>(qkv_w, qkvw16, ow, ow16, ew1, ew116, ew2, ew216);

    istats_kernel<<<BB*FF, 256>>>(x, istats, cnt);
    embed_kernel<<<TT, 128>>>(x, Wp, bp, femb, fidx, istats, h, h16);

    for (int l = 0; l < LL; l++) {
        // QKV projection -> half only
        gemm_h<false,false,2><<<dim3(3*DD/128, TT/128, 1), 256, GEMM_SMEM>>>(
            h16, qkvw16 + (long)l*3*DD*DD, qkv_b + l*3*DD, nullptr, qkv16,
            TT, 3*DD, DD, DD, 3*DD, 0, 0, 0, 0, nullptr, nullptr);
        // attention (fp16 flash) -> half
        attn_h_kernel<<<dim3(SS/128, HH, BB), 256, ATT_SMEM>>>(qkv16, attn16);
        // output projection -> fp32
        gemm_h<false,false,1><<<dim3(DD/128, TT/128, 1), 256, GEMM_SMEM>>>(
            attn16, ow16 + (long)l*DD*DD, ob + l*DD, tmp, nullptr,
            TT, DD, DD, DD, DD, 0, 0, 0, 0, nullptr, nullptr);
        // add + LN + fused gating
        add_ln_gate_kernel<<<TT, 128>>>(h, tmp, g1 + l*DD, beta1 + l*DD,
                                        gw + l*EE*DD, gb + l*EE,
                                        h, h16, cnt + l*EE, etok, slot, wt);
        // MoE expert FFNs (routed)
        gemm_h<true,true,2><<<dim3(2*DD/128, TT/128, EE), 256, GEMM_SMEM>>>(
            h16, ew116 + (long)l*EE*2*DD*DD, eb1 + l*EE*2*DD, nullptr, hid16,
            TT, 2*DD, DD, DD, 2*DD,
            0, (long)2*DD*DD, 2*DD, (long)TT*2*DD, etok, cnt + l*EE);
        gemm_h<false,false,2><<<dim3(DD/128, TT/128, EE), 256, GEMM_SMEM>>>(
            hid16, ew216 + (long)l*EE*2*DD*DD, eb2 + l*EE*DD, nullptr, eo16,
            TT, DD, 2*DD, 2*DD, DD,
            (long)TT*2*DD, (long)2*DD*DD, DD, (long)TT*DD, nullptr, cnt + l*EE);
        moe_combine_ln_kernel<<<TT, 128>>>(h, eo16, slot, wt, g2 + l*DD, beta2 + l*DD, h, h16);
    }
    head_kernel<<<1, 768>>>(h, hw, hb, out);
}

// round 8
// speedup vs baseline: 5.9848x; 1.0122x over previous
#include <cuda_runtime.h>
#include <cuda_fp16.h>
#include <math.h>
#include <cstdint>

#define BB 8
#define SS 1024
#define FF 8
#define DD 512
#define HH 8
#define LL 3
#define EE 4
#define TT (BB*SS)
#define HD 64

// ---------------- scratch (device globals; no allocs allowed) ----------------
__device__ float g_h[TT*DD];
__device__ int   g_cnt[LL*EE];
__device__ int   g_etok[EE*TT];
__device__ int   g_slot[2*TT];
__device__ float g_wt[2*TT];
__device__ float g_istats[BB*FF*2];

__device__ __align__(16) __half g_h16[TT*DD];
__device__ __align__(16) __half g_qkv16[TT*3*DD];
__device__ __align__(16) __half g_attn16[TT*DD];
__device__ __align__(16) __half g_tmp16[TT*DD];
__device__ __align__(16) __half g_hid16[(size_t)EE*TT*2*DD];
__device__ __align__(16) __half g_eo16[(size_t)EE*TT*DD];
__device__ __align__(16) __half g_qkvw16[LL*3*DD*DD];
__device__ __align__(16) __half g_ow16[LL*DD*DD];
__device__ __align__(16) __half g_ew116[(size_t)LL*EE*2*DD*DD];
__device__ __align__(16) __half g_ew216[(size_t)LL*EE*2*DD*DD];

__device__ __forceinline__ uint32_t smem_u32(const void* p) {
    uint32_t a;
    asm("{ .reg .u64 t; cvta.to.shared.u64 t, %1; cvt.u32.u64 %0, t; }" : "=r"(a) : "l"(p));
    return a;
}
__device__ __forceinline__ void mma_f16(float* d, const uint32_t* a, const uint32_t* b) {
    asm volatile(
      "mma.sync.aligned.m16n8k16.row.col.f32.f16.f16.f32 "
      "{%0,%1,%2,%3}, {%4,%5,%6,%7}, {%8,%9}, {%0,%1,%2,%3};"
      : "+f"(d[0]), "+f"(d[1]), "+f"(d[2]), "+f"(d[3])
      : "r"(a[0]), "r"(a[1]), "r"(a[2]), "r"(a[3]), "r"(b[0]), "r"(b[1]));
}
__device__ __forceinline__ void ldm_x4(uint32_t* r, uint32_t addr) {
    asm volatile("ldmatrix.sync.aligned.m8n8.x4.shared.b16 {%0,%1,%2,%3}, [%4];"
        : "=r"(r[0]), "=r"(r[1]), "=r"(r[2]), "=r"(r[3]) : "r"(addr));
}
__device__ __forceinline__ void ldm_x4_t(uint32_t* r, uint32_t addr) {
    asm volatile("ldmatrix.sync.aligned.m8n8.x4.trans.shared.b16 {%0,%1,%2,%3}, [%4];"
        : "=r"(r[0]), "=r"(r[1]), "=r"(r[2]), "=r"(r[3]) : "r"(addr));
}
#define CP_ASYNC16(dst, src, sz) \
  asm volatile("cp.async.cg.shared.global [%0], [%1], 16, %2;" :: "r"(dst), "l"(src), "r"(sz) : "memory")
#define CP_COMMIT() asm volatile("cp.async.commit_group;" ::: "memory")
#define CP_WAIT0()  asm volatile("cp.async.wait_group 0;" ::: "memory")
#define CP_WAIT1()  asm volatile("cp.async.wait_group 1;" ::: "memory")

__device__ __forceinline__ uint32_t h2u(__half2 h) { return *(uint32_t*)&h; }

// ---------------- merged fp32 -> fp16 weight convert (single launch) ----------------
#define N1F4 (LL*3*DD*DD/4)
#define N2F4 (LL*DD*DD/4)
#define N3F4 (LL*EE*2*DD*DD/4)
#define NTOTF4 (N1F4 + N2F4 + 2*N3F4)
__global__ void f2h_all_kernel(const float* __restrict__ s1, __half* __restrict__ d1,
                               const float* __restrict__ s2, __half* __restrict__ d2,
                               const float* __restrict__ s3, __half* __restrict__ d3,
                               const float* __restrict__ s4, __half* __restrict__ d4)
{
    long i = (long)blockIdx.x * 256 + threadIdx.x;
    if (i >= NTOTF4) return;
    const float* src; __half* dst; long j;
    if (i < N1F4)                    { src = s1; dst = d1; j = i; }
    else if (i < N1F4 + N2F4)        { src = s2; dst = d2; j = i - N1F4; }
    else if (i < N1F4 + N2F4 + N3F4) { src = s3; dst = d3; j = i - N1F4 - N2F4; }
    else                             { src = s4; dst = d4; j = i - N1F4 - N2F4 - N3F4; }
    float4 v = ((const float4*)src)[j];
    __half2* op = (__half2*)(dst + 4*j);
    op[0] = __floats2half2_rn(v.x, v.y);
    op[1] = __floats2half2_rn(v.z, v.w);
}

// ================= fp16 mma GEMM: 3-stage cp.async, single sync per K-tile =================
#define GBUF (128*144)
#define GEMM_SMEM (6*GBUF)         // 3 stages x (A,B) = 110592 B
template<bool GATHER, bool RELU, int WMODE>   // WMODE bit0: fp32 C, bit1: half C16
__global__ void __launch_bounds__(256) gemm_h(
    const __half* __restrict__ A, const __half* __restrict__ W,
    const float* __restrict__ bias, float* __restrict__ C, __half* __restrict__ C16,
    int M, int N, int Kd, int lda, int ldc,
    long astride, long wstride, int bstride, long cstride,
    const int* __restrict__ gidx, const int* __restrict__ cnts)
{
    extern __shared__ char smem[];
    int e = blockIdx.z;
    A    += (long)e * astride;
    W    += (long)e * wstride;
    bias += (long)e * bstride;
    if (WMODE & 1) C   += (long)e * cstride;
    if (WMODE & 2) C16 += (long)e * cstride;
    if (cnts) M = cnts[e];
    int m0 = blockIdx.y * 128;
    if (m0 >= M) return;
    int n0 = blockIdx.x * 128;

    int tid = threadIdx.x, lane = tid & 31, warp = tid >> 5;
    int g = lane >> 2, t = lane & 3;
    int wm = (warp >> 2) * 64, wn = (warp & 3) * 32;

    uint32_t sb = smem_u32(smem);
    int rbase = tid >> 3, c8 = tid & 7;

    const __half* asrc[4]; uint32_t asz[4];
    const __half* bsrc[4];
    uint32_t adst[4], bdst[4];
#pragma unroll
    for (int p = 0; p < 4; p++) {
        int row = rbase + p * 32;
        int mr = m0 + row;
        bool ok = mr < M;
        int ar = 0;
        if (ok) ar = GATHER ? gidx[(long)e * TT + mr] : mr;
        asrc[p] = A + (long)ar * lda + c8 * 8;
        asz[p] = ok ? 16u : 0u;
        bsrc[p] = W + (long)(n0 + row) * Kd + c8 * 8;
        adst[p] = sb + row * 144 + c8 * 16;
        bdst[p] = sb + 3*GBUF + row * 144 + c8 * 16;
    }

    uint32_t qrow  = (lane & 7) + ((lane >> 3) & 1) * 8;
    uint32_t khalf = (lane >> 4) * 16;
    uint32_t offA[4], offB[2];
#pragma unroll
    for (int mf = 0; mf < 4; mf++) offA[mf] = (wm + mf*16 + qrow) * 144 + khalf;
#pragma unroll
    for (int j = 0; j < 2; j++)
        offB[j] = (uint32_t)(wn + j*16 + ((lane >> 4) & 1)*8 + (lane & 7)) * 144
                + ((lane >> 3) & 1) * 16;

    float acc[4][4][4];
#pragma unroll
    for (int a_ = 0; a_ < 4; a_++)
#pragma unroll
        for (int b_ = 0; b_ < 4; b_++)
#pragma unroll
            for (int c_ = 0; c_ < 4; c_++) acc[a_][b_][c_] = 0.f;

    int nkt = Kd / 64;

    // stage(s): issue cp.async for K-tile s into buffer s%3 and commit
    #define STAGE(s) do { \
        uint32_t _off = (uint32_t)((s) % 3) * GBUF; \
        int _ko = (s) * 64; \
        _Pragma("unroll") \
        for (int p = 0; p < 4; p++) { \
            CP_ASYNC16(adst[p] + _off, asrc[p] + _ko, asz[p]); \
            CP_ASYNC16(bdst[p] + _off, bsrc[p] + _ko, 16u); \
        } \
        CP_COMMIT(); \
    } while (0)

    STAGE(0);
    STAGE(1);

    for (int kt = 0; kt < nkt; kt++) {
        if (kt + 1 < nkt) CP_WAIT1(); else CP_WAIT0();
        __syncthreads();
        if (kt + 2 < nkt) STAGE(kt + 2);

        uint32_t ab = sb + (uint32_t)(kt % 3) * GBUF;
        uint32_t bb = sb + 3*GBUF + (uint32_t)(kt % 3) * GBUF;
#pragma unroll
        for (int ks = 0; ks < 4; ks++) {
            uint32_t af[4][4], bf[2][4];
#pragma unroll
            for (int mf = 0; mf < 4; mf++) ldm_x4(af[mf], ab + offA[mf] + ks*32);
#pragma unroll
            for (int j = 0; j < 2; j++) ldm_x4(bf[j], bb + offB[j] + ks*32);
#pragma unroll
            for (int mf = 0; mf < 4; mf++)
#pragma unroll
                for (int nf = 0; nf < 4; nf++)
                    mma_f16(acc[mf][nf], af[mf], &bf[nf >> 1][(nf & 1) * 2]);
        }
    }
    #undef STAGE

#pragma unroll
    for (int mf = 0; mf < 4; mf++) {
        int rA = m0 + wm + mf*16 + g;
        int rB = rA + 8;
#pragma unroll
        for (int nf = 0; nf < 4; nf++) {
            int col = n0 + wn + nf*8 + t*2;
            float2 bb2 = *(const float2*)&bias[col];
            float2 v0, v1;
            v0.x = acc[mf][nf][0] + bb2.x; v0.y = acc[mf][nf][1] + bb2.y;
            v1.x = acc[mf][nf][2] + bb2.x; v1.y = acc[mf][nf][3] + bb2.y;
            if (RELU) {
                v0.x = fmaxf(v0.x, 0.f); v0.y = fmaxf(v0.y, 0.f);
                v1.x = fmaxf(v1.x, 0.f); v1.y = fmaxf(v1.y, 0.f);
            }
            if (rA < M) {
                if (WMODE & 1) *(float2*)&C[(long)rA*ldc + col] = v0;
                if (WMODE & 2) *(__half2*)&C16[(long)rA*ldc + col] = __floats2half2_rn(v0.x, v0.y);
            }
            if (rB < M) {
                if (WMODE & 1) *(float2*)&C[(long)rB*ldc + col] = v1;
                if (WMODE & 2) *(__half2*)&C16[(long)rB*ldc + col] = __floats2half2_rn(v1.x, v1.y);
            }
        }
    }
}

// ================= attention: flash fp16 mma + ldmatrix + cp.async prefetch =================
#define AQB 0
#define AKB 18432
#define AVB 36864
#define APB 55296
#define AKVB 9216
#define ATT_SMEM 73728
__global__ void __launch_bounds__(256) attn_h_kernel(const __half* __restrict__ qkv,
                                                     __half* __restrict__ out)
{
    extern __shared__ char smc[];
    uint32_t sb = smem_u32(smc);
    uint32_t* Pw = (uint32_t*)(smc + APB);

    int q0 = blockIdx.x * 128;
    int hh = blockIdx.y;
    int b  = blockIdx.z;
    int tid = threadIdx.x, lane = tid & 31, warp = tid >> 5;
    int g = lane >> 2, t = lane & 3;
    const __half* base  = qkv + (long)b * SS * (3*DD) + hh * HD;
    const __half* kbase = base + DD;
    const __half* vbase = base + 2*DD;

    int srow0 = tid >> 3, sc8 = tid & 7;
    int srow1 = srow0 + 32;
    uint32_t kd0 = sb + AKB + srow0*144 + sc8*16;
    uint32_t kd1 = sb + AKB + srow1*144 + sc8*16;
    uint32_t vd0 = sb + AVB + srow0*144 + sc8*16;
    uint32_t vd1 = sb + AVB + srow1*144 + sc8*16;

    {
        const __half* k0 = kbase + (long)srow0*(3*DD) + sc8*8;
        const __half* k1 = kbase + (long)srow1*(3*DD) + sc8*8;
        const __half* v0 = vbase + (long)srow0*(3*DD) + sc8*8;
        const __half* v1 = vbase + (long)srow1*(3*DD) + sc8*8;
        CP_ASYNC16(kd0, k0, 16u); CP_ASYNC16(kd1, k1, 16u);
        CP_ASYNC16(vd0, v0, 16u); CP_ASYNC16(vd1, v1, 16u);
    }
    CP_COMMIT();

#pragma unroll
    for (int p = 0; p < 4; p++) {
        int idx = tid + p*256;
        int row = idx >> 3, c8 = idx & 7;
        *(uint4*)(smc + AQB + row*144 + c8*16) =
            *(const uint4*)(base + (long)(q0 + row) * (3*DD) + c8*8);
    }

    uint32_t qrow  = (lane & 7) + ((lane >> 3) & 1) * 8;
    uint32_t khalf = (lane >> 4) * 16;
    uint32_t offQ = sb + AQB + (warp*16 + qrow)*144 + khalf;
    uint32_t offP = sb + APB + (warp*16 + qrow)*144 + khalf;
    uint32_t offK[4], offV[4];
#pragma unroll
    for (int j = 0; j < 4; j++)
        offK[j] = (uint32_t)(j*16 + ((lane >> 4) & 1)*8 + (lane & 7)) * 144
                + ((lane >> 3) & 1) * 16;
    {
        uint32_t kr = ((lane >> 3) & 1)*8 + (lane & 7);
#pragma unroll
        for (int j = 0; j < 4; j++)
            offV[j] = kr*144 + j*32 + ((lane >> 4) & 1)*16;
    }

    int r0 = warp*16 + g;
    float mm0 = -1e30f, mm1 = -1e30f, ll0 = 0.f, ll1 = 0.f;
    float o[8][4];
#pragma unroll
    for (int nf = 0; nf < 8; nf++)
#pragma unroll
        for (int c = 0; c < 4; c++) o[nf][c] = 0.f;

    for (int jc = 0; jc < SS/64; jc++) {
        int buf = jc & 1;
        CP_WAIT0();
        __syncthreads();
        if (jc + 1 < SS/64) {
            uint32_t nb = (uint32_t)(buf ^ 1) * AKVB;
            long goff = (long)(jc + 1) * 64 * (3*DD);
            const __half* k0 = kbase + goff + (long)srow0*(3*DD) + sc8*8;
            const __half* k1 = kbase + goff + (long)srow1*(3*DD) + sc8*8;
            const __half* v0 = vbase + goff + (long)srow0*(3*DD) + sc8*8;
            const __half* v1 = vbase + goff + (long)srow1*(3*DD) + sc8*8;
            CP_ASYNC16(kd0 + nb, k0, 16u); CP_ASYNC16(kd1 + nb, k1, 16u);
            CP_ASYNC16(vd0 + nb, v0, 16u); CP_ASYNC16(vd1 + nb, v1, 16u);
            CP_COMMIT();
        }
        uint32_t kb = sb + AKB + buf * AKVB;
        uint32_t vb = sb + AVB + buf * AKVB;

        float s[8][4];
#pragma unroll
        for (int nf = 0; nf < 8; nf++)
#pragma unroll
            for (int c = 0; c < 4; c++) s[nf][c] = 0.f;
#pragma unroll
        for (int ks = 0; ks < 4; ks++) {
            uint32_t a[4];
            ldm_x4(a, offQ + ks*32);
#pragma unroll
            for (int j = 0; j < 4; j++) {
                uint32_t bf[4];
                ldm_x4(bf, kb + offK[j] + ks*32);
                mma_f16(s[2*j],   a, &bf[0]);
                mma_f16(s[2*j+1], a, &bf[2]);
            }
        }
        float mx0 = mm0, mx1 = mm1;
#pragma unroll
        for (int nf = 0; nf < 8; nf++) {
            s[nf][0] *= 0.125f; s[nf][1] *= 0.125f;
            s[nf][2] *= 0.125f; s[nf][3] *= 0.125f;
            mx0 = fmaxf(mx0, fmaxf(s[nf][0], s[nf][1]));
            mx1 = fmaxf(mx1, fmaxf(s[nf][2], s[nf][3]));
        }
        mx0 = fmaxf(mx0, __shfl_xor_sync(0xffffffffu, mx0, 1));
        mx0 = fmaxf(mx0, __shfl_xor_sync(0xffffffffu, mx0, 2));
        mx1 = fmaxf(mx1, __shfl_xor_sync(0xffffffffu, mx1, 1));
        mx1 = fmaxf(mx1, __shfl_xor_sync(0xffffffffu, mx1, 2));
        float al0 = __expf(mm0 - mx0), al1 = __expf(mm1 - mx1);
        float sum0 = 0.f, sum1 = 0.f;
#pragma unroll
        for (int nf = 0; nf < 8; nf++) {
            s[nf][0] = __expf(s[nf][0] - mx0);
            s[nf][1] = __expf(s[nf][1] - mx0);
            s[nf][2] = __expf(s[nf][2] - mx1);
            s[nf][3] = __expf(s[nf][3] - mx1);
            sum0 += s[nf][0] + s[nf][1];
            sum1 += s[nf][2] + s[nf][3];
        }
        sum0 += __shfl_xor_sync(0xffffffffu, sum0, 1);
        sum0 += __shfl_xor_sync(0xffffffffu, sum0, 2);
        sum1 += __shfl_xor_sync(0xffffffffu, sum1, 1);
        sum1 += __shfl_xor_sync(0xffffffffu, sum1, 2);
        ll0 = ll0*al0 + sum0; ll1 = ll1*al1 + sum1;
        mm0 = mx0; mm1 = mx1;
#pragma unroll
        for (int nf = 0; nf < 8; nf++) {
            o[nf][0] *= al0; o[nf][1] *= al0;
            o[nf][2] *= al1; o[nf][3] *= al1;
        }
#pragma unroll
        for (int nf = 0; nf < 8; nf++) {
            Pw[(warp*16 + g)*36 + nf*4 + t]     = h2u(__floats2half2_rn(s[nf][0], s[nf][1]));
            Pw[(warp*16 + g + 8)*36 + nf*4 + t] = h2u(__floats2half2_rn(s[nf][2], s[nf][3]));
        }
        __syncwarp();
#pragma unroll
        for (int ks = 0; ks < 4; ks++) {
            uint32_t a[4];
            ldm_x4(a, offP + ks*32);
#pragma unroll
            for (int j = 0; j < 4; j++) {
                uint32_t bf[4];
                ldm_x4_t(bf, vb + offV[j] + ks*2304);
                mma_f16(o[2*j],   a, &bf[0]);
                mma_f16(o[2*j+1], a, &bf[2]);
            }
        }
    }

    float inv0 = 1.f / ll0, inv1 = 1.f / ll1;
    long tok0 = (long)(b*SS + q0 + r0) * DD + hh*HD;
    long tok1 = tok0 + 8L*DD;
#pragma unroll
    for (int nf = 0; nf < 8; nf++) {
        int col = nf*8 + 2*t;
        *(__half2*)&out[tok0 + col] = __floats2half2_rn(o[nf][0]*inv0, o[nf][1]*inv0);
        *(__half2*)&out[tok1 + col] = __floats2half2_rn(o[nf][2]*inv1, o[nf][3]*inv1);
    }
}

// ---------------- instance-norm stats (+ zero MoE counters) ----------------
__global__ void istats_kernel(const float* __restrict__ x, float* __restrict__ stats,
                              int* __restrict__ cntAll)
{
    int bf = blockIdx.x;
    int b = bf >> 3, f = bf & 7;
    int tid = threadIdx.x;
    if (bf == 0 && tid < LL*EE) cntAll[tid] = 0;
    float s = 0.f, ss = 0.f;
    for (int i = tid; i < SS; i += 256) {
        float v = x[((long)b*SS + i)*FF + f];
        s += v; ss += v*v;
    }
    __shared__ float red[16];
    int lane = tid & 31, wid = tid >> 5;
#pragma unroll
    for (int o = 16; o; o >>= 1) {
        s  += __shfl_down_sync(0xffffffffu, s, o);
        ss += __shfl_down_sync(0xffffffffu, ss, o);
    }
    if (!lane) { red[wid] = s; red[8+wid] = ss; }
    __syncthreads();
    if (!tid) {
        float S = 0.f, Q = 0.f;
        for (int w = 0; w < 8; w++) { S += red[w]; Q += red[8+w]; }
        float m = S / SS;
        float var = (Q - SS*m*m) / (SS - 1);
        stats[bf*2]   = m;
        stats[bf*2+1] = 1.f / (sqrtf(var) + 1e-5f);
    }
}

// ---------------- embed (writes fp32 + fp16) ----------------
__global__ void embed_kernel(const float* __restrict__ x, const float* __restrict__ Wp,
                             const float* __restrict__ bp, const float* __restrict__ femb,
                             const int* __restrict__ fidx, const float* __restrict__ stats,
                             float* __restrict__ h, __half* __restrict__ h16)
{
    int token = blockIdx.x;
    int b = token >> 10, s = token & 1023;
    int tid = threadIdx.x;
    __shared__ float xn[8];
    if (tid < 8) {
        float m = stats[(b*8+tid)*2], inv = stats[(b*8+tid)*2+1];
        xn[tid] = (x[(long)token*FF + tid] - m) * inv;
    }
    __syncthreads();
    int fi = *fidx;
    int d0 = tid * 4;
    float4 acc = *(const float4*)&bp[d0];
    float* ap = &acc.x;
#pragma unroll
    for (int f = 0; f < 8; f++) {
        float xv = xn[f];
        ap[0] += xv * Wp[(d0+0)*8+f];
        ap[1] += xv * Wp[(d0+1)*8+f];
        ap[2] += xv * Wp[(d0+2)*8+f];
        ap[3] += xv * Wp[(d0+3)*8+f];
    }
    const float c = -0.0179889460f;
#pragma unroll
    for (int j = 0; j < 4; j++) {
        int d = d0 + j;
        int i = d >> 1;
        float ang = (float)s * expf((float)(2*i) * c);
        float pe = (d & 1) ? cosf(ang) : sinf(ang);
        ap[j] += femb[fi*DD + d] + pe;
    }
    *(float4*)&h[(long)token*DD + d0] = acc;
    __half2* hp = (__half2*)&h16[(long)token*DD + d0];
    hp[0] = __floats2half2_rn(acc.x, acc.y);
    hp[1] = __floats2half2_rn(acc.z, acc.w);
}

// ---------------- add + layernorm + fused MoE gating (add term in fp16) ----------------
__global__ void add_ln_gate_kernel(const float* __restrict__ base, const __half* __restrict__ add,
                                   const float* __restrict__ g, const float* __restrict__ bet,
                                   const float* __restrict__ gw, const float* __restrict__ gb,
                                   float* __restrict__ out, __half* __restrict__ out16,
                                   int* __restrict__ cnt, int* __restrict__ etok,
                                   int* __restrict__ slot, float* __restrict__ wt)
{
    long tk = blockIdx.x;
    int tid = threadIdx.x;
    float4 xb = *(const float4*)&base[tk*DD + tid*4];
    uint2 au = *(const uint2*)&add[tk*DD + tid*4];
    float2 aa = __half22float2(*(__half2*)&au.x);
    float2 ab = __half22float2(*(__half2*)&au.y);
    float v0=xb.x+aa.x, v1=xb.y+aa.y, v2=xb.z+ab.x, v3=xb.w+ab.y;
    float s = v0+v1+v2+v3, ss = v0*v0+v1*v1+v2*v2+v3*v3;
    __shared__ float red[16];
    __shared__ float gred[4][4];
    int lane = tid & 31, wid = tid >> 5;
#pragma unroll
    for (int o = 16; o; o >>= 1) {
        s  += __shfl_down_sync(0xffffffffu, s, o);
        ss += __shfl_down_sync(0xffffffffu, ss, o);
    }
    if (!lane) { red[wid] = s; red[8+wid] = ss; }
    __syncthreads();
    if (!tid) {
        float S = red[0]+red[1]+red[2]+red[3];
        float Q = red[8]+red[9]+red[10]+red[11];
        red[0] = S * (1.f/DD);
        red[1] = Q * (1.f/DD);
    }
    __syncthreads();
    float m = red[0];
    float r = rsqrtf(red[1] - m*m + 1e-5f);
    float4 gv = *(const float4*)&g[tid*4];
    float4 bv = *(const float4*)&bet[tid*4];
    float4 o4;
    o4.x = (v0-m)*r*gv.x + bv.x;
    o4.y = (v1-m)*r*gv.y + bv.y;
    o4.z = (v2-m)*r*gv.z + bv.z;
    o4.w = (v3-m)*r*gv.w + bv.w;
    *(float4*)&out[tk*DD + tid*4] = o4;
    __half2* hp = (__half2*)&out16[tk*DD + tid*4];
    hp[0] = __floats2half2_rn(o4.x, o4.y);
    hp[1] = __floats2half2_rn(o4.z, o4.w);

    float p[4];
#pragma unroll
    for (int e = 0; e < 4; e++) {
        float4 wv = *(const float4*)&gw[e*DD + tid*4];
        p[e] = o4.x*wv.x + o4.y*wv.y + o4.z*wv.z + o4.w*wv.w;
    }
#pragma unroll
    for (int e = 0; e < 4; e++)
#pragma unroll
        for (int o = 16; o; o >>= 1)
            p[e] += __shfl_down_sync(0xffffffffu, p[e], o);
    if (!lane) {
        gred[wid][0] = p[0]; gred[wid][1] = p[1];
        gred[wid][2] = p[2]; gred[wid][3] = p[3];
    }
    __syncthreads();
    if (!tid) {
        float lg[4], pr[4];
        float mx = -1e30f;
#pragma unroll
        for (int e = 0; e < 4; e++) {
            lg[e] = gred[0][e]+gred[1][e]+gred[2][e]+gred[3][e] + gb[e];
            mx = fmaxf(mx, lg[e]);
        }
        float sum = 0.f;
#pragma unroll
        for (int e = 0; e < 4; e++) { pr[e] = expf(lg[e]-mx); sum += pr[e]; }
#pragma unroll
        for (int e = 0; e < 4; e++) pr[e] /= sum;
        int i0 = 0;
#pragma unroll
        for (int e = 1; e < 4; e++) if (pr[e] > pr[i0]) i0 = e;
        int i1 = (i0 == 0) ? 1 : 0;
#pragma unroll
        for (int e = 0; e < 4; e++) if (e != i0 && pr[e] > pr[i1]) i1 = e;
        float w0 = pr[i0], w1 = pr[i1];
        float inv = 1.f / (w0 + w1);
        int pos0 = atomicAdd(&cnt[i0], 1);
        etok[i0*TT + pos0] = (int)tk;
        slot[2*tk]   = i0*TT + pos0;
        wt[2*tk]     = w0 * inv;
        int pos1 = atomicAdd(&cnt[i1], 1);
        etok[i1*TT + pos1] = (int)tk;
        slot[2*tk+1] = i1*TT + pos1;
        wt[2*tk+1]   = w1 * inv;
    }
}

// ---------------- moe combine + layernorm (eo in fp16) ----------------
__global__ void moe_combine_ln_kernel(const float* __restrict__ h, const __half* __restrict__ eo,
                                      const int* __restrict__ slot, const float* __restrict__ wt,
                                      const float* __restrict__ g, const float* __restrict__ bet,
                                      float* __restrict__ out, __half* __restrict__ out16)
{
    long t = blockIdx.x;
    int tid = threadIdx.x;
    int s0 = slot[2*t], s1 = slot[2*t+1];
    float w0 = wt[2*t], w1 = wt[2*t+1];
    float4 xh = *(const float4*)&h[t*DD + tid*4];
    uint2 e0u = *(const uint2*)&eo[(long)s0*DD + tid*4];
    uint2 e1u = *(const uint2*)&eo[(long)s1*DD + tid*4];
    float2 e0a = __half22float2(*(__half2*)&e0u.x);
    float2 e0b = __half22float2(*(__half2*)&e0u.y);
    float2 e1a = __half22float2(*(__half2*)&e1u.x);
    float2 e1b = __half22float2(*(__half2*)&e1u.y);
    float v0 = xh.x + w0*e0a.x + w1*e1a.x;
    float v1 = xh.y + w0*e0a.y + w1*e1a.y;
    float v2 = xh.z + w0*e0b.x + w1*e1b.x;
    float v3 = xh.w + w0*e0b.y + w1*e1b.y;
    float s = v0+v1+v2+v3, ss = v0*v0+v1*v1+v2*v2+v3*v3;
    __shared__ float red[16];
    int lane = tid & 31, wid = tid >> 5;
#pragma unroll
    for (int o = 16; o; o >>= 1) {
        s  += __shfl_down_sync(0xffffffffu, s, o);
        ss += __shfl_down_sync(0xffffffffu, ss, o);
    }
    if (!lane) { red[wid] = s; red[8+wid] = ss; }
    __syncthreads();
    if (!tid) {
        float S = red[0]+red[1]+red[2]+red[3];
        float Q = red[8]+red[9]+red[10]+red[11];
        red[0] = S * (1.f/DD);
        red[1] = Q * (1.f/DD);
    }
    __syncthreads();
    float m = red[0];
    float r = rsqrtf(red[1] - m*m + 1e-5f);
    float4 gv = *(const float4*)&g[tid*4];
    float4 bv = *(const float4*)&bet[tid*4];
    float4 o4;
    o4.x = (v0-m)*r*gv.x + bv.x;
    o4.y = (v1-m)*r*gv.y + bv.y;
    o4.z = (v2-m)*r*gv.z + bv.z;
    o4.w = (v3-m)*r*gv.w + bv.w;
    *(float4*)&out[t*DD + tid*4] = o4;
    __half2* hp = (__half2*)&out16[t*DD + tid*4];
    hp[0] = __floats2half2_rn(o4.x, o4.y);
    hp[1] = __floats2half2_rn(o4.z, o4.w);
}

// ---------------- head ----------------
__global__ void head_kernel(const float* __restrict__ h, const float* __restrict__ hw,
                            const float* __restrict__ hb, float* __restrict__ out)
{
    int w = threadIdx.x >> 5, lane = threadIdx.x & 31;
    int b = w / 3, i = w % 3;
    const float* hp = h + ((long)(b*SS + SS-1)) * DD;
    float s = 0.f;
#pragma unroll
    for (int it = 0; it < 4; it++) {
        int d0 = (it*32 + lane) * 4;
        float4 a = *(const float4*)&hp[d0];
        float4 c = *(const float4*)&hw[i*DD + d0];
        s += a.x*c.x + a.y*c.y + a.z*c.z + a.w*c.w;
    }
#pragma unroll
    for (int o = 16; o; o >>= 1) s += __shfl_down_sync(0xffffffffu, s, o);
    if (!lane) out[b*3+i] = s + hb[i];
}

// ---------------- orchestration ----------------
extern "C" void kernel_launch(void* const* d_in, const int* in_sizes, int n_in,
                              void* d_out, int out_size)
{
    const float* x      = (const float*)d_in[0];
    const float* Wp     = (const float*)d_in[1];
    const float* bp     = (const float*)d_in[2];
    const float* femb   = (const float*)d_in[3];
    const float* qkv_w  = (const float*)d_in[4];
    const float* qkv_b  = (const float*)d_in[5];
    const float* ow     = (const float*)d_in[6];
    const float* ob     = (const float*)d_in[7];
    const float* g1     = (const float*)d_in[8];
    const float* beta1  = (const float*)d_in[9];
    const float* gw     = (const float*)d_in[10];
    const float* gb     = (const float*)d_in[11];
    const float* ew1    = (const float*)d_in[12];
    const float* eb1    = (const float*)d_in[13];
    const float* ew2    = (const float*)d_in[14];
    const float* eb2    = (const float*)d_in[15];
    const float* g2     = (const float*)d_in[16];
    const float* beta2  = (const float*)d_in[17];
    const float* hw     = (const float*)d_in[18];
    const float* hb     = (const float*)d_in[19];
    const int*   fidx   = (const int*)d_in[20];
    float* out = (float*)d_out;

    float *h, *wt, *istats;
    int *cnt, *etok, *slot;
    __half *h16, *qkv16, *attn16, *tmp16, *hid16, *eo16, *qkvw16, *ow16, *ew116, *ew216;
    cudaGetSymbolAddress((void**)&h,      g_h);
    cudaGetSymbolAddress((void**)&cnt,    g_cnt);
    cudaGetSymbolAddress((void**)&etok,   g_etok);
    cudaGetSymbolAddress((void**)&slot,   g_slot);
    cudaGetSymbolAddress((void**)&wt,     g_wt);
    cudaGetSymbolAddress((void**)&istats, g_istats);
    cudaGetSymbolAddress((void**)&h16,    g_h16);
    cudaGetSymbolAddress((void**)&qkv16,  g_qkv16);
    cudaGetSymbolAddress((void**)&attn16, g_attn16);
    cudaGetSymbolAddress((void**)&tmp16,  g_tmp16);
    cudaGetSymbolAddress((void**)&hid16,  g_hid16);
    cudaGetSymbolAddress((void**)&eo16,   g_eo16);
    cudaGetSymbolAddress((void**)&qkvw16, g_qkvw16);
    cudaGetSymbolAddress((void**)&ow16,   g_ow16);
    cudaGetSymbolAddress((void**)&ew116,  g_ew116);
    cudaGetSymbolAddress((void**)&ew216,  g_ew216);

    cudaFuncSetAttribute(attn_h_kernel, cudaFuncAttributeMaxDynamicSharedMemorySize, ATT_SMEM);
    cudaFuncSetAttribute(gemm_h<false,false,2>, cudaFuncAttributeMaxDynamicSharedMemorySize, GEMM_SMEM);
    cudaFuncSetAttribute(gemm_h<true,true,2>,   cudaFuncAttributeMaxDynamicSharedMemorySize, GEMM_SMEM);

    f2h_all_kernel<<<(NTOTF4 + 255)/256, 256>>>(qkv_w, qkvw16, ow, ow16, ew1, ew116, ew2, ew216);

    istats_kernel<<<BB*FF, 256>>>(x, istats, cnt);
    embed_kernel<<<TT, 128>>>(x, Wp, bp, femb, fidx, istats, h, h16);

    for (int l = 0; l < LL; l++) {
        // QKV projection -> half
        gemm_h<false,false,2><<<dim3(3*DD/128, TT/128, 1), 256, GEMM_SMEM>>>(
            h16, qkvw16 + (long)l*3*DD*DD, qkv_b + l*3*DD, nullptr, qkv16,
            TT, 3*DD, DD, DD, 3*DD, 0, 0, 0, 0, nullptr, nullptr);
        // attention (fp16 flash) -> half
        attn_h_kernel<<<dim3(SS/128, HH, BB), 256, ATT_SMEM>>>(qkv16, attn16);
        // output projection -> half
        gemm_h<false,false,2><<<dim3(DD/128, TT/128, 1), 256, GEMM_SMEM>>>(
            attn16, ow16 + (long)l*DD*DD, ob + l*DD, nullptr, tmp16,
            TT, DD, DD, DD, DD, 0, 0, 0, 0, nullptr, nullptr);
        // add + LN + fused gating
        add_ln_gate_kernel<<<TT, 128>>>(h, tmp16, g1 + l*DD, beta1 + l*DD,
                                        gw + l*EE*DD, gb + l*EE,
                                        h, h16, cnt + l*EE, etok, slot, wt);
        // MoE expert FFNs (routed)
        gemm_h<true,true,2><<<dim3(2*DD/128, TT/128, EE), 256, GEMM_SMEM>>>(
            h16, ew116 + (long)l*EE*2*DD*DD, eb1 + l*EE*2*DD, nullptr, hid16,
            TT, 2*DD, DD, DD, 2*DD,
            0, (long)2*DD*DD, 2*DD, (long)TT*2*DD, etok, cnt + l*EE);
        gemm_h<false,false,2><<<dim3(DD/128, TT/128, EE), 256, GEMM_SMEM>>>(
            hid16, ew216 + (long)l*EE*2*DD*DD, eb2 + l*EE*DD, nullptr, eo16,
            TT, DD, 2*DD, 2*DD, DD,
            (long)TT*2*DD, (long)2*DD*DD, DD, (long)TT*DD, nullptr, cnt + l*EE);
        moe_combine_ln_kernel<<<TT, 128>>>(h, eo16, slot, wt, g2 + l*DD, beta2 + l*DD, h, h16);
    }
    head_kernel<<<1, 768>>>(h, hw, hb, out);
}